// round 2
// baseline (speedup 1.0000x reference)
#include <cuda_runtime.h>
#include <cuda_bf16.h>
#include <cstdint>

// Problem constants
#define NB    1024   // batch
#define C     512    // channels
#define NP    64     // tokens (8x8)
#define HEADS 16
#define INTER 256
#define DH    16     // INTER/HEADS
#define CH    32     // C/HEADS (channels per head for mixing)

// ---------------- scratch (allocation-free: __device__ globals) ----------------
__device__ float g_ctx[(size_t)NB * C * NP];      // 128 MB  position-mixed context
__device__ float g_g[(size_t)NB * INTER * NP];    //  64 MB
__device__ float g_phi[(size_t)NB * INTER * NP];  //  64 MB
__device__ float g_theta[(size_t)NB * INTER * NP];//  64 MB
__device__ float g_y[(size_t)NB * INTER * NP];    //  64 MB

// ---------------- K1: position mixing ----------------
// ctx_new[n, h*32+d, o] = ctx[.,o] + bm[h,o] + sum_k ctx[n,h*32+d,k] * Wm[h,o,k]
__global__ __launch_bounds__(256)
void mix_kernel(const float* __restrict__ ctx, const float* __restrict__ Wm,
                const float* __restrict__ bm, float* __restrict__ out)
{
    const int h = blockIdx.x;
    const int n = blockIdx.y;
    __shared__ float sW[64 * 65];   // Wm[h][o][k], padded rows
    __shared__ float sC[32 * 64];   // ctx block  [d][k]
    const size_t cbase = ((size_t)n * C + h * CH) * NP;
    const float* wblk = Wm + (size_t)h * 64 * 64;
    const int t = threadIdx.x;

    #pragma unroll
    for (int i = t; i < 64 * 64; i += 256) {
        int o = i >> 6, k = i & 63;
        sW[o * 65 + k] = wblk[i];
    }
    #pragma unroll
    for (int i = t; i < 32 * 64; i += 256) sC[i] = ctx[cbase + i];
    __syncthreads();

    #pragma unroll
    for (int j = 0; j < 8; j++) {
        int idx = t + 256 * j;          // idx = d*64 + o
        int d = idx >> 6, o = idx & 63;
        float acc = sC[idx] + bm[h * 64 + o];
        const float* crow = sC + d * 64;
        const float* wrow = sW + o * 65;
        #pragma unroll
        for (int k = 0; k < 64; k++) acc += crow[k] * wrow[k];
        out[cbase + idx] = acc;
    }
}

// ---------------- K2/K4: batched GEMM  Y[n] = W(MxK) @ X[n](Kx64) + b (+resid) ----------------
// Block computes 256 rows x 64 cols of Y[n]. grid = (M/256, NB), 256 threads.
// Thread (ty,tx): rows ty+32u (u<8), cols tx+8v (v<8) -> 64 accumulators.
template<int K, int M, bool RESID>
__global__ __launch_bounds__(256)
void gemm_kernel(const float* __restrict__ W, const float* __restrict__ bias,
                 const float* __restrict__ X, const float* __restrict__ resid,
                 float* __restrict__ Y)
{
    const int n = blockIdx.y;
    const int row0 = blockIdx.x * 256;
    const float* Xn = X + (size_t)n * K * NP;

    __shared__ float sW[16][257];   // [kk][row], padded
    __shared__ float sX[16 * 64];   // [kk][col]

    const int t = threadIdx.x;
    const int tx = t & 7;           // col group
    const int ty = t >> 3;          // row group (0..31)

    float acc[8][8];
    #pragma unroll
    for (int u = 0; u < 8; u++)
        #pragma unroll
        for (int v = 0; v < 8; v++) acc[u][v] = 0.f;

    for (int k0 = 0; k0 < K; k0 += 16) {
        // W tile: 256 rows x 16 k  (consecutive threads read consecutive k)
        #pragma unroll
        for (int i = 0; i < 16; i++) {
            int idx = t + 256 * i;
            int r = idx >> 4, kk = idx & 15;
            sW[kk][r] = W[(size_t)(row0 + r) * K + k0 + kk];
        }
        // X tile: 16 x 64 contiguous block
        #pragma unroll
        for (int i = 0; i < 4; i++) {
            int idx = t + 256 * i;
            sX[idx] = Xn[k0 * 64 + idx];
        }
        __syncthreads();

        #pragma unroll
        for (int kk = 0; kk < 16; kk++) {
            float a[8], b[8];
            #pragma unroll
            for (int u = 0; u < 8; u++) a[u] = sW[kk][ty + 32 * u];
            #pragma unroll
            for (int v = 0; v < 8; v++) b[v] = sX[kk * 64 + tx + 8 * v];
            #pragma unroll
            for (int u = 0; u < 8; u++)
                #pragma unroll
                for (int v = 0; v < 8; v++) acc[u][v] = fmaf(a[u], b[v], acc[u][v]);
        }
        __syncthreads();
    }

    #pragma unroll
    for (int u = 0; u < 8; u++) {
        int r = ty + 32 * u;
        float bb = bias[row0 + r];
        #pragma unroll
        for (int v = 0; v < 8; v++) {
            int cidx = tx + 8 * v;
            size_t off = ((size_t)n * M + row0 + r) * NP + cidx;
            float val = acc[u][v] + bb;
            if (RESID) val += resid[off];
            Y[off] = val;
        }
    }
}

// ---------------- K3: per-(n,h) attention ----------------
// scores[q,k] = (1/4) sum_d theta[d,q] phi[d,k]; softmax over k; y[d,q] = sum_k w[q,k] g[d,k]
__global__ __launch_bounds__(256)
void attn_kernel(const float* __restrict__ Th, const float* __restrict__ Ph,
                 const float* __restrict__ G, float* __restrict__ Y)
{
    const int h = blockIdx.x;
    const int n = blockIdx.y;
    __shared__ float sT[16 * 64], sP[16 * 64], sG[16 * 64];
    __shared__ float sS[64][65];
    const size_t base = ((size_t)n * INTER + h * DH) * NP;
    const int t = threadIdx.x;

    #pragma unroll
    for (int i = t; i < 16 * 64; i += 256) {
        sT[i] = Th[base + i];
        sP[i] = Ph[base + i];
        sG[i] = G[base + i];
    }
    __syncthreads();

    #pragma unroll
    for (int j = 0; j < 16; j++) {
        int idx = t + 256 * j;          // idx = q*64 + k
        int q = idx >> 6, k = idx & 63;
        float acc = 0.f;
        #pragma unroll
        for (int d = 0; d < 16; d++) acc = fmaf(sT[d * 64 + q], sP[d * 64 + k], acc);
        sS[q][k] = acc * 0.25f;
    }
    __syncthreads();

    if (t < 64) {
        float m = -1e30f;
        #pragma unroll
        for (int k = 0; k < 64; k++) m = fmaxf(m, sS[t][k]);
        float s = 0.f;
        #pragma unroll
        for (int k = 0; k < 64; k++) { float e = __expf(sS[t][k] - m); sS[t][k] = e; s += e; }
        float inv = 1.0f / s;
        #pragma unroll
        for (int k = 0; k < 64; k++) sS[t][k] *= inv;
    }
    __syncthreads();

    #pragma unroll
    for (int j = 0; j < 4; j++) {
        int idx = t + 256 * j;          // idx = d*64 + q
        int d = idx >> 6, q = idx & 63;
        float acc = 0.f;
        #pragma unroll
        for (int k = 0; k < 64; k++) acc = fmaf(sS[q][k], sG[d * 64 + k], acc);
        Y[base + idx] = acc;
    }
}

// ---------------- launch ----------------
extern "C" void kernel_launch(void* const* d_in, const int* in_sizes, int n_in,
                              void* d_out, int out_size)
{
    const float* query   = (const float*)d_in[0];
    const float* context = (const float*)d_in[1];
    const float* Wm = (const float*)d_in[2];
    const float* bm = (const float*)d_in[3];
    const float* Wg = (const float*)d_in[4];
    const float* bg = (const float*)d_in[5];
    const float* Wt = (const float*)d_in[6];
    const float* bt = (const float*)d_in[7];
    const float* Wp = (const float*)d_in[8];
    const float* bp = (const float*)d_in[9];
    const float* Wo = (const float*)d_in[10];
    const float* bo = (const float*)d_in[11];
    float* out = (float*)d_out;

    float *ctxp, *gp, *phip, *thetap, *yp;
    cudaGetSymbolAddress((void**)&ctxp,   g_ctx);
    cudaGetSymbolAddress((void**)&gp,     g_g);
    cudaGetSymbolAddress((void**)&phip,   g_phi);
    cudaGetSymbolAddress((void**)&thetap, g_theta);
    cudaGetSymbolAddress((void**)&yp,     g_y);

    // 1) position mixing: ctx_new = ctx @ (I + Wm[h])^T + bm
    mix_kernel<<<dim3(HEADS, NB), 256>>>(context, Wm, bm, ctxp);

    // 2) projections (batched GEMMs, K=512, M=256)
    gemm_kernel<512, 256, false><<<dim3(1, NB), 256>>>(Wg, bg, ctxp,  nullptr, gp);
    gemm_kernel<512, 256, false><<<dim3(1, NB), 256>>>(Wp, bp, ctxp,  nullptr, phip);
    gemm_kernel<512, 256, false><<<dim3(1, NB), 256>>>(Wt, bt, query, nullptr, thetap);

    // 3) attention per (n, head)
    attn_kernel<<<dim3(HEADS, NB), 256>>>(thetap, phip, gp, yp);

    // 4) output projection + residual (K=256, M=512)
    gemm_kernel<256, 512, true><<<dim3(2, NB), 256>>>(Wo, bo, yp, query, out);
}

// round 4
// speedup vs baseline: 2.2806x; 2.2806x over previous
#include <cuda_runtime.h>
#include <cstdint>

#define NB    1024
#define C     512
#define NP    64
#define HEADS 16
#define INTER 256

// ---------------- scratch (__device__ globals, allocation-free) ----------------
__device__ float g_ctxT[(size_t)NB * NP * C];     // token-major mixed ctx  (n*64+tok, 512)
__device__ float g_qT[(size_t)NB * NP * C];       // token-major query
__device__ float g_g[(size_t)NB * INTER * NP];    // (n, 256, 64)
__device__ float g_phi[(size_t)NB * INTER * NP];
__device__ float g_theta[(size_t)NB * INTER * NP];
__device__ float g_yT[(size_t)NB * NP * INTER];   // token-major y (n*64+tok, 256)

// ---------------- helpers ----------------
__device__ __forceinline__ uint32_t smem_u32(const void* p) {
    uint32_t a;
    asm("{ .reg .u64 t; cvta.to.shared.u64 t, %1; cvt.u32.u64 %0, t; }" : "=r"(a) : "l"(p));
    return a;
}
__device__ __forceinline__ void cp_async16(void* dst, const void* src) {
    asm volatile("cp.async.cg.shared.global [%0], [%1], 16;"
                 :: "r"(smem_u32(dst)), "l"(src));
}
#define CP_COMMIT() asm volatile("cp.async.commit_group;" ::: "memory")
#define CP_WAIT(n)  asm volatile("cp.async.wait_group %0;" :: "n"(n) : "memory")

__device__ __forceinline__ uint32_t f2tf32(float f) {
    uint32_t r;
    asm("cvt.rna.tf32.f32 %0, %1;" : "=r"(r) : "f"(f));
    return r;
}
__device__ __forceinline__ void mma_tf32(float c[4], const uint32_t a[4], uint32_t b0, uint32_t b1) {
    asm volatile(
        "mma.sync.aligned.m16n8k8.row.col.f32.tf32.tf32.f32 "
        "{%0,%1,%2,%3}, {%4,%5,%6,%7}, {%8,%9}, {%0,%1,%2,%3};"
        : "+f"(c[0]), "+f"(c[1]), "+f"(c[2]), "+f"(c[3])
        : "r"(a[0]), "r"(a[1]), "r"(a[2]), "r"(a[3]), "r"(b0), "r"(b1));
}

// ---------------- K1: position mixing -> token-major ctxT ----------------
__global__ __launch_bounds__(256)
void mix_kernel(const float* __restrict__ ctx, const float* __restrict__ Wm,
                const float* __restrict__ bm, float* __restrict__ outT)
{
    const int h = blockIdx.x;
    const int n = blockIdx.y;
    __shared__ float sW[64 * 65];
    __shared__ float sC[32 * 64];
    __shared__ float sOut[64 * 36];
    const size_t cbase = ((size_t)n * C + h * 32) * NP;
    const float* wblk = Wm + (size_t)h * 64 * 64;
    const int t = threadIdx.x;

    #pragma unroll
    for (int i = t; i < 64 * 64; i += 256) {
        int o = i >> 6, k = i & 63;
        sW[o * 65 + k] = wblk[i];
    }
    #pragma unroll
    for (int i = t; i < 32 * 64; i += 256) sC[i] = ctx[cbase + i];
    __syncthreads();

    #pragma unroll
    for (int j = 0; j < 8; j++) {
        int idx = t + 256 * j;          // idx = d*64 + o
        int d = idx >> 6, o = idx & 63;
        float acc = sC[idx] + bm[h * 64 + o];
        const float* crow = sC + d * 64;
        const float* wrow = sW + o * 65;
        #pragma unroll
        for (int k = 0; k < 64; k++) acc += crow[k] * wrow[k];
        sOut[o * 36 + d] = acc;
    }
    __syncthreads();

    const int o = t >> 2, dp = t & 3;
    float* dst = outT + ((size_t)(n * 64 + o)) * C + h * 32 + dp * 8;
    *(float4*)(dst + 0) = *(const float4*)(&sOut[o * 36 + dp * 8]);
    *(float4*)(dst + 4) = *(const float4*)(&sOut[o * 36 + dp * 8 + 4]);
}

// ---------------- transpose query -> token-major ----------------
__global__ __launch_bounds__(256)
void transpose_kernel(const float* __restrict__ q, float* __restrict__ qT)
{
    const int n = blockIdx.x;
    const int t = threadIdx.x;
    __shared__ float s[64 * 65];
    const size_t nbase = (size_t)n * C * NP;

    for (int c0 = 0; c0 < C; c0 += 64) {
        #pragma unroll
        for (int i = 0; i < 16; i++) {
            int idx = t + 256 * i;
            int cc = idx >> 6, col = idx & 63;
            s[cc * 65 + col] = q[nbase + (size_t)(c0 + cc) * 64 + col];
        }
        __syncthreads();
        const int col = t >> 2, cp = t & 3;
        float v[16];
        #pragma unroll
        for (int i = 0; i < 16; i++) v[i] = s[(cp * 16 + i) * 65 + col];
        float* dst = qT + ((size_t)(n * 64 + col)) * C + c0 + cp * 16;
        #pragma unroll
        for (int i = 0; i < 4; i++) *(float4*)(dst + 4 * i) = *(const float4*)(&v[4 * i]);
        __syncthreads();
    }
}

// ---------------- mma.sync tf32 batched GEMM ----------------
// blockIdx.x = tile (fast dim -> same-n tiles co-resident, B reuse in L2)
// blockIdx.y = n. Tile t < TA: rows t*128 of Wa -> Y0; else rows (t-TA)*128 of Wb -> Y1.
// X token-major (n*64+tok, K).  Y[(n*MY + m)*64 + tok] = W[m,:]·X[tok,:] + bias (+resid)
#define ASTR 36
template<int K, int TA, bool RESID>
__global__ __launch_bounds__(256)
void gemm_mma(const float* __restrict__ Wa, const float* __restrict__ Wb,
              const float* __restrict__ biasa, const float* __restrict__ biasb,
              int MY, const float* __restrict__ Xt, const float* __restrict__ resid,
              float* __restrict__ Y0, float* __restrict__ Y1)
{
    const int n = blockIdx.y;
    const int tile = blockIdx.x;
    const float* W;
    const float* bias;
    float* Y;
    int rowoff;
    if (tile < TA) {
        W = Wa + (size_t)tile * 128 * K; bias = biasa + tile * 128;
        Y = Y0; rowoff = tile * 128;
    } else {
        int u = tile - TA;
        W = Wb + (size_t)u * 128 * K; bias = biasb + u * 128;
        Y = Y1; rowoff = u * 128;
    }
    const float* Xp = Xt + (size_t)n * 64 * K;

    extern __shared__ float sm[];
    float* sA = sm;                    // [2][128*ASTR]
    float* sB = sm + 2 * 128 * ASTR;   // [2][64*ASTR]

    const int t = threadIdx.x;
    const int w = t >> 5, lane = t & 31;
    const int g = lane >> 2, tq = lane & 3;
    const int wm = w & 3, wn = w >> 2;       // warp tile: rows wm*32, cols wn*32

    float acc[2][4][4];
    #pragma unroll
    for (int mt = 0; mt < 2; mt++)
        #pragma unroll
        for (int nt = 0; nt < 4; nt++)
            #pragma unroll
            for (int i = 0; i < 4; i++) acc[mt][nt][i] = 0.f;

    constexpr int NIT = K / 32;

    // ---- cp.async stage ----
    auto copy_tiles = [&](int k0, int buf) {
        float* dA = sA + buf * 128 * ASTR;
        float* dB = sB + buf * 64 * ASTR;
        #pragma unroll
        for (int i = 0; i < 4; i++) {               // A: 128 rows x 8 chunks
            int idx = t + 256 * i;
            int r = idx >> 3, c2 = idx & 7;
            cp_async16(dA + r * ASTR + c2 * 4, W + (size_t)r * K + k0 + c2 * 4);
        }
        #pragma unroll
        for (int i = 0; i < 2; i++) {               // B: 64 rows x 8 chunks
            int idx = t + 256 * i;
            int r = idx >> 3, c2 = idx & 7;
            cp_async16(dB + r * ASTR + c2 * 4, Xp + (size_t)r * K + k0 + c2 * 4);
        }
    };

    copy_tiles(0, 0);
    CP_COMMIT();

    int buf = 0;
    for (int it = 0; it < NIT; ++it) {
        if (it + 1 < NIT) {
            copy_tiles((it + 1) * 32, buf ^ 1);
            CP_COMMIT();
            CP_WAIT(1);
        } else {
            CP_WAIT(0);
        }
        __syncthreads();

        const float* cA = sA + buf * 128 * ASTR;
        const float* cB = sB + buf * 64 * ASTR;
        #pragma unroll
        for (int s = 0; s < 4; s++) {
            const int kb = s * 8;
            uint32_t af[2][4];
            #pragma unroll
            for (int mt = 0; mt < 2; mt++) {
                const int rb = wm * 32 + mt * 16;
                af[mt][0] = f2tf32(cA[(rb + g)     * ASTR + kb + tq]);
                af[mt][1] = f2tf32(cA[(rb + g + 8) * ASTR + kb + tq]);
                af[mt][2] = f2tf32(cA[(rb + g)     * ASTR + kb + tq + 4]);
                af[mt][3] = f2tf32(cA[(rb + g + 8) * ASTR + kb + tq + 4]);
            }
            uint32_t bf[4][2];
            #pragma unroll
            for (int nt = 0; nt < 4; nt++) {
                const int nb = wn * 32 + nt * 8;
                bf[nt][0] = f2tf32(cB[(nb + g) * ASTR + kb + tq]);
                bf[nt][1] = f2tf32(cB[(nb + g) * ASTR + kb + tq + 4]);
            }
            #pragma unroll
            for (int mt = 0; mt < 2; mt++)
                #pragma unroll
                for (int nt = 0; nt < 4; nt++)
                    mma_tf32(acc[mt][nt], af[mt], bf[nt][0], bf[nt][1]);
        }
        __syncthreads();
        buf ^= 1;
    }

    // ---- epilogue ----
    #pragma unroll
    for (int mt = 0; mt < 2; mt++) {
        const int rl0 = wm * 32 + mt * 16 + g;     // local rows
        const int rl1 = rl0 + 8;
        const float bv0 = bias[rl0];
        const float bv1 = bias[rl1];
        #pragma unroll
        for (int nt = 0; nt < 4; nt++) {
            const int col = wn * 32 + nt * 8 + tq * 2;
            size_t off0 = ((size_t)n * MY + rowoff + rl0) * 64 + col;
            size_t off1 = ((size_t)n * MY + rowoff + rl1) * 64 + col;
            float2 v0, v1;
            v0.x = acc[mt][nt][0] + bv0; v0.y = acc[mt][nt][1] + bv0;
            v1.x = acc[mt][nt][2] + bv1; v1.y = acc[mt][nt][3] + bv1;
            if (RESID) {
                const float2 r0 = *(const float2*)(resid + off0);
                const float2 r1 = *(const float2*)(resid + off1);
                v0.x += r0.x; v0.y += r0.y;
                v1.x += r1.x; v1.y += r1.y;
            }
            *(float2*)(Y + off0) = v0;
            *(float2*)(Y + off1) = v1;
        }
    }
}

// ---------------- attention (fp32), writes token-major y ----------------
__global__ __launch_bounds__(256)
void attn_kernel(const float* __restrict__ Th, const float* __restrict__ Ph,
                 const float* __restrict__ G, float* __restrict__ YT)
{
    const int h = blockIdx.x;
    const int n = blockIdx.y;
    __shared__ float sT[16 * 64], sP[16 * 64], sG[16 * 64];
    __shared__ float sS[64][65];
    __shared__ float sY[64 * 20];
    const size_t base = ((size_t)n * INTER + h * 16) * NP;
    const int t = threadIdx.x;

    #pragma unroll
    for (int i = t; i < 16 * 64; i += 256) {
        sT[i] = Th[base + i];
        sP[i] = Ph[base + i];
        sG[i] = G[base + i];
    }
    __syncthreads();

    #pragma unroll
    for (int j = 0; j < 16; j++) {
        int idx = t + 256 * j;          // q*64 + k
        int q = idx >> 6, k = idx & 63;
        float acc = 0.f;
        #pragma unroll
        for (int d = 0; d < 16; d++) acc = fmaf(sT[d * 64 + q], sP[d * 64 + k], acc);
        sS[q][k] = acc * 0.25f;
    }
    __syncthreads();

    if (t < 64) {
        float m = -1e30f;
        #pragma unroll
        for (int k = 0; k < 64; k++) m = fmaxf(m, sS[t][k]);
        float s = 0.f;
        #pragma unroll
        for (int k = 0; k < 64; k++) { float e = __expf(sS[t][k] - m); sS[t][k] = e; s += e; }
        float inv = 1.0f / s;
        #pragma unroll
        for (int k = 0; k < 64; k++) sS[t][k] *= inv;
    }
    __syncthreads();

    #pragma unroll
    for (int j = 0; j < 4; j++) {
        int idx = t + 256 * j;          // d*64 + q
        int d = idx >> 6, q = idx & 63;
        float acc = 0.f;
        #pragma unroll
        for (int k = 0; k < 64; k++) acc = fmaf(sS[q][k], sG[d * 64 + k], acc);
        sY[q * 20 + d] = acc;
    }
    __syncthreads();

    const int q = t >> 2, dp = t & 3;
    float* dst = YT + ((size_t)(n * 64 + q)) * INTER + h * 16 + dp * 4;
    *(float4*)dst = *(const float4*)(&sY[q * 20 + dp * 4]);
}

// ---------------- launch ----------------
extern "C" void kernel_launch(void* const* d_in, const int* in_sizes, int n_in,
                              void* d_out, int out_size)
{
    const float* query   = (const float*)d_in[0];
    const float* context = (const float*)d_in[1];
    const float* Wm = (const float*)d_in[2];
    const float* bm = (const float*)d_in[3];
    const float* Wg = (const float*)d_in[4];
    const float* bg = (const float*)d_in[5];
    const float* Wt = (const float*)d_in[6];
    const float* bt = (const float*)d_in[7];
    const float* Wp = (const float*)d_in[8];
    const float* bp = (const float*)d_in[9];
    const float* Wo = (const float*)d_in[10];
    const float* bo = (const float*)d_in[11];
    float* out = (float*)d_out;

    float *ctxT, *qT, *gp, *phip, *thetap, *yT;
    cudaGetSymbolAddress((void**)&ctxT,   g_ctxT);
    cudaGetSymbolAddress((void**)&qT,     g_qT);
    cudaGetSymbolAddress((void**)&gp,     g_g);
    cudaGetSymbolAddress((void**)&phip,   g_phi);
    cudaGetSymbolAddress((void**)&thetap, g_theta);
    cudaGetSymbolAddress((void**)&yT,     g_yT);

    const int SMEM = (2 * 128 * ASTR + 2 * 64 * ASTR) * 4;   // 55296 B
    cudaFuncSetAttribute((const void*)gemm_mma<512, 2, false>,
                         cudaFuncAttributeMaxDynamicSharedMemorySize, SMEM);
    cudaFuncSetAttribute((const void*)gemm_mma<256, 4, true>,
                         cudaFuncAttributeMaxDynamicSharedMemorySize, SMEM);

    // 1) position mixing -> token-major ctxT; transpose query
    mix_kernel<<<dim3(HEADS, NB), 256>>>(context, Wm, bm, ctxT);
    transpose_kernel<<<NB, 256>>>(query, qT);

    // 2) projections: g+phi fused (share X slice in L2), theta
    gemm_mma<512, 2, false><<<dim3(4, NB), 256, SMEM>>>(
        Wg, Wp, bg, bp, INTER, ctxT, nullptr, gp, phip);
    gemm_mma<512, 2, false><<<dim3(2, NB), 256, SMEM>>>(
        Wt, Wt, bt, bt, INTER, qT, nullptr, thetap, thetap);

    // 3) attention -> token-major yT
    attn_kernel<<<dim3(HEADS, NB), 256>>>(thetap, phip, gp, yT);

    // 4) output projection + bias + residual
    gemm_mma<256, 4, true><<<dim3(4, NB), 256, SMEM>>>(
        Wo, Wo, bo, bo, C, yT, query, out, out);
}

// round 5
// speedup vs baseline: 3.0019x; 1.3163x over previous
#include <cuda_runtime.h>
#include <cstdint>

#define NB    1024
#define C     512
#define NP    64
#define HEADS 16
#define INTER 256

// ---------------- scratch (__device__ globals, allocation-free) ----------------
__device__ float g_ctx2[(size_t)NB * C * NP];     // mixed ctx, natural (n, 512, 64)
__device__ float g_g[(size_t)NB * INTER * NP];    // (n, 256, 64)
__device__ float g_phi[(size_t)NB * INTER * NP];
__device__ float g_theta[(size_t)NB * INTER * NP];
__device__ float g_y[(size_t)NB * INTER * NP];    // attention output, natural

// ---------------- helpers ----------------
__device__ __forceinline__ uint32_t smem_u32(const void* p) {
    uint32_t a;
    asm("{ .reg .u64 t; cvta.to.shared.u64 t, %1; cvt.u32.u64 %0, t; }" : "=r"(a) : "l"(p));
    return a;
}
__device__ __forceinline__ void cp_async16(void* dst, const void* src) {
    asm volatile("cp.async.cg.shared.global [%0], [%1], 16;"
                 :: "r"(smem_u32(dst)), "l"(src));
}
#define CP_COMMIT() asm volatile("cp.async.commit_group;" ::: "memory")
#define CP_WAIT(n)  asm volatile("cp.async.wait_group %0;" :: "n"(n) : "memory")

__device__ __forceinline__ uint32_t f2tf32(float f) {
    uint32_t r;
    asm("cvt.rna.tf32.f32 %0, %1;" : "=r"(r) : "f"(f));
    return r;
}
__device__ __forceinline__ void mma_tf32(float c[4], const uint32_t a[4], uint32_t b0, uint32_t b1) {
    asm volatile(
        "mma.sync.aligned.m16n8k8.row.col.f32.tf32.tf32.f32 "
        "{%0,%1,%2,%3}, {%4,%5,%6,%7}, {%8,%9}, {%0,%1,%2,%3};"
        : "+f"(c[0]), "+f"(c[1]), "+f"(c[2]), "+f"(c[3])
        : "r"(a[0]), "r"(a[1]), "r"(a[2]), "r"(a[3]), "r"(b0), "r"(b1));
}

// ============================================================================
// K1: position mixing via mma.sync.
// Per CTA: head h, 4 batches (128 A-rows = 4n x 32d), K=64 tokens, N=64 out tokens.
// out[n, h*32+d, o] = ctx[n,h*32+d,o] + bm[h,o] + sum_k ctx[n,h*32+d,k]*Wm[h,o,k]
// ============================================================================
#define MSTR 68
__global__ __launch_bounds__(256)
void mix_mma(const float* __restrict__ ctx, const float* __restrict__ Wm,
             const float* __restrict__ bm, float* __restrict__ out)
{
    const int h = blockIdx.x;
    const int n0 = blockIdx.y * 4;

    extern __shared__ float sm[];
    float* sA = sm;               // [128][MSTR]
    float* sB = sm + 128 * MSTR;  // [64][MSTR]

    const int t = threadIdx.x;
    const int w = t >> 5, lane = t & 31;
    const int g = lane >> 2, tq = lane & 3;
    const int wm = w & 3, wn = w >> 2;

    // Load A: ctx rows (nl, d) -> 128 rows x 64 k
    #pragma unroll
    for (int i = 0; i < 8; i++) {
        int idx = t + 256 * i;
        int r = idx >> 4, c = idx & 15;
        const float* src = ctx + (((size_t)(n0 + (r >> 5)) * C) + h * 32 + (r & 31)) * NP + c * 4;
        cp_async16(sA + r * MSTR + c * 4, src);
    }
    // Load B: Wm[h] 64 x 64
    #pragma unroll
    for (int i = 0; i < 4; i++) {
        int idx = t + 256 * i;
        int r = idx >> 4, c = idx & 15;
        cp_async16(sB + r * MSTR + c * 4, Wm + (size_t)h * 4096 + r * 64 + c * 4);
    }
    CP_COMMIT();
    CP_WAIT(0);
    __syncthreads();

    float acc[2][4][4];
    #pragma unroll
    for (int mt = 0; mt < 2; mt++)
        #pragma unroll
        for (int nt = 0; nt < 4; nt++)
            #pragma unroll
            for (int i = 0; i < 4; i++) acc[mt][nt][i] = 0.f;

    #pragma unroll
    for (int s = 0; s < 8; s++) {
        const int kb = s * 8;
        uint32_t af[2][4];
        #pragma unroll
        for (int mt = 0; mt < 2; mt++) {
            const int rb = wm * 32 + mt * 16;
            af[mt][0] = f2tf32(sA[(rb + g)     * MSTR + kb + tq]);
            af[mt][1] = f2tf32(sA[(rb + g + 8) * MSTR + kb + tq]);
            af[mt][2] = f2tf32(sA[(rb + g)     * MSTR + kb + tq + 4]);
            af[mt][3] = f2tf32(sA[(rb + g + 8) * MSTR + kb + tq + 4]);
        }
        uint32_t bf[4][2];
        #pragma unroll
        for (int nt = 0; nt < 4; nt++) {
            const int nb = wn * 32 + nt * 8;
            bf[nt][0] = f2tf32(sB[(nb + g) * MSTR + kb + tq]);
            bf[nt][1] = f2tf32(sB[(nb + g) * MSTR + kb + tq + 4]);
        }
        #pragma unroll
        for (int mt = 0; mt < 2; mt++)
            #pragma unroll
            for (int nt = 0; nt < 4; nt++)
                mma_tf32(acc[mt][nt], af[mt], bf[nt][0], bf[nt][1]);
    }

    // epilogue: + ctx (from sA, k-range == o-range) + bm
    #pragma unroll
    for (int mt = 0; mt < 2; mt++) {
        const int rl0 = wm * 32 + mt * 16 + g;
        const int rl1 = rl0 + 8;
        #pragma unroll
        for (int nt = 0; nt < 4; nt++) {
            const int col = wn * 32 + nt * 8 + tq * 2;
            const float b0 = __ldg(bm + h * 64 + col);
            const float b1 = __ldg(bm + h * 64 + col + 1);
            float2 v0, v1;
            v0.x = acc[mt][nt][0] + sA[rl0 * MSTR + col]     + b0;
            v0.y = acc[mt][nt][1] + sA[rl0 * MSTR + col + 1] + b1;
            v1.x = acc[mt][nt][2] + sA[rl1 * MSTR + col]     + b0;
            v1.y = acc[mt][nt][3] + sA[rl1 * MSTR + col + 1] + b1;
            size_t off0 = (((size_t)(n0 + (rl0 >> 5)) * C) + h * 32 + (rl0 & 31)) * NP + col;
            size_t off1 = (((size_t)(n0 + (rl1 >> 5)) * C) + h * 32 + (rl1 & 31)) * NP + col;
            *(float2*)(out + off0) = v0;
            *(float2*)(out + off1) = v1;
        }
    }
}

// ============================================================================
// batched GEMM via mma.sync. X in NATURAL (n, K, 64) layout.
// B tile loaded as [k][tok] (stride 72, conflict-free fragment reads).
// Y[(n*MY + m)*64 + tok] = W[m,:]·X[:,tok] + bias (+resid)
// ============================================================================
#define ASTR 36
#define BSTR 72
template<int K, int TA, bool RESID>
__global__ __launch_bounds__(256)
void gemm_mma(const float* __restrict__ Wa, const float* __restrict__ Wb,
              const float* __restrict__ biasa, const float* __restrict__ biasb,
              int MY, const float* __restrict__ Xt, const float* __restrict__ resid,
              float* __restrict__ Y0, float* __restrict__ Y1)
{
    const int n = blockIdx.y;
    const int tile = blockIdx.x;
    const float* W;
    const float* bias;
    float* Y;
    int rowoff;
    if (tile < TA) {
        W = Wa + (size_t)tile * 128 * K; bias = biasa + tile * 128;
        Y = Y0; rowoff = tile * 128;
    } else {
        int u = tile - TA;
        W = Wb + (size_t)u * 128 * K; bias = biasb + u * 128;
        Y = Y1; rowoff = u * 128;
    }
    const float* Xp = Xt + (size_t)n * K * 64;

    extern __shared__ float sm[];
    float* sA = sm;                    // [2][128*ASTR]
    float* sB = sm + 2 * 128 * ASTR;   // [2][32*BSTR]

    const int t = threadIdx.x;
    const int w = t >> 5, lane = t & 31;
    const int g = lane >> 2, tq = lane & 3;
    const int wm = w & 3, wn = w >> 2;

    float acc[2][4][4];
    #pragma unroll
    for (int mt = 0; mt < 2; mt++)
        #pragma unroll
        for (int nt = 0; nt < 4; nt++)
            #pragma unroll
            for (int i = 0; i < 4; i++) acc[mt][nt][i] = 0.f;

    constexpr int NIT = K / 32;

    auto copy_tiles = [&](int k0, int buf) {
        float* dA = sA + buf * 128 * ASTR;
        float* dB = sB + buf * 32 * BSTR;
        #pragma unroll
        for (int i = 0; i < 4; i++) {               // A: 128 rows x 32 k
            int idx = t + 256 * i;
            int r = idx >> 3, c2 = idx & 7;
            cp_async16(dA + r * ASTR + c2 * 4, W + (size_t)r * K + k0 + c2 * 4);
        }
        #pragma unroll
        for (int i = 0; i < 2; i++) {               // B: 32 k-rows x 64 tok (natural)
            int idx = t + 256 * i;
            int kk = idx >> 4, c = idx & 15;
            cp_async16(dB + kk * BSTR + c * 4, Xp + (size_t)(k0 + kk) * 64 + c * 4);
        }
    };

    copy_tiles(0, 0);
    CP_COMMIT();

    int buf = 0;
    for (int it = 0; it < NIT; ++it) {
        if (it + 1 < NIT) {
            copy_tiles((it + 1) * 32, buf ^ 1);
            CP_COMMIT();
            CP_WAIT(1);
        } else {
            CP_WAIT(0);
        }
        __syncthreads();

        const float* cA = sA + buf * 128 * ASTR;
        const float* cB = sB + buf * 32 * BSTR;
        #pragma unroll
        for (int s = 0; s < 4; s++) {
            const int kb = s * 8;
            uint32_t af[2][4];
            #pragma unroll
            for (int mt = 0; mt < 2; mt++) {
                const int rb = wm * 32 + mt * 16;
                af[mt][0] = f2tf32(cA[(rb + g)     * ASTR + kb + tq]);
                af[mt][1] = f2tf32(cA[(rb + g + 8) * ASTR + kb + tq]);
                af[mt][2] = f2tf32(cA[(rb + g)     * ASTR + kb + tq + 4]);
                af[mt][3] = f2tf32(cA[(rb + g + 8) * ASTR + kb + tq + 4]);
            }
            uint32_t bf[4][2];
            #pragma unroll
            for (int nt = 0; nt < 4; nt++) {
                const int nb = wn * 32 + nt * 8;
                bf[nt][0] = f2tf32(cB[(kb + tq)     * BSTR + nb + g]);
                bf[nt][1] = f2tf32(cB[(kb + tq + 4) * BSTR + nb + g]);
            }
            #pragma unroll
            for (int mt = 0; mt < 2; mt++)
                #pragma unroll
                for (int nt = 0; nt < 4; nt++)
                    mma_tf32(acc[mt][nt], af[mt], bf[nt][0], bf[nt][1]);
        }
        __syncthreads();
        buf ^= 1;
    }

    #pragma unroll
    for (int mt = 0; mt < 2; mt++) {
        const int rl0 = wm * 32 + mt * 16 + g;
        const int rl1 = rl0 + 8;
        const float bv0 = bias[rl0];
        const float bv1 = bias[rl1];
        #pragma unroll
        for (int nt = 0; nt < 4; nt++) {
            const int col = wn * 32 + nt * 8 + tq * 2;
            size_t off0 = ((size_t)n * MY + rowoff + rl0) * 64 + col;
            size_t off1 = ((size_t)n * MY + rowoff + rl1) * 64 + col;
            float2 v0, v1;
            v0.x = acc[mt][nt][0] + bv0; v0.y = acc[mt][nt][1] + bv0;
            v1.x = acc[mt][nt][2] + bv1; v1.y = acc[mt][nt][3] + bv1;
            if (RESID) {
                const float2 r0 = *(const float2*)(resid + off0);
                const float2 r1 = *(const float2*)(resid + off1);
                v0.x += r0.x; v0.y += r0.y;
                v1.x += r1.x; v1.y += r1.y;
            }
            *(float2*)(Y + off0) = v0;
            *(float2*)(Y + off1) = v1;
        }
    }
}

// ============================================================================
// attention (fp32), natural layouts in AND out, parallel softmax
// ============================================================================
__global__ __launch_bounds__(256)
void attn_kernel(const float* __restrict__ Th, const float* __restrict__ Ph,
                 const float* __restrict__ G, float* __restrict__ Y)
{
    const int h = blockIdx.x;
    const int n = blockIdx.y;
    __shared__ float sT[16 * 64], sP[16 * 64], sG[16 * 64];
    __shared__ float sS[64][65];
    __shared__ float sRed[4][66];
    const size_t base = ((size_t)n * INTER + h * 16) * NP;
    const int t = threadIdx.x;

    #pragma unroll
    for (int i = t; i < 16 * 64; i += 256) {
        sT[i] = Th[base + i];
        sP[i] = Ph[base + i];
        sG[i] = G[base + i];
    }
    __syncthreads();

    #pragma unroll
    for (int j = 0; j < 16; j++) {
        int idx = t + 256 * j;          // q*64 + k
        int q = idx >> 6, k = idx & 63;
        float acc = 0.f;
        #pragma unroll
        for (int d = 0; d < 16; d++) acc = fmaf(sT[d * 64 + q], sP[d * 64 + k], acc);
        sS[q][k] = acc * 0.25f;
    }
    __syncthreads();

    // parallel softmax: thread t -> row r = t&63, segment p = t>>6 (16 k's each)
    {
        const int r = t & 63, p = t >> 6, k0 = p * 16;
        float m = -1e30f;
        #pragma unroll
        for (int k = 0; k < 16; k++) m = fmaxf(m, sS[r][k0 + k]);
        sRed[p][r] = m;
        __syncthreads();
        m = fmaxf(fmaxf(sRed[0][r], sRed[1][r]), fmaxf(sRed[2][r], sRed[3][r]));
        float s = 0.f;
        #pragma unroll
        for (int k = 0; k < 16; k++) {
            float e = __expf(sS[r][k0 + k] - m);
            sS[r][k0 + k] = e;
            s += e;
        }
        __syncthreads();
        sRed[p][r] = s;
        __syncthreads();
        s = sRed[0][r] + sRed[1][r] + sRed[2][r] + sRed[3][r];
        float inv = 1.0f / s;
        #pragma unroll
        for (int k = 0; k < 16; k++) sS[r][k0 + k] *= inv;
    }
    __syncthreads();

    #pragma unroll
    for (int j = 0; j < 4; j++) {
        int idx = t + 256 * j;          // d*64 + q
        int d = idx >> 6, q = idx & 63;
        float acc = 0.f;
        #pragma unroll
        for (int k = 0; k < 64; k++) acc = fmaf(sS[q][k], sG[d * 64 + k], acc);
        Y[base + idx] = acc;            // natural (d, q), coalesced
    }
}

// ---------------- launch ----------------
extern "C" void kernel_launch(void* const* d_in, const int* in_sizes, int n_in,
                              void* d_out, int out_size)
{
    const float* query   = (const float*)d_in[0];
    const float* context = (const float*)d_in[1];
    const float* Wm = (const float*)d_in[2];
    const float* bm = (const float*)d_in[3];
    const float* Wg = (const float*)d_in[4];
    const float* bg = (const float*)d_in[5];
    const float* Wt = (const float*)d_in[6];
    const float* bt = (const float*)d_in[7];
    const float* Wp = (const float*)d_in[8];
    const float* bp = (const float*)d_in[9];
    const float* Wo = (const float*)d_in[10];
    const float* bo = (const float*)d_in[11];
    float* out = (float*)d_out;

    float *ctx2, *gp, *phip, *thetap, *yp;
    cudaGetSymbolAddress((void**)&ctx2,   g_ctx2);
    cudaGetSymbolAddress((void**)&gp,     g_g);
    cudaGetSymbolAddress((void**)&phip,   g_phi);
    cudaGetSymbolAddress((void**)&thetap, g_theta);
    cudaGetSymbolAddress((void**)&yp,     g_y);

    const int GSMEM = (2 * 128 * ASTR + 2 * 32 * BSTR) * 4;   // 55296 B
    const int XSMEM = (128 * MSTR + 64 * MSTR) * 4;           // 52224 B
    cudaFuncSetAttribute((const void*)gemm_mma<512, 2, false>,
                         cudaFuncAttributeMaxDynamicSharedMemorySize, GSMEM);
    cudaFuncSetAttribute((const void*)gemm_mma<256, 4, true>,
                         cudaFuncAttributeMaxDynamicSharedMemorySize, GSMEM);
    cudaFuncSetAttribute((const void*)mix_mma,
                         cudaFuncAttributeMaxDynamicSharedMemorySize, XSMEM);

    // 1) position mixing (mma) -> natural ctx2
    mix_mma<<<dim3(HEADS, NB / 4), 256, XSMEM>>>(context, Wm, bm, ctx2);

    // 2) projections: g+phi fused; theta reads query directly (no transpose)
    gemm_mma<512, 2, false><<<dim3(4, NB), 256, GSMEM>>>(
        Wg, Wp, bg, bp, INTER, ctx2, nullptr, gp, phip);
    gemm_mma<512, 2, false><<<dim3(2, NB), 256, GSMEM>>>(
        Wt, Wt, bt, bt, INTER, query, nullptr, thetap, thetap);

    // 3) attention -> natural y
    attn_kernel<<<dim3(HEADS, NB), 256>>>(thetap, phip, gp, yp);

    // 4) output projection + bias + residual
    gemm_mma<256, 4, true><<<dim3(4, NB), 256, GSMEM>>>(
        Wo, Wo, bo, bo, C, yp, query, out, out);
}

// round 6
// speedup vs baseline: 3.8015x; 1.2664x over previous
#include <cuda_runtime.h>
#include <cstdint>

#define NB    1024
#define C     512
#define NP    64
#define HEADS 16
#define INTER 256

// ---------------- scratch (__device__ globals, allocation-free) ----------------
__device__ float g_ctx2[(size_t)NB * C * NP];     // mixed ctx, natural (n, 512, 64)
__device__ float g_g[(size_t)NB * INTER * NP];    // (n, 256, 64)
__device__ float g_phi[(size_t)NB * INTER * NP];
__device__ float g_theta[(size_t)NB * INTER * NP];
__device__ float g_y[(size_t)NB * INTER * NP];    // attention output, natural

// ---------------- helpers ----------------
__device__ __forceinline__ uint32_t smem_u32(const void* p) {
    uint32_t a;
    asm("{ .reg .u64 t; cvta.to.shared.u64 t, %1; cvt.u32.u64 %0, t; }" : "=r"(a) : "l"(p));
    return a;
}
__device__ __forceinline__ void cp_async16(void* dst, const void* src) {
    asm volatile("cp.async.cg.shared.global [%0], [%1], 16;"
                 :: "r"(smem_u32(dst)), "l"(src));
}
#define CP_COMMIT() asm volatile("cp.async.commit_group;" ::: "memory")
#define CP_WAIT(n)  asm volatile("cp.async.wait_group %0;" :: "n"(n) : "memory")

__device__ __forceinline__ uint32_t f2tf32(float f) {
    uint32_t r;
    asm("cvt.rna.tf32.f32 %0, %1;" : "=r"(r) : "f"(f));
    return r;
}
__device__ __forceinline__ void mma_tf32(float c[4], const uint32_t a[4], uint32_t b0, uint32_t b1) {
    asm volatile(
        "mma.sync.aligned.m16n8k8.row.col.f32.tf32.tf32.f32 "
        "{%0,%1,%2,%3}, {%4,%5,%6,%7}, {%8,%9}, {%0,%1,%2,%3};"
        : "+f"(c[0]), "+f"(c[1]), "+f"(c[2]), "+f"(c[3])
        : "r"(a[0]), "r"(a[1]), "r"(a[2]), "r"(a[3]), "r"(b0), "r"(b1));
}

// ============================================================================
// K1: position mixing via mma.sync (unchanged from round 5)
// ============================================================================
#define MSTR 68
__global__ __launch_bounds__(256)
void mix_mma(const float* __restrict__ ctx, const float* __restrict__ Wm,
             const float* __restrict__ bm, float* __restrict__ out)
{
    const int h = blockIdx.x;
    const int n0 = blockIdx.y * 4;

    extern __shared__ float sm[];
    float* sA = sm;               // [128][MSTR]
    float* sB = sm + 128 * MSTR;  // [64][MSTR]

    const int t = threadIdx.x;
    const int w = t >> 5, lane = t & 31;
    const int g = lane >> 2, tq = lane & 3;
    const int wm = w & 3, wn = w >> 2;

    #pragma unroll
    for (int i = 0; i < 8; i++) {
        int idx = t + 256 * i;
        int r = idx >> 4, c = idx & 15;
        const float* src = ctx + (((size_t)(n0 + (r >> 5)) * C) + h * 32 + (r & 31)) * NP + c * 4;
        cp_async16(sA + r * MSTR + c * 4, src);
    }
    #pragma unroll
    for (int i = 0; i < 4; i++) {
        int idx = t + 256 * i;
        int r = idx >> 4, c = idx & 15;
        cp_async16(sB + r * MSTR + c * 4, Wm + (size_t)h * 4096 + r * 64 + c * 4);
    }
    CP_COMMIT();
    CP_WAIT(0);
    __syncthreads();

    float acc[2][4][4];
    #pragma unroll
    for (int mt = 0; mt < 2; mt++)
        #pragma unroll
        for (int nt = 0; nt < 4; nt++)
            #pragma unroll
            for (int i = 0; i < 4; i++) acc[mt][nt][i] = 0.f;

    #pragma unroll
    for (int s = 0; s < 8; s++) {
        const int kb = s * 8;
        uint32_t af[2][4];
        #pragma unroll
        for (int mt = 0; mt < 2; mt++) {
            const int rb = wm * 32 + mt * 16;
            af[mt][0] = f2tf32(sA[(rb + g)     * MSTR + kb + tq]);
            af[mt][1] = f2tf32(sA[(rb + g + 8) * MSTR + kb + tq]);
            af[mt][2] = f2tf32(sA[(rb + g)     * MSTR + kb + tq + 4]);
            af[mt][3] = f2tf32(sA[(rb + g + 8) * MSTR + kb + tq + 4]);
        }
        uint32_t bf[4][2];
        #pragma unroll
        for (int nt = 0; nt < 4; nt++) {
            const int nb = wn * 32 + nt * 8;
            bf[nt][0] = f2tf32(sB[(nb + g) * MSTR + kb + tq]);
            bf[nt][1] = f2tf32(sB[(nb + g) * MSTR + kb + tq + 4]);
        }
        #pragma unroll
        for (int mt = 0; mt < 2; mt++)
            #pragma unroll
            for (int nt = 0; nt < 4; nt++)
                mma_tf32(acc[mt][nt], af[mt], bf[nt][0], bf[nt][1]);
    }

    #pragma unroll
    for (int mt = 0; mt < 2; mt++) {
        const int rl0 = wm * 32 + mt * 16 + g;
        const int rl1 = rl0 + 8;
        #pragma unroll
        for (int nt = 0; nt < 4; nt++) {
            const int col = wn * 32 + nt * 8 + tq * 2;
            const float b0 = __ldg(bm + h * 64 + col);
            const float b1 = __ldg(bm + h * 64 + col + 1);
            float2 v0, v1;
            v0.x = acc[mt][nt][0] + sA[rl0 * MSTR + col]     + b0;
            v0.y = acc[mt][nt][1] + sA[rl0 * MSTR + col + 1] + b1;
            v1.x = acc[mt][nt][2] + sA[rl1 * MSTR + col]     + b0;
            v1.y = acc[mt][nt][3] + sA[rl1 * MSTR + col + 1] + b1;
            size_t off0 = (((size_t)(n0 + (rl0 >> 5)) * C) + h * 32 + (rl0 & 31)) * NP + col;
            size_t off1 = (((size_t)(n0 + (rl1 >> 5)) * C) + h * 32 + (rl1 & 31)) * NP + col;
            *(float2*)(out + off0) = v0;
            *(float2*)(out + off1) = v1;
        }
    }
}

// ============================================================================
// batched GEMM via mma.sync (unchanged from round 5)
// ============================================================================
#define ASTR 36
#define BSTR 72
template<int K, int TA, bool RESID>
__global__ __launch_bounds__(256)
void gemm_mma(const float* __restrict__ Wa, const float* __restrict__ Wb,
              const float* __restrict__ biasa, const float* __restrict__ biasb,
              int MY, const float* __restrict__ Xt, const float* __restrict__ resid,
              float* __restrict__ Y0, float* __restrict__ Y1)
{
    const int n = blockIdx.y;
    const int tile = blockIdx.x;
    const float* W;
    const float* bias;
    float* Y;
    int rowoff;
    if (tile < TA) {
        W = Wa + (size_t)tile * 128 * K; bias = biasa + tile * 128;
        Y = Y0; rowoff = tile * 128;
    } else {
        int u = tile - TA;
        W = Wb + (size_t)u * 128 * K; bias = biasb + u * 128;
        Y = Y1; rowoff = u * 128;
    }
    const float* Xp = Xt + (size_t)n * K * 64;

    extern __shared__ float sm[];
    float* sA = sm;
    float* sB = sm + 2 * 128 * ASTR;

    const int t = threadIdx.x;
    const int w = t >> 5, lane = t & 31;
    const int g = lane >> 2, tq = lane & 3;
    const int wm = w & 3, wn = w >> 2;

    float acc[2][4][4];
    #pragma unroll
    for (int mt = 0; mt < 2; mt++)
        #pragma unroll
        for (int nt = 0; nt < 4; nt++)
            #pragma unroll
            for (int i = 0; i < 4; i++) acc[mt][nt][i] = 0.f;

    constexpr int NIT = K / 32;

    auto copy_tiles = [&](int k0, int buf) {
        float* dA = sA + buf * 128 * ASTR;
        float* dB = sB + buf * 32 * BSTR;
        #pragma unroll
        for (int i = 0; i < 4; i++) {
            int idx = t + 256 * i;
            int r = idx >> 3, c2 = idx & 7;
            cp_async16(dA + r * ASTR + c2 * 4, W + (size_t)r * K + k0 + c2 * 4);
        }
        #pragma unroll
        for (int i = 0; i < 2; i++) {
            int idx = t + 256 * i;
            int kk = idx >> 4, c = idx & 15;
            cp_async16(dB + kk * BSTR + c * 4, Xp + (size_t)(k0 + kk) * 64 + c * 4);
        }
    };

    copy_tiles(0, 0);
    CP_COMMIT();

    int buf = 0;
    for (int it = 0; it < NIT; ++it) {
        if (it + 1 < NIT) {
            copy_tiles((it + 1) * 32, buf ^ 1);
            CP_COMMIT();
            CP_WAIT(1);
        } else {
            CP_WAIT(0);
        }
        __syncthreads();

        const float* cA = sA + buf * 128 * ASTR;
        const float* cB = sB + buf * 32 * BSTR;
        #pragma unroll
        for (int s = 0; s < 4; s++) {
            const int kb = s * 8;
            uint32_t af[2][4];
            #pragma unroll
            for (int mt = 0; mt < 2; mt++) {
                const int rb = wm * 32 + mt * 16;
                af[mt][0] = f2tf32(cA[(rb + g)     * ASTR + kb + tq]);
                af[mt][1] = f2tf32(cA[(rb + g + 8) * ASTR + kb + tq]);
                af[mt][2] = f2tf32(cA[(rb + g)     * ASTR + kb + tq + 4]);
                af[mt][3] = f2tf32(cA[(rb + g + 8) * ASTR + kb + tq + 4]);
            }
            uint32_t bf[4][2];
            #pragma unroll
            for (int nt = 0; nt < 4; nt++) {
                const int nb = wn * 32 + nt * 8;
                bf[nt][0] = f2tf32(cB[(kb + tq)     * BSTR + nb + g]);
                bf[nt][1] = f2tf32(cB[(kb + tq + 4) * BSTR + nb + g]);
            }
            #pragma unroll
            for (int mt = 0; mt < 2; mt++)
                #pragma unroll
                for (int nt = 0; nt < 4; nt++)
                    mma_tf32(acc[mt][nt], af[mt], bf[nt][0], bf[nt][1]);
        }
        __syncthreads();
        buf ^= 1;
    }

    #pragma unroll
    for (int mt = 0; mt < 2; mt++) {
        const int rl0 = wm * 32 + mt * 16 + g;
        const int rl1 = rl0 + 8;
        const float bv0 = bias[rl0];
        const float bv1 = bias[rl1];
        #pragma unroll
        for (int nt = 0; nt < 4; nt++) {
            const int col = wn * 32 + nt * 8 + tq * 2;
            size_t off0 = ((size_t)n * MY + rowoff + rl0) * 64 + col;
            size_t off1 = ((size_t)n * MY + rowoff + rl1) * 64 + col;
            float2 v0, v1;
            v0.x = acc[mt][nt][0] + bv0; v0.y = acc[mt][nt][1] + bv0;
            v1.x = acc[mt][nt][2] + bv1; v1.y = acc[mt][nt][3] + bv1;
            if (RESID) {
                const float2 r0 = *(const float2*)(resid + off0);
                const float2 r1 = *(const float2*)(resid + off1);
                v0.x += r0.x; v0.y += r0.y;
                v1.x += r1.x; v1.y += r1.y;
            }
            *(float2*)(Y + off0) = v0;
            *(float2*)(Y + off1) = v1;
        }
    }
}

// ============================================================================
// attention via mma.sync. CTA = (n, 2 heads), 8 warps; warp = (head, 16 q-rows).
// S = theta^T phi via mma (reg accum) -> softmax in registers (shfl) ->
// P round-trip through warp-private smem -> Y^T = P @ G^T via mma ->
// staged smem -> coalesced natural-layout store.
// Strides: theta/phi/P 72 (bank-perfect for k-row fragment reads),
//          G 68 (bank-perfect for m-row fragment reads).
// ============================================================================
#define HSTR 72
#define GSTR 68
// smem float offsets
#define A_T   0                      // theta [2][16*HSTR]  (reused as Y staging)
#define A_P   (2 * 16 * HSTR)        // phi   [2][16*HSTR]
#define A_G   (A_P + 2 * 16 * HSTR)  // g     [2][16*GSTR]
#define A_P2  (A_G + 2 * 16 * GSTR)  // P     [2][64*HSTR]
#define A_TOT (A_P2 + 2 * 64 * HSTR) // 16000 floats = 64000 B

__global__ __launch_bounds__(256)
void attn_mma(const float* __restrict__ Th, const float* __restrict__ Ph,
              const float* __restrict__ G, float* __restrict__ Y)
{
    const int hp = blockIdx.x;       // head pair
    const int n  = blockIdx.y;
    extern __shared__ float sm[];

    const int t = threadIdx.x;
    const int w = t >> 5, lane = t & 31;
    const int g = lane >> 2, tq = lane & 3;
    const int hl = w >> 2;           // head within pair (0/1)
    const int rb = (w & 3) * 16;     // q-block

    const size_t base0 = ((size_t)n * INTER + (2 * hp) * 16) * NP;
    const size_t base1 = base0 + 16 * NP;

    // ---- load theta/phi/g for both heads (512 16B-chunks each) ----
    #pragma unroll
    for (int i = 0; i < 2; i++) {
        int c = t + 256 * i;
        int ch = c >> 8, r = (c >> 4) & 15, q4 = c & 15;
        size_t src = (ch ? base1 : base0) + r * 64 + q4 * 4;
        cp_async16(sm + A_T + ch * 16 * HSTR + r * HSTR + q4 * 4, Th + src);
        cp_async16(sm + A_P + ch * 16 * HSTR + r * HSTR + q4 * 4, Ph + src);
        cp_async16(sm + A_G + ch * 16 * GSTR + r * GSTR + q4 * 4, G + src);
    }
    CP_COMMIT();
    CP_WAIT(0);
    __syncthreads();

    const float* Tm = sm + A_T + hl * 16 * HSTR;
    const float* Pm = sm + A_P + hl * 16 * HSTR;
    const float* Gm = sm + A_G + hl * 16 * GSTR;
    float*       Pw = sm + A_P2 + hl * 64 * HSTR;

    // ---- S stage: M=16 (q), N=64 (tokens), K=16 (d) ----
    float sacc[8][4];
    #pragma unroll
    for (int nt = 0; nt < 8; nt++)
        #pragma unroll
        for (int i = 0; i < 4; i++) sacc[nt][i] = 0.f;

    #pragma unroll
    for (int k2 = 0; k2 < 2; k2++) {
        const int kb = k2 * 8;
        uint32_t af[4];
        af[0] = f2tf32(Tm[(kb + tq)     * HSTR + rb + g]);
        af[1] = f2tf32(Tm[(kb + tq)     * HSTR + rb + g + 8]);
        af[2] = f2tf32(Tm[(kb + tq + 4) * HSTR + rb + g]);
        af[3] = f2tf32(Tm[(kb + tq + 4) * HSTR + rb + g + 8]);
        #pragma unroll
        for (int nt = 0; nt < 8; nt++) {
            uint32_t b0 = f2tf32(Pm[(kb + tq)     * HSTR + nt * 8 + g]);
            uint32_t b1 = f2tf32(Pm[(kb + tq + 4) * HSTR + nt * 8 + g]);
            mma_tf32(sacc[nt], af, b0, b1);
        }
    }

    // ---- softmax in registers (rows g and g+8; 16 vals/row/thread, quad-reduce) ----
    {
        float m0 = -1e30f, m1 = -1e30f;
        #pragma unroll
        for (int nt = 0; nt < 8; nt++) {
            #pragma unroll
            for (int i = 0; i < 4; i++) sacc[nt][i] *= 0.25f;
            m0 = fmaxf(m0, fmaxf(sacc[nt][0], sacc[nt][1]));
            m1 = fmaxf(m1, fmaxf(sacc[nt][2], sacc[nt][3]));
        }
        m0 = fmaxf(m0, __shfl_xor_sync(0xffffffffu, m0, 1));
        m0 = fmaxf(m0, __shfl_xor_sync(0xffffffffu, m0, 2));
        m1 = fmaxf(m1, __shfl_xor_sync(0xffffffffu, m1, 1));
        m1 = fmaxf(m1, __shfl_xor_sync(0xffffffffu, m1, 2));
        float s0 = 0.f, s1 = 0.f;
        #pragma unroll
        for (int nt = 0; nt < 8; nt++) {
            sacc[nt][0] = __expf(sacc[nt][0] - m0);
            sacc[nt][1] = __expf(sacc[nt][1] - m0);
            sacc[nt][2] = __expf(sacc[nt][2] - m1);
            sacc[nt][3] = __expf(sacc[nt][3] - m1);
            s0 += sacc[nt][0] + sacc[nt][1];
            s1 += sacc[nt][2] + sacc[nt][3];
        }
        s0 += __shfl_xor_sync(0xffffffffu, s0, 1);
        s0 += __shfl_xor_sync(0xffffffffu, s0, 2);
        s1 += __shfl_xor_sync(0xffffffffu, s1, 1);
        s1 += __shfl_xor_sync(0xffffffffu, s1, 2);
        const float i0 = 1.0f / s0, i1 = 1.0f / s1;
        #pragma unroll
        for (int nt = 0; nt < 8; nt++) {
            float2 v0 = { sacc[nt][0] * i0, sacc[nt][1] * i0 };
            float2 v1 = { sacc[nt][2] * i1, sacc[nt][3] * i1 };
            *(float2*)&Pw[(rb + g)     * HSTR + nt * 8 + 2 * tq] = v0;
            *(float2*)&Pw[(rb + g + 8) * HSTR + nt * 8 + 2 * tq] = v1;
        }
    }
    __syncthreads();   // also makes theta region safe to reuse below

    // ---- AV stage: Yt[q,d] = P @ G^T.  M=16 (q), N=16 (d), K=64 (tokens) ----
    float acc2[2][4];
    #pragma unroll
    for (int nt = 0; nt < 2; nt++)
        #pragma unroll
        for (int i = 0; i < 4; i++) acc2[nt][i] = 0.f;

    #pragma unroll
    for (int k2 = 0; k2 < 8; k2++) {
        const int kb = k2 * 8;
        uint32_t af[4];
        af[0] = f2tf32(Pw[(rb + g)     * HSTR + kb + tq]);
        af[1] = f2tf32(Pw[(rb + g + 8) * HSTR + kb + tq]);
        af[2] = f2tf32(Pw[(rb + g)     * HSTR + kb + tq + 4]);
        af[3] = f2tf32(Pw[(rb + g + 8) * HSTR + kb + tq + 4]);
        #pragma unroll
        for (int nt = 0; nt < 2; nt++) {
            uint32_t b0 = f2tf32(Gm[(nt * 8 + g) * GSTR + kb + tq]);
            uint32_t b1 = f2tf32(Gm[(nt * 8 + g) * GSTR + kb + tq + 4]);
            mma_tf32(acc2[nt], af, b0, b1);
        }
    }

    // ---- stage Yt -> sY[d][q] (reuse theta region), then coalesced store ----
    float* sY = sm + A_T + hl * 16 * HSTR;
    #pragma unroll
    for (int nt = 0; nt < 2; nt++) {
        const int d0 = nt * 8 + 2 * tq, d1 = d0 + 1;
        sY[d0 * HSTR + rb + g]     = acc2[nt][0];
        sY[d1 * HSTR + rb + g]     = acc2[nt][1];
        sY[d0 * HSTR + rb + g + 8] = acc2[nt][2];
        sY[d1 * HSTR + rb + g + 8] = acc2[nt][3];
    }
    __syncthreads();

    #pragma unroll
    for (int i = 0; i < 2; i++) {
        int c = t + 256 * i;
        int ch = c >> 8, d = (c >> 4) & 15, q4 = c & 15;
        *(float4*)(Y + (ch ? base1 : base0) + d * 64 + q4 * 4) =
            *(const float4*)(sm + A_T + ch * 16 * HSTR + d * HSTR + q4 * 4);
    }
}

// ---------------- launch ----------------
extern "C" void kernel_launch(void* const* d_in, const int* in_sizes, int n_in,
                              void* d_out, int out_size)
{
    const float* query   = (const float*)d_in[0];
    const float* context = (const float*)d_in[1];
    const float* Wm = (const float*)d_in[2];
    const float* bm = (const float*)d_in[3];
    const float* Wg = (const float*)d_in[4];
    const float* bg = (const float*)d_in[5];
    const float* Wt = (const float*)d_in[6];
    const float* bt = (const float*)d_in[7];
    const float* Wp = (const float*)d_in[8];
    const float* bp = (const float*)d_in[9];
    const float* Wo = (const float*)d_in[10];
    const float* bo = (const float*)d_in[11];
    float* out = (float*)d_out;

    float *ctx2, *gp, *phip, *thetap, *yp;
    cudaGetSymbolAddress((void**)&ctx2,   g_ctx2);
    cudaGetSymbolAddress((void**)&gp,     g_g);
    cudaGetSymbolAddress((void**)&phip,   g_phi);
    cudaGetSymbolAddress((void**)&thetap, g_theta);
    cudaGetSymbolAddress((void**)&yp,     g_y);

    const int GSMEM = (2 * 128 * ASTR + 2 * 32 * BSTR) * 4;   // 55296 B
    const int XSMEM = (128 * MSTR + 64 * MSTR) * 4;           // 52224 B
    const int ASMEM = A_TOT * 4;                              // 64000 B
    cudaFuncSetAttribute((const void*)gemm_mma<512, 2, false>,
                         cudaFuncAttributeMaxDynamicSharedMemorySize, GSMEM);
    cudaFuncSetAttribute((const void*)gemm_mma<256, 4, true>,
                         cudaFuncAttributeMaxDynamicSharedMemorySize, GSMEM);
    cudaFuncSetAttribute((const void*)mix_mma,
                         cudaFuncAttributeMaxDynamicSharedMemorySize, XSMEM);
    cudaFuncSetAttribute((const void*)attn_mma,
                         cudaFuncAttributeMaxDynamicSharedMemorySize, ASMEM);

    // 1) position mixing (mma) -> natural ctx2
    mix_mma<<<dim3(HEADS, NB / 4), 256, XSMEM>>>(context, Wm, bm, ctx2);

    // 2) projections: g+phi fused; theta reads query directly
    gemm_mma<512, 2, false><<<dim3(4, NB), 256, GSMEM>>>(
        Wg, Wp, bg, bp, INTER, ctx2, nullptr, gp, phip);
    gemm_mma<512, 2, false><<<dim3(2, NB), 256, GSMEM>>>(
        Wt, Wt, bt, bt, INTER, query, nullptr, thetap, thetap);

    // 3) attention via mma -> natural y
    attn_mma<<<dim3(HEADS / 2, NB), 256, ASMEM>>>(thetap, phip, gp, yp);

    // 4) output projection + bias + residual
    gemm_mma<256, 4, true><<<dim3(4, NB), 256, GSMEM>>>(
        Wo, Wo, bo, bo, C, yp, query, out, out);
}

// round 7
// speedup vs baseline: 4.3162x; 1.1354x over previous
#include <cuda_runtime.h>
#include <cstdint>

#define NB    1024
#define C     512
#define NP    64
#define HEADS 16
#define INTER 256

// ---------------- scratch (__device__ globals, allocation-free) ----------------
__device__ float g_ctx2[(size_t)NB * C * NP];     // mixed ctx (tf32-rounded), natural
__device__ float g_g[(size_t)NB * INTER * NP];    // tf32-rounded
__device__ float g_phi[(size_t)NB * INTER * NP];  // tf32-rounded
__device__ float g_theta[(size_t)NB * INTER * NP];// tf32-rounded
__device__ float g_y[(size_t)NB * INTER * NP];    // tf32-rounded
__device__ float g_Wr[4 * 131072];                // rounded Wg, Wp, Wt, Wo

// ---------------- helpers ----------------
__device__ __forceinline__ uint32_t smem_u32(const void* p) {
    uint32_t a;
    asm("{ .reg .u64 t; cvta.to.shared.u64 t, %1; cvt.u32.u64 %0, t; }" : "=r"(a) : "l"(p));
    return a;
}
__device__ __forceinline__ void cp_async16(void* dst, const void* src) {
    asm volatile("cp.async.cg.shared.global [%0], [%1], 16;"
                 :: "r"(smem_u32(dst)), "l"(src));
}
#define CP_COMMIT() asm volatile("cp.async.commit_group;" ::: "memory")
#define CP_WAIT(n)  asm volatile("cp.async.wait_group %0;" :: "n"(n) : "memory")

__device__ __forceinline__ uint32_t f2tf32(float f) {
    uint32_t r;
    asm("cvt.rna.tf32.f32 %0, %1;" : "=r"(r) : "f"(f));
    return r;
}
__device__ __forceinline__ float rnd32(float f) { return __uint_as_float(f2tf32(f)); }

__device__ __forceinline__ void mma_tf32(float c[4], const uint32_t a[4], uint32_t b0, uint32_t b1) {
    asm volatile(
        "mma.sync.aligned.m16n8k8.row.col.f32.tf32.tf32.f32 "
        "{%0,%1,%2,%3}, {%4,%5,%6,%7}, {%8,%9}, {%0,%1,%2,%3};"
        : "+f"(c[0]), "+f"(c[1]), "+f"(c[2]), "+f"(c[3])
        : "r"(a[0]), "r"(a[1]), "r"(a[2]), "r"(a[3]), "r"(b0), "r"(b1));
}
__device__ __forceinline__ uint32_t ldu(const float* p) {
    return __float_as_uint(*p);     // operand already tf32-rounded
}

// ---------------- K0: pre-round weights to tf32 ----------------
__global__ __launch_bounds__(256)
void round_w(const float* __restrict__ Wg, const float* __restrict__ Wp,
             const float* __restrict__ Wt, const float* __restrict__ Wo,
             float* __restrict__ dst)
{
    int i = blockIdx.x * 256 + threadIdx.x;   // 131072 elements each
    dst[i]              = rnd32(Wg[i]);
    dst[131072 + i]     = rnd32(Wp[i]);
    dst[262144 + i]     = rnd32(Wt[i]);
    dst[393216 + i]     = rnd32(Wo[i]);
}

// ============================================================================
// K1: position mixing via mma.sync -> ctx2 (tf32-rounded)
// ============================================================================
#define MSTR 68
__global__ __launch_bounds__(256)
void mix_mma(const float* __restrict__ ctx, const float* __restrict__ Wm,
             const float* __restrict__ bm, float* __restrict__ out)
{
    const int h = blockIdx.x;
    const int n0 = blockIdx.y * 4;

    extern __shared__ float sm[];
    float* sA = sm;               // [128][MSTR]
    float* sB = sm + 128 * MSTR;  // [64][MSTR]

    const int t = threadIdx.x;
    const int w = t >> 5, lane = t & 31;
    const int g = lane >> 2, tq = lane & 3;
    const int wm = w & 3, wn = w >> 2;

    #pragma unroll
    for (int i = 0; i < 8; i++) {
        int idx = t + 256 * i;
        int r = idx >> 4, c = idx & 15;
        const float* src = ctx + (((size_t)(n0 + (r >> 5)) * C) + h * 32 + (r & 31)) * NP + c * 4;
        cp_async16(sA + r * MSTR + c * 4, src);
    }
    #pragma unroll
    for (int i = 0; i < 4; i++) {
        int idx = t + 256 * i;
        int r = idx >> 4, c = idx & 15;
        cp_async16(sB + r * MSTR + c * 4, Wm + (size_t)h * 4096 + r * 64 + c * 4);
    }
    CP_COMMIT();
    CP_WAIT(0);
    __syncthreads();

    float acc[2][4][4];
    #pragma unroll
    for (int mt = 0; mt < 2; mt++)
        #pragma unroll
        for (int nt = 0; nt < 4; nt++)
            #pragma unroll
            for (int i = 0; i < 4; i++) acc[mt][nt][i] = 0.f;

    #pragma unroll
    for (int s = 0; s < 8; s++) {
        const int kb = s * 8;
        uint32_t af[2][4];
        #pragma unroll
        for (int mt = 0; mt < 2; mt++) {
            const int rb = wm * 32 + mt * 16;
            af[mt][0] = f2tf32(sA[(rb + g)     * MSTR + kb + tq]);
            af[mt][1] = f2tf32(sA[(rb + g + 8) * MSTR + kb + tq]);
            af[mt][2] = f2tf32(sA[(rb + g)     * MSTR + kb + tq + 4]);
            af[mt][3] = f2tf32(sA[(rb + g + 8) * MSTR + kb + tq + 4]);
        }
        uint32_t bf[4][2];
        #pragma unroll
        for (int nt = 0; nt < 4; nt++) {
            const int nb = wn * 32 + nt * 8;
            bf[nt][0] = f2tf32(sB[(nb + g) * MSTR + kb + tq]);
            bf[nt][1] = f2tf32(sB[(nb + g) * MSTR + kb + tq + 4]);
        }
        #pragma unroll
        for (int mt = 0; mt < 2; mt++)
            #pragma unroll
            for (int nt = 0; nt < 4; nt++)
                mma_tf32(acc[mt][nt], af[mt], bf[nt][0], bf[nt][1]);
    }

    #pragma unroll
    for (int mt = 0; mt < 2; mt++) {
        const int rl0 = wm * 32 + mt * 16 + g;
        const int rl1 = rl0 + 8;
        #pragma unroll
        for (int nt = 0; nt < 4; nt++) {
            const int col = wn * 32 + nt * 8 + tq * 2;
            const float b0 = __ldg(bm + h * 64 + col);
            const float b1 = __ldg(bm + h * 64 + col + 1);
            float2 v0, v1;
            v0.x = rnd32(acc[mt][nt][0] + sA[rl0 * MSTR + col]     + b0);
            v0.y = rnd32(acc[mt][nt][1] + sA[rl0 * MSTR + col + 1] + b1);
            v1.x = rnd32(acc[mt][nt][2] + sA[rl1 * MSTR + col]     + b0);
            v1.y = rnd32(acc[mt][nt][3] + sA[rl1 * MSTR + col + 1] + b1);
            size_t off0 = (((size_t)(n0 + (rl0 >> 5)) * C) + h * 32 + (rl0 & 31)) * NP + col;
            size_t off1 = (((size_t)(n0 + (rl1 >> 5)) * C) + h * 32 + (rl1 & 31)) * NP + col;
            *(float2*)(out + off0) = v0;
            *(float2*)(out + off1) = v1;
        }
    }
}

// ============================================================================
// batched GEMM via mma.sync. CTA = 128 W-rows x 128 tokens (2 batches).
// W pre-rounded to tf32; B pre-rounded unless CVTB.
// ============================================================================
#define ASTR  36
#define BNSTR 136
template<int K, int TA, bool RESID, bool CVTB, bool ROUND_OUT>
__global__ __launch_bounds__(256)
void gemm_mma(const float* __restrict__ Wa, const float* __restrict__ Wb,
              const float* __restrict__ biasa, const float* __restrict__ biasb,
              int MY, const float* __restrict__ Xt, const float* __restrict__ resid,
              float* __restrict__ Y0, float* __restrict__ Y1)
{
    const int n0 = blockIdx.y * 2;
    const int tile = blockIdx.x;
    const float* W;
    const float* bias;
    float* Y;
    int rowoff;
    if (tile < TA) {
        W = Wa + (size_t)tile * 128 * K; bias = biasa + tile * 128;
        Y = Y0; rowoff = tile * 128;
    } else {
        int u = tile - TA;
        W = Wb + (size_t)u * 128 * K; bias = biasb + u * 128;
        Y = Y1; rowoff = u * 128;
    }
    const float* Xp0 = Xt + (size_t)n0 * K * 64;
    const float* Xp1 = Xp0 + (size_t)K * 64;

    extern __shared__ float sm[];
    float* sA = sm;                     // [2][128*ASTR]
    float* sB = sm + 2 * 128 * ASTR;    // [2][32*BNSTR]

    const int t = threadIdx.x;
    const int w = t >> 5, lane = t & 31;
    const int g = lane >> 2, tq = lane & 3;
    const int wm = w & 3, wn = w >> 2;      // warp: 32 rows x 64 cols

    float acc[2][8][4];
    #pragma unroll
    for (int mt = 0; mt < 2; mt++)
        #pragma unroll
        for (int nt = 0; nt < 8; nt++)
            #pragma unroll
            for (int i = 0; i < 4; i++) acc[mt][nt][i] = 0.f;

    constexpr int NIT = K / 32;

    auto copy_tiles = [&](int k0, int buf) {
        float* dA = sA + buf * 128 * ASTR;
        float* dB = sB + buf * 32 * BNSTR;
        #pragma unroll
        for (int i = 0; i < 4; i++) {               // A: 128 rows x 32 k
            int idx = t + 256 * i;
            int r = idx >> 3, c2 = idx & 7;
            cp_async16(dA + r * ASTR + c2 * 4, W + (size_t)r * K + k0 + c2 * 4);
        }
        #pragma unroll
        for (int i = 0; i < 4; i++) {               // B: 32 k x 128 tok (2 batches)
            int idx = t + 256 * i;
            int kk = idx >> 5, c = idx & 31;
            const float* src = ((c < 16) ? Xp0 : Xp1) + (size_t)(k0 + kk) * 64 + (c & 15) * 4;
            cp_async16(dB + kk * BNSTR + c * 4, src);
        }
    };

    copy_tiles(0, 0);
    CP_COMMIT();

    int buf = 0;
    for (int it = 0; it < NIT; ++it) {
        if (it + 1 < NIT) {
            copy_tiles((it + 1) * 32, buf ^ 1);
            CP_COMMIT();
            CP_WAIT(1);
        } else {
            CP_WAIT(0);
        }
        __syncthreads();

        const float* cA = sA + buf * 128 * ASTR;
        const float* cB = sB + buf * 32 * BNSTR;
        #pragma unroll
        for (int s = 0; s < 4; s++) {
            const int kb = s * 8;
            uint32_t af[2][4];
            #pragma unroll
            for (int mt = 0; mt < 2; mt++) {
                const int rb = wm * 32 + mt * 16;
                af[mt][0] = ldu(&cA[(rb + g)     * ASTR + kb + tq]);
                af[mt][1] = ldu(&cA[(rb + g + 8) * ASTR + kb + tq]);
                af[mt][2] = ldu(&cA[(rb + g)     * ASTR + kb + tq + 4]);
                af[mt][3] = ldu(&cA[(rb + g + 8) * ASTR + kb + tq + 4]);
            }
            uint32_t bf[8][2];
            #pragma unroll
            for (int nt = 0; nt < 8; nt++) {
                const int nb = wn * 64 + nt * 8;
                if (CVTB) {
                    bf[nt][0] = f2tf32(cB[(kb + tq)     * BNSTR + nb + g]);
                    bf[nt][1] = f2tf32(cB[(kb + tq + 4) * BNSTR + nb + g]);
                } else {
                    bf[nt][0] = ldu(&cB[(kb + tq)     * BNSTR + nb + g]);
                    bf[nt][1] = ldu(&cB[(kb + tq + 4) * BNSTR + nb + g]);
                }
            }
            #pragma unroll
            for (int mt = 0; mt < 2; mt++)
                #pragma unroll
                for (int nt = 0; nt < 8; nt++)
                    mma_tf32(acc[mt][nt], af[mt], bf[nt][0], bf[nt][1]);
        }
        __syncthreads();
        buf ^= 1;
    }

    #pragma unroll
    for (int mt = 0; mt < 2; mt++) {
        const int rl0 = wm * 32 + mt * 16 + g;
        const int rl1 = rl0 + 8;
        const float bv0 = bias[rl0];
        const float bv1 = bias[rl1];
        #pragma unroll
        for (int nt = 0; nt < 8; nt++) {
            const int gcol = wn * 64 + nt * 8 + tq * 2;
            const int n = n0 + (gcol >> 6);
            const int col = gcol & 63;
            size_t off0 = ((size_t)n * MY + rowoff + rl0) * 64 + col;
            size_t off1 = ((size_t)n * MY + rowoff + rl1) * 64 + col;
            float2 v0, v1;
            v0.x = acc[mt][nt][0] + bv0; v0.y = acc[mt][nt][1] + bv0;
            v1.x = acc[mt][nt][2] + bv1; v1.y = acc[mt][nt][3] + bv1;
            if (RESID) {
                const float2 r0 = *(const float2*)(resid + off0);
                const float2 r1 = *(const float2*)(resid + off1);
                v0.x += r0.x; v0.y += r0.y;
                v1.x += r1.x; v1.y += r1.y;
            }
            if (ROUND_OUT) {
                v0.x = rnd32(v0.x); v0.y = rnd32(v0.y);
                v1.x = rnd32(v1.x); v1.y = rnd32(v1.y);
            }
            *(float2*)(Y + off0) = v0;
            *(float2*)(Y + off1) = v1;
        }
    }
}

// ============================================================================
// attention via mma.sync; inputs pre-rounded tf32 -> zero cvt in MMA paths
// ============================================================================
#define HSTR 72
#define GSTR 68
#define A_T   0
#define A_P   (2 * 16 * HSTR)
#define A_G   (A_P + 2 * 16 * HSTR)
#define A_P2  (A_G + 2 * 16 * GSTR)
#define A_TOT (A_P2 + 2 * 64 * HSTR)

__global__ __launch_bounds__(256)
void attn_mma(const float* __restrict__ Th, const float* __restrict__ Ph,
              const float* __restrict__ G, float* __restrict__ Y)
{
    const int hp = blockIdx.x;
    const int n  = blockIdx.y;
    extern __shared__ float sm[];

    const int t = threadIdx.x;
    const int w = t >> 5, lane = t & 31;
    const int g = lane >> 2, tq = lane & 3;
    const int hl = w >> 2;
    const int rb = (w & 3) * 16;

    const size_t base0 = ((size_t)n * INTER + (2 * hp) * 16) * NP;
    const size_t base1 = base0 + 16 * NP;

    #pragma unroll
    for (int i = 0; i < 2; i++) {
        int c = t + 256 * i;
        int ch = c >> 8, r = (c >> 4) & 15, q4 = c & 15;
        size_t src = (ch ? base1 : base0) + r * 64 + q4 * 4;
        cp_async16(sm + A_T + ch * 16 * HSTR + r * HSTR + q4 * 4, Th + src);
        cp_async16(sm + A_P + ch * 16 * HSTR + r * HSTR + q4 * 4, Ph + src);
        cp_async16(sm + A_G + ch * 16 * GSTR + r * GSTR + q4 * 4, G + src);
    }
    CP_COMMIT();
    CP_WAIT(0);
    __syncthreads();

    const float* Tm = sm + A_T + hl * 16 * HSTR;
    const float* Pm = sm + A_P + hl * 16 * HSTR;
    const float* Gm = sm + A_G + hl * 16 * GSTR;
    float*       Pw = sm + A_P2 + hl * 64 * HSTR;

    float sacc[8][4];
    #pragma unroll
    for (int nt = 0; nt < 8; nt++)
        #pragma unroll
        for (int i = 0; i < 4; i++) sacc[nt][i] = 0.f;

    #pragma unroll
    for (int k2 = 0; k2 < 2; k2++) {
        const int kb = k2 * 8;
        uint32_t af[4];
        af[0] = ldu(&Tm[(kb + tq)     * HSTR + rb + g]);
        af[1] = ldu(&Tm[(kb + tq)     * HSTR + rb + g + 8]);
        af[2] = ldu(&Tm[(kb + tq + 4) * HSTR + rb + g]);
        af[3] = ldu(&Tm[(kb + tq + 4) * HSTR + rb + g + 8]);
        #pragma unroll
        for (int nt = 0; nt < 8; nt++) {
            uint32_t b0 = ldu(&Pm[(kb + tq)     * HSTR + nt * 8 + g]);
            uint32_t b1 = ldu(&Pm[(kb + tq + 4) * HSTR + nt * 8 + g]);
            mma_tf32(sacc[nt], af, b0, b1);
        }
    }

    {
        float m0 = -1e30f, m1 = -1e30f;
        #pragma unroll
        for (int nt = 0; nt < 8; nt++) {
            #pragma unroll
            for (int i = 0; i < 4; i++) sacc[nt][i] *= 0.25f;
            m0 = fmaxf(m0, fmaxf(sacc[nt][0], sacc[nt][1]));
            m1 = fmaxf(m1, fmaxf(sacc[nt][2], sacc[nt][3]));
        }
        m0 = fmaxf(m0, __shfl_xor_sync(0xffffffffu, m0, 1));
        m0 = fmaxf(m0, __shfl_xor_sync(0xffffffffu, m0, 2));
        m1 = fmaxf(m1, __shfl_xor_sync(0xffffffffu, m1, 1));
        m1 = fmaxf(m1, __shfl_xor_sync(0xffffffffu, m1, 2));
        float s0 = 0.f, s1 = 0.f;
        #pragma unroll
        for (int nt = 0; nt < 8; nt++) {
            sacc[nt][0] = __expf(sacc[nt][0] - m0);
            sacc[nt][1] = __expf(sacc[nt][1] - m0);
            sacc[nt][2] = __expf(sacc[nt][2] - m1);
            sacc[nt][3] = __expf(sacc[nt][3] - m1);
            s0 += sacc[nt][0] + sacc[nt][1];
            s1 += sacc[nt][2] + sacc[nt][3];
        }
        s0 += __shfl_xor_sync(0xffffffffu, s0, 1);
        s0 += __shfl_xor_sync(0xffffffffu, s0, 2);
        s1 += __shfl_xor_sync(0xffffffffu, s1, 1);
        s1 += __shfl_xor_sync(0xffffffffu, s1, 2);
        const float i0 = 1.0f / s0, i1 = 1.0f / s1;
        #pragma unroll
        for (int nt = 0; nt < 8; nt++) {
            float2 v0 = { rnd32(sacc[nt][0] * i0), rnd32(sacc[nt][1] * i0) };
            float2 v1 = { rnd32(sacc[nt][2] * i1), rnd32(sacc[nt][3] * i1) };
            *(float2*)&Pw[(rb + g)     * HSTR + nt * 8 + 2 * tq] = v0;
            *(float2*)&Pw[(rb + g + 8) * HSTR + nt * 8 + 2 * tq] = v1;
        }
    }
    __syncthreads();

    float acc2[2][4];
    #pragma unroll
    for (int nt = 0; nt < 2; nt++)
        #pragma unroll
        for (int i = 0; i < 4; i++) acc2[nt][i] = 0.f;

    #pragma unroll
    for (int k2 = 0; k2 < 8; k2++) {
        const int kb = k2 * 8;
        uint32_t af[4];
        af[0] = ldu(&Pw[(rb + g)     * HSTR + kb + tq]);
        af[1] = ldu(&Pw[(rb + g + 8) * HSTR + kb + tq]);
        af[2] = ldu(&Pw[(rb + g)     * HSTR + kb + tq + 4]);
        af[3] = ldu(&Pw[(rb + g + 8) * HSTR + kb + tq + 4]);
        #pragma unroll
        for (int nt = 0; nt < 2; nt++) {
            uint32_t b0 = ldu(&Gm[(nt * 8 + g) * GSTR + kb + tq]);
            uint32_t b1 = ldu(&Gm[(nt * 8 + g) * GSTR + kb + tq + 4]);
            mma_tf32(acc2[nt], af, b0, b1);
        }
    }

    float* sY = sm + A_T + hl * 16 * HSTR;
    #pragma unroll
    for (int nt = 0; nt < 2; nt++) {
        const int d0 = nt * 8 + 2 * tq, d1 = d0 + 1;
        sY[d0 * HSTR + rb + g]     = rnd32(acc2[nt][0]);
        sY[d1 * HSTR + rb + g]     = rnd32(acc2[nt][1]);
        sY[d0 * HSTR + rb + g + 8] = rnd32(acc2[nt][2]);
        sY[d1 * HSTR + rb + g + 8] = rnd32(acc2[nt][3]);
    }
    __syncthreads();

    #pragma unroll
    for (int i = 0; i < 2; i++) {
        int c = t + 256 * i;
        int ch = c >> 8, d = (c >> 4) & 15, q4 = c & 15;
        *(float4*)(Y + (ch ? base1 : base0) + d * 64 + q4 * 4) =
            *(const float4*)(sm + A_T + ch * 16 * HSTR + d * HSTR + q4 * 4);
    }
}

// ---------------- launch ----------------
extern "C" void kernel_launch(void* const* d_in, const int* in_sizes, int n_in,
                              void* d_out, int out_size)
{
    const float* query   = (const float*)d_in[0];
    const float* context = (const float*)d_in[1];
    const float* Wm = (const float*)d_in[2];
    const float* bm = (const float*)d_in[3];
    const float* Wg = (const float*)d_in[4];
    const float* bg = (const float*)d_in[5];
    const float* Wt = (const float*)d_in[6];
    const float* bt = (const float*)d_in[7];
    const float* Wp = (const float*)d_in[8];
    const float* bp = (const float*)d_in[9];
    const float* Wo = (const float*)d_in[10];
    const float* bo = (const float*)d_in[11];
    float* out = (float*)d_out;

    float *ctx2, *gp, *phip, *thetap, *yp, *wr;
    cudaGetSymbolAddress((void**)&ctx2,   g_ctx2);
    cudaGetSymbolAddress((void**)&gp,     g_g);
    cudaGetSymbolAddress((void**)&phip,   g_phi);
    cudaGetSymbolAddress((void**)&thetap, g_theta);
    cudaGetSymbolAddress((void**)&yp,     g_y);
    cudaGetSymbolAddress((void**)&wr,     g_Wr);

    const float* Wg_r = wr;
    const float* Wp_r = wr + 131072;
    const float* Wt_r = wr + 262144;
    const float* Wo_r = wr + 393216;

    const int GSMEM = (2 * 128 * ASTR + 2 * 32 * BNSTR) * 4;  // 71680 B
    const int XSMEM = (128 * MSTR + 64 * MSTR) * 4;           // 52224 B
    const int ASMEM = A_TOT * 4;                              // 64000 B
    cudaFuncSetAttribute((const void*)gemm_mma<512, 2, false, false, true>,
                         cudaFuncAttributeMaxDynamicSharedMemorySize, GSMEM);
    cudaFuncSetAttribute((const void*)gemm_mma<512, 2, false, true, true>,
                         cudaFuncAttributeMaxDynamicSharedMemorySize, GSMEM);
    cudaFuncSetAttribute((const void*)gemm_mma<256, 4, true, false, false>,
                         cudaFuncAttributeMaxDynamicSharedMemorySize, GSMEM);
    cudaFuncSetAttribute((const void*)mix_mma,
                         cudaFuncAttributeMaxDynamicSharedMemorySize, XSMEM);
    cudaFuncSetAttribute((const void*)attn_mma,
                         cudaFuncAttributeMaxDynamicSharedMemorySize, ASMEM);

    // 0) pre-round weights
    round_w<<<512, 256>>>(Wg, Wp, Wt, Wo, wr);

    // 1) position mixing -> tf32-rounded ctx2
    mix_mma<<<dim3(HEADS, NB / 4), 256, XSMEM>>>(context, Wm, bm, ctx2);

    // 2) projections (128x128 tiles, 2 batches/CTA)
    gemm_mma<512, 2, false, false, true><<<dim3(4, NB / 2), 256, GSMEM>>>(
        Wg_r, Wp_r, bg, bp, INTER, ctx2, nullptr, gp, phip);
    gemm_mma<512, 2, false, true, true><<<dim3(2, NB / 2), 256, GSMEM>>>(
        Wt_r, Wt_r, bt, bt, INTER, query, nullptr, thetap, thetap);

    // 3) attention (cvt-free MMA paths)
    attn_mma<<<dim3(HEADS / 2, NB), 256, ASMEM>>>(thetap, phip, gp, yp);

    // 4) output projection + bias + residual (exact fp32 epilogue)
    gemm_mma<256, 4, true, false, false><<<dim3(4, NB / 2), 256, GSMEM>>>(
        Wo_r, Wo_r, bo, bo, C, yp, query, out, out);
}

// round 8
// speedup vs baseline: 4.5681x; 1.0584x over previous
#include <cuda_runtime.h>
#include <cstdint>

#define NB    1024
#define C     512
#define NP    64
#define HEADS 16
#define INTER 256

// ---------------- scratch (__device__ globals, allocation-free) ----------------
__device__ float g_ctx2[(size_t)NB * C * NP];     // mixed ctx (tf32-rounded), natural
__device__ float g_g[(size_t)NB * INTER * NP];    // tf32-rounded
__device__ float g_phi[(size_t)NB * INTER * NP];  // tf32-rounded
__device__ float g_theta[(size_t)NB * INTER * NP];// tf32-rounded
__device__ float g_y[(size_t)NB * INTER * NP];    // tf32-rounded
__device__ float g_Wr[4 * 131072];                // rounded Wg, Wp, Wt, Wo

// ---------------- helpers ----------------
__device__ __forceinline__ uint32_t smem_u32(const void* p) {
    uint32_t a;
    asm("{ .reg .u64 t; cvta.to.shared.u64 t, %1; cvt.u32.u64 %0, t; }" : "=r"(a) : "l"(p));
    return a;
}
__device__ __forceinline__ void cp_async16(void* dst, const void* src) {
    asm volatile("cp.async.cg.shared.global [%0], [%1], 16;"
                 :: "r"(smem_u32(dst)), "l"(src));
}
#define CP_COMMIT() asm volatile("cp.async.commit_group;" ::: "memory")
#define CP_WAIT(n)  asm volatile("cp.async.wait_group %0;" :: "n"(n) : "memory")

__device__ __forceinline__ uint32_t f2tf32(float f) {
    uint32_t r;
    asm("cvt.rna.tf32.f32 %0, %1;" : "=r"(r) : "f"(f));
    return r;
}
__device__ __forceinline__ float rnd32(float f) { return __uint_as_float(f2tf32(f)); }

__device__ __forceinline__ void mma_tf32(float c[4], const uint32_t a[4], uint32_t b0, uint32_t b1) {
    asm volatile(
        "mma.sync.aligned.m16n8k8.row.col.f32.tf32.tf32.f32 "
        "{%0,%1,%2,%3}, {%4,%5,%6,%7}, {%8,%9}, {%0,%1,%2,%3};"
        : "+f"(c[0]), "+f"(c[1]), "+f"(c[2]), "+f"(c[3])
        : "r"(a[0]), "r"(a[1]), "r"(a[2]), "r"(a[3]), "r"(b0), "r"(b1));
}
__device__ __forceinline__ uint32_t ldu(const float* p) {
    return __float_as_uint(*p);     // operand already tf32-rounded
}

// ---------------- K0: pre-round weights to tf32 ----------------
__global__ __launch_bounds__(256)
void round_w(const float* __restrict__ Wg, const float* __restrict__ Wp,
             const float* __restrict__ Wt, const float* __restrict__ Wo,
             float* __restrict__ dst)
{
    int i = blockIdx.x * 256 + threadIdx.x;   // 131072 elements each
    dst[i]              = rnd32(Wg[i]);
    dst[131072 + i]     = rnd32(Wp[i]);
    dst[262144 + i]     = rnd32(Wt[i]);
    dst[393216 + i]     = rnd32(Wo[i]);
}

// ============================================================================
// K1: position mixing via mma.sync -> ctx2 (tf32-rounded)
// ============================================================================
#define MSTR 68
__global__ __launch_bounds__(256, 2)
void mix_mma(const float* __restrict__ ctx, const float* __restrict__ Wm,
             const float* __restrict__ bm, float* __restrict__ out)
{
    const int h = blockIdx.x;
    const int n0 = blockIdx.y * 4;

    extern __shared__ float sm[];
    float* sA = sm;               // [128][MSTR]
    float* sB = sm + 128 * MSTR;  // [64][MSTR]

    const int t = threadIdx.x;
    const int w = t >> 5, lane = t & 31;
    const int g = lane >> 2, tq = lane & 3;
    const int wm = w & 3, wn = w >> 2;

    #pragma unroll
    for (int i = 0; i < 8; i++) {
        int idx = t + 256 * i;
        int r = idx >> 4, c = idx & 15;
        const float* src = ctx + (((size_t)(n0 + (r >> 5)) * C) + h * 32 + (r & 31)) * NP + c * 4;
        cp_async16(sA + r * MSTR + c * 4, src);
    }
    #pragma unroll
    for (int i = 0; i < 4; i++) {
        int idx = t + 256 * i;
        int r = idx >> 4, c = idx & 15;
        cp_async16(sB + r * MSTR + c * 4, Wm + (size_t)h * 4096 + r * 64 + c * 4);
    }
    CP_COMMIT();
    CP_WAIT(0);
    __syncthreads();

    float acc[2][4][4];
    #pragma unroll
    for (int mt = 0; mt < 2; mt++)
        #pragma unroll
        for (int nt = 0; nt < 4; nt++)
            #pragma unroll
            for (int i = 0; i < 4; i++) acc[mt][nt][i] = 0.f;

    #pragma unroll
    for (int s = 0; s < 8; s++) {
        const int kb = s * 8;
        uint32_t af[2][4];
        #pragma unroll
        for (int mt = 0; mt < 2; mt++) {
            const int rb = wm * 32 + mt * 16;
            af[mt][0] = f2tf32(sA[(rb + g)     * MSTR + kb + tq]);
            af[mt][1] = f2tf32(sA[(rb + g + 8) * MSTR + kb + tq]);
            af[mt][2] = f2tf32(sA[(rb + g)     * MSTR + kb + tq + 4]);
            af[mt][3] = f2tf32(sA[(rb + g + 8) * MSTR + kb + tq + 4]);
        }
        uint32_t bf[4][2];
        #pragma unroll
        for (int nt = 0; nt < 4; nt++) {
            const int nb = wn * 32 + nt * 8;
            bf[nt][0] = f2tf32(sB[(nb + g) * MSTR + kb + tq]);
            bf[nt][1] = f2tf32(sB[(nb + g) * MSTR + kb + tq + 4]);
        }
        #pragma unroll
        for (int mt = 0; mt < 2; mt++)
            #pragma unroll
            for (int nt = 0; nt < 4; nt++)
                mma_tf32(acc[mt][nt], af[mt], bf[nt][0], bf[nt][1]);
    }

    #pragma unroll
    for (int mt = 0; mt < 2; mt++) {
        const int rl0 = wm * 32 + mt * 16 + g;
        const int rl1 = rl0 + 8;
        #pragma unroll
        for (int nt = 0; nt < 4; nt++) {
            const int col = wn * 32 + nt * 8 + tq * 2;
            const float b0 = __ldg(bm + h * 64 + col);
            const float b1 = __ldg(bm + h * 64 + col + 1);
            float2 v0, v1;
            v0.x = rnd32(acc[mt][nt][0] + sA[rl0 * MSTR + col]     + b0);
            v0.y = rnd32(acc[mt][nt][1] + sA[rl0 * MSTR + col + 1] + b1);
            v1.x = rnd32(acc[mt][nt][2] + sA[rl1 * MSTR + col]     + b0);
            v1.y = rnd32(acc[mt][nt][3] + sA[rl1 * MSTR + col + 1] + b1);
            size_t off0 = (((size_t)(n0 + (rl0 >> 5)) * C) + h * 32 + (rl0 & 31)) * NP + col;
            size_t off1 = (((size_t)(n0 + (rl1 >> 5)) * C) + h * 32 + (rl1 & 31)) * NP + col;
            *(float2*)(out + off0) = v0;
            *(float2*)(out + off1) = v1;
        }
    }
}

// ============================================================================
// shared GEMM core: 128 W-rows x 128 tokens (2 batches), mma.sync tf32.
// ============================================================================
#define ASTR  36
#define BNSTR 136
template<int K, bool RESID, bool CVTB, bool ROUND_OUT>
__device__ __forceinline__ void gemm_core(
    const float* __restrict__ W, const float* __restrict__ Xp0,
    const float* __restrict__ Xp1, const float* __restrict__ bias,
    const float* __restrict__ resid, float* __restrict__ Y,
    int MY, int rowoff, int n0, float* sA, float* sB, int t)
{
    const int w = t >> 5, lane = t & 31;
    const int g = lane >> 2, tq = lane & 3;
    const int wm = w & 3, wn = w >> 2;      // warp: 32 rows x 64 cols

    float acc[2][8][4];
    #pragma unroll
    for (int mt = 0; mt < 2; mt++)
        #pragma unroll
        for (int nt = 0; nt < 8; nt++)
            #pragma unroll
            for (int i = 0; i < 4; i++) acc[mt][nt][i] = 0.f;

    constexpr int NIT = K / 32;

    auto copy_tiles = [&](int k0, int buf) {
        float* dA = sA + buf * 128 * ASTR;
        float* dB = sB + buf * 32 * BNSTR;
        #pragma unroll
        for (int i = 0; i < 4; i++) {               // A: 128 rows x 32 k
            int idx = t + 256 * i;
            int r = idx >> 3, c2 = idx & 7;
            cp_async16(dA + r * ASTR + c2 * 4, W + (size_t)r * K + k0 + c2 * 4);
        }
        #pragma unroll
        for (int i = 0; i < 4; i++) {               // B: 32 k x 128 tok (2 batches)
            int idx = t + 256 * i;
            int kk = idx >> 5, c = idx & 31;
            const float* src = ((c < 16) ? Xp0 : Xp1) + (size_t)(k0 + kk) * 64 + (c & 15) * 4;
            cp_async16(dB + kk * BNSTR + c * 4, src);
        }
    };

    copy_tiles(0, 0);
    CP_COMMIT();

    int buf = 0;
    for (int it = 0; it < NIT; ++it) {
        if (it + 1 < NIT) {
            copy_tiles((it + 1) * 32, buf ^ 1);
            CP_COMMIT();
            CP_WAIT(1);
        } else {
            CP_WAIT(0);
        }
        __syncthreads();

        const float* cA = sA + buf * 128 * ASTR;
        const float* cB = sB + buf * 32 * BNSTR;
        #pragma unroll
        for (int s = 0; s < 4; s++) {
            const int kb = s * 8;
            uint32_t af[2][4];
            #pragma unroll
            for (int mt = 0; mt < 2; mt++) {
                const int rb = wm * 32 + mt * 16;
                af[mt][0] = ldu(&cA[(rb + g)     * ASTR + kb + tq]);
                af[mt][1] = ldu(&cA[(rb + g + 8) * ASTR + kb + tq]);
                af[mt][2] = ldu(&cA[(rb + g)     * ASTR + kb + tq + 4]);
                af[mt][3] = ldu(&cA[(rb + g + 8) * ASTR + kb + tq + 4]);
            }
            uint32_t bf[8][2];
            #pragma unroll
            for (int nt = 0; nt < 8; nt++) {
                const int nb = wn * 64 + nt * 8;
                if (CVTB) {
                    bf[nt][0] = f2tf32(cB[(kb + tq)     * BNSTR + nb + g]);
                    bf[nt][1] = f2tf32(cB[(kb + tq + 4) * BNSTR + nb + g]);
                } else {
                    bf[nt][0] = ldu(&cB[(kb + tq)     * BNSTR + nb + g]);
                    bf[nt][1] = ldu(&cB[(kb + tq + 4) * BNSTR + nb + g]);
                }
            }
            #pragma unroll
            for (int mt = 0; mt < 2; mt++)
                #pragma unroll
                for (int nt = 0; nt < 8; nt++)
                    mma_tf32(acc[mt][nt], af[mt], bf[nt][0], bf[nt][1]);
        }
        __syncthreads();
        buf ^= 1;
    }

    #pragma unroll
    for (int mt = 0; mt < 2; mt++) {
        const int rl0 = wm * 32 + mt * 16 + g;
        const int rl1 = rl0 + 8;
        const float bv0 = bias[rl0];
        const float bv1 = bias[rl1];
        #pragma unroll
        for (int nt = 0; nt < 8; nt++) {
            const int gcol = wn * 64 + nt * 8 + tq * 2;
            const int n = n0 + (gcol >> 6);
            const int col = gcol & 63;
            size_t off0 = ((size_t)n * MY + rowoff + rl0) * 64 + col;
            size_t off1 = ((size_t)n * MY + rowoff + rl1) * 64 + col;
            float2 v0, v1;
            v0.x = acc[mt][nt][0] + bv0; v0.y = acc[mt][nt][1] + bv0;
            v1.x = acc[mt][nt][2] + bv1; v1.y = acc[mt][nt][3] + bv1;
            if (RESID) {
                const float2 r0 = *(const float2*)(resid + off0);
                const float2 r1 = *(const float2*)(resid + off1);
                v0.x += r0.x; v0.y += r0.y;
                v1.x += r1.x; v1.y += r1.y;
            }
            if (ROUND_OUT) {
                v0.x = rnd32(v0.x); v0.y = rnd32(v0.y);
                v1.x = rnd32(v1.x); v1.y = rnd32(v1.y);
            }
            *(float2*)(Y + off0) = v0;
            *(float2*)(Y + off1) = v1;
        }
    }
}

// ---- merged projection kernel: tiles 0-1 g, 2-3 phi, 4-5 theta ----
__global__ __launch_bounds__(256, 2)
void proj_mma(const float* __restrict__ Wg, const float* __restrict__ Wp,
              const float* __restrict__ Wt,
              const float* __restrict__ bg, const float* __restrict__ bp,
              const float* __restrict__ bt,
              const float* __restrict__ ctx, const float* __restrict__ query,
              float* __restrict__ Yg, float* __restrict__ Yp, float* __restrict__ Yt)
{
    extern __shared__ float sm[];
    float* sA = sm;
    float* sB = sm + 2 * 128 * ASTR;
    const int t = threadIdx.x;
    const int tile = blockIdx.x;
    const int n0 = blockIdx.y * 2;
    const int rowoff = (tile & 1) * 128;

    if (tile < 4) {
        const float* W    = (tile < 2 ? Wg : Wp) + (size_t)rowoff * 512;
        const float* bias = (tile < 2 ? bg : bp) + rowoff;
        float* Y          = (tile < 2 ? Yg : Yp);
        const float* X0 = ctx + (size_t)n0 * 512 * 64;
        gemm_core<512, false, false, true>(W, X0, X0 + (size_t)512 * 64,
                                           bias, nullptr, Y, INTER, rowoff, n0, sA, sB, t);
    } else {
        const float* W = Wt + (size_t)rowoff * 512;
        const float* X0 = query + (size_t)n0 * 512 * 64;
        gemm_core<512, false, true, true>(W, X0, X0 + (size_t)512 * 64,
                                          bt + rowoff, nullptr, Yt, INTER, rowoff, n0, sA, sB, t);
    }
}

// ---- output projection kernel ----
__global__ __launch_bounds__(256, 2)
void out_mma(const float* __restrict__ Wo, const float* __restrict__ bo,
             const float* __restrict__ Yin, const float* __restrict__ query,
             float* __restrict__ out)
{
    extern __shared__ float sm[];
    float* sA = sm;
    float* sB = sm + 2 * 128 * ASTR;
    const int t = threadIdx.x;
    const int tile = blockIdx.x;
    const int n0 = blockIdx.y * 2;
    const int rowoff = tile * 128;
    const float* X0 = Yin + (size_t)n0 * 256 * 64;
    gemm_core<256, true, false, false>(Wo + (size_t)rowoff * 256, X0, X0 + (size_t)256 * 64,
                                       bo + rowoff, query, out, C, rowoff, n0, sA, sB, t);
}

// ============================================================================
// attention via mma.sync; inputs pre-rounded tf32 -> zero cvt in MMA paths
// ============================================================================
#define HSTR 72
#define GSTR 68
#define A_T   0
#define A_P   (2 * 16 * HSTR)
#define A_G   (A_P + 2 * 16 * HSTR)
#define A_P2  (A_G + 2 * 16 * GSTR)
#define A_TOT (A_P2 + 2 * 64 * HSTR)

__global__ __launch_bounds__(256, 2)
void attn_mma(const float* __restrict__ Th, const float* __restrict__ Ph,
              const float* __restrict__ G, float* __restrict__ Y)
{
    const int hp = blockIdx.x;
    const int n  = blockIdx.y;
    extern __shared__ float sm[];

    const int t = threadIdx.x;
    const int w = t >> 5, lane = t & 31;
    const int g = lane >> 2, tq = lane & 3;
    const int hl = w >> 2;
    const int rb = (w & 3) * 16;

    const size_t base0 = ((size_t)n * INTER + (2 * hp) * 16) * NP;
    const size_t base1 = base0 + 16 * NP;

    #pragma unroll
    for (int i = 0; i < 2; i++) {
        int c = t + 256 * i;
        int ch = c >> 8, r = (c >> 4) & 15, q4 = c & 15;
        size_t src = (ch ? base1 : base0) + r * 64 + q4 * 4;
        cp_async16(sm + A_T + ch * 16 * HSTR + r * HSTR + q4 * 4, Th + src);
        cp_async16(sm + A_P + ch * 16 * HSTR + r * HSTR + q4 * 4, Ph + src);
        cp_async16(sm + A_G + ch * 16 * GSTR + r * GSTR + q4 * 4, G + src);
    }
    CP_COMMIT();
    CP_WAIT(0);
    __syncthreads();

    const float* Tm = sm + A_T + hl * 16 * HSTR;
    const float* Pm = sm + A_P + hl * 16 * HSTR;
    const float* Gm = sm + A_G + hl * 16 * GSTR;
    float*       Pw = sm + A_P2 + hl * 64 * HSTR;

    float sacc[8][4];
    #pragma unroll
    for (int nt = 0; nt < 8; nt++)
        #pragma unroll
        for (int i = 0; i < 4; i++) sacc[nt][i] = 0.f;

    #pragma unroll
    for (int k2 = 0; k2 < 2; k2++) {
        const int kb = k2 * 8;
        uint32_t af[4];
        af[0] = ldu(&Tm[(kb + tq)     * HSTR + rb + g]);
        af[1] = ldu(&Tm[(kb + tq)     * HSTR + rb + g + 8]);
        af[2] = ldu(&Tm[(kb + tq + 4) * HSTR + rb + g]);
        af[3] = ldu(&Tm[(kb + tq + 4) * HSTR + rb + g + 8]);
        #pragma unroll
        for (int nt = 0; nt < 8; nt++) {
            uint32_t b0 = ldu(&Pm[(kb + tq)     * HSTR + nt * 8 + g]);
            uint32_t b1 = ldu(&Pm[(kb + tq + 4) * HSTR + nt * 8 + g]);
            mma_tf32(sacc[nt], af, b0, b1);
        }
    }

    {
        float m0 = -1e30f, m1 = -1e30f;
        #pragma unroll
        for (int nt = 0; nt < 8; nt++) {
            #pragma unroll
            for (int i = 0; i < 4; i++) sacc[nt][i] *= 0.25f;
            m0 = fmaxf(m0, fmaxf(sacc[nt][0], sacc[nt][1]));
            m1 = fmaxf(m1, fmaxf(sacc[nt][2], sacc[nt][3]));
        }
        m0 = fmaxf(m0, __shfl_xor_sync(0xffffffffu, m0, 1));
        m0 = fmaxf(m0, __shfl_xor_sync(0xffffffffu, m0, 2));
        m1 = fmaxf(m1, __shfl_xor_sync(0xffffffffu, m1, 1));
        m1 = fmaxf(m1, __shfl_xor_sync(0xffffffffu, m1, 2));
        float s0 = 0.f, s1 = 0.f;
        #pragma unroll
        for (int nt = 0; nt < 8; nt++) {
            sacc[nt][0] = __expf(sacc[nt][0] - m0);
            sacc[nt][1] = __expf(sacc[nt][1] - m0);
            sacc[nt][2] = __expf(sacc[nt][2] - m1);
            sacc[nt][3] = __expf(sacc[nt][3] - m1);
            s0 += sacc[nt][0] + sacc[nt][1];
            s1 += sacc[nt][2] + sacc[nt][3];
        }
        s0 += __shfl_xor_sync(0xffffffffu, s0, 1);
        s0 += __shfl_xor_sync(0xffffffffu, s0, 2);
        s1 += __shfl_xor_sync(0xffffffffu, s1, 1);
        s1 += __shfl_xor_sync(0xffffffffu, s1, 2);
        const float i0 = 1.0f / s0, i1 = 1.0f / s1;
        #pragma unroll
        for (int nt = 0; nt < 8; nt++) {
            float2 v0 = { rnd32(sacc[nt][0] * i0), rnd32(sacc[nt][1] * i0) };
            float2 v1 = { rnd32(sacc[nt][2] * i1), rnd32(sacc[nt][3] * i1) };
            *(float2*)&Pw[(rb + g)     * HSTR + nt * 8 + 2 * tq] = v0;
            *(float2*)&Pw[(rb + g + 8) * HSTR + nt * 8 + 2 * tq] = v1;
        }
    }
    __syncthreads();

    float acc2[2][4];
    #pragma unroll
    for (int nt = 0; nt < 2; nt++)
        #pragma unroll
        for (int i = 0; i < 4; i++) acc2[nt][i] = 0.f;

    #pragma unroll
    for (int k2 = 0; k2 < 8; k2++) {
        const int kb = k2 * 8;
        uint32_t af[4];
        af[0] = ldu(&Pw[(rb + g)     * HSTR + kb + tq]);
        af[1] = ldu(&Pw[(rb + g + 8) * HSTR + kb + tq]);
        af[2] = ldu(&Pw[(rb + g)     * HSTR + kb + tq + 4]);
        af[3] = ldu(&Pw[(rb + g + 8) * HSTR + kb + tq + 4]);
        #pragma unroll
        for (int nt = 0; nt < 2; nt++) {
            uint32_t b0 = ldu(&Gm[(nt * 8 + g) * GSTR + kb + tq]);
            uint32_t b1 = ldu(&Gm[(nt * 8 + g) * GSTR + kb + tq + 4]);
            mma_tf32(acc2[nt], af, b0, b1);
        }
    }

    float* sY = sm + A_T + hl * 16 * HSTR;
    #pragma unroll
    for (int nt = 0; nt < 2; nt++) {
        const int d0 = nt * 8 + 2 * tq, d1 = d0 + 1;
        sY[d0 * HSTR + rb + g]     = rnd32(acc2[nt][0]);
        sY[d1 * HSTR + rb + g]     = rnd32(acc2[nt][1]);
        sY[d0 * HSTR + rb + g + 8] = rnd32(acc2[nt][2]);
        sY[d1 * HSTR + rb + g + 8] = rnd32(acc2[nt][3]);
    }
    __syncthreads();

    #pragma unroll
    for (int i = 0; i < 2; i++) {
        int c = t + 256 * i;
        int ch = c >> 8, d = (c >> 4) & 15, q4 = c & 15;
        *(float4*)(Y + (ch ? base1 : base0) + d * 64 + q4 * 4) =
            *(const float4*)(sm + A_T + ch * 16 * HSTR + d * HSTR + q4 * 4);
    }
}

// ---------------- launch ----------------
extern "C" void kernel_launch(void* const* d_in, const int* in_sizes, int n_in,
                              void* d_out, int out_size)
{
    const float* query   = (const float*)d_in[0];
    const float* context = (const float*)d_in[1];
    const float* Wm = (const float*)d_in[2];
    const float* bm = (const float*)d_in[3];
    const float* Wg = (const float*)d_in[4];
    const float* bg = (const float*)d_in[5];
    const float* Wt = (const float*)d_in[6];
    const float* bt = (const float*)d_in[7];
    const float* Wp = (const float*)d_in[8];
    const float* bp = (const float*)d_in[9];
    const float* Wo = (const float*)d_in[10];
    const float* bo = (const float*)d_in[11];
    float* out = (float*)d_out;

    float *ctx2, *gp, *phip, *thetap, *yp, *wr;
    cudaGetSymbolAddress((void**)&ctx2,   g_ctx2);
    cudaGetSymbolAddress((void**)&gp,     g_g);
    cudaGetSymbolAddress((void**)&phip,   g_phi);
    cudaGetSymbolAddress((void**)&thetap, g_theta);
    cudaGetSymbolAddress((void**)&yp,     g_y);
    cudaGetSymbolAddress((void**)&wr,     g_Wr);

    const float* Wg_r = wr;
    const float* Wp_r = wr + 131072;
    const float* Wt_r = wr + 262144;
    const float* Wo_r = wr + 393216;

    const int GSMEM = (2 * 128 * ASTR + 2 * 32 * BNSTR) * 4;  // 71680 B
    const int XSMEM = (128 * MSTR + 64 * MSTR) * 4;           // 52224 B
    const int ASMEM = A_TOT * 4;                              // 64000 B
    cudaFuncSetAttribute((const void*)proj_mma,
                         cudaFuncAttributeMaxDynamicSharedMemorySize, GSMEM);
    cudaFuncSetAttribute((const void*)out_mma,
                         cudaFuncAttributeMaxDynamicSharedMemorySize, GSMEM);
    cudaFuncSetAttribute((const void*)mix_mma,
                         cudaFuncAttributeMaxDynamicSharedMemorySize, XSMEM);
    cudaFuncSetAttribute((const void*)attn_mma,
                         cudaFuncAttributeMaxDynamicSharedMemorySize, ASMEM);

    // 0) pre-round weights
    round_w<<<512, 256>>>(Wg, Wp, Wt, Wo, wr);

    // 1) position mixing -> tf32-rounded ctx2
    mix_mma<<<dim3(HEADS, NB / 4), 256, XSMEM>>>(context, Wm, bm, ctx2);

    // 2) merged projections: g (tiles 0-1), phi (2-3), theta (4-5)
    proj_mma<<<dim3(6, NB / 2), 256, GSMEM>>>(
        Wg_r, Wp_r, Wt_r, bg, bp, bt, ctx2, query, gp, phip, thetap);

    // 3) attention (cvt-free MMA paths)
    attn_mma<<<dim3(HEADS / 2, NB), 256, ASMEM>>>(thetap, phip, gp, yp);

    // 4) output projection + bias + residual
    out_mma<<<dim3(4, NB / 2), 256, GSMEM>>>(Wo_r, bo, yp, query, out);
}

// round 9
// speedup vs baseline: 6.3857x; 1.3979x over previous
#include <cuda_runtime.h>
#include <cuda_bf16.h>
#include <cstdint>

#define NB    1024
#define C     512
#define NP    64
#define HEADS 16
#define INTER 256

// ---------------- scratch (__device__ globals, allocation-free) ----------------
// packed bf16x2 formats:
//  ctxp/qp : per n [256 chp][64 tok] u32, pair along channel (lo = even ch)
//  thp/php : per n [128 chp][64 tok] u32, pair along channel
//  gp2     : per n [32 tokp][256 ch] u32, pair along token (lo = even tok)
//  yp      : per n [128 chp][64 tok] u32, pair along channel
__device__ unsigned g_ctxp[(size_t)NB * 256 * 64];
__device__ unsigned g_qp[(size_t)NB * 256 * 64];
__device__ unsigned g_thp[(size_t)NB * 128 * 64];
__device__ unsigned g_php[(size_t)NB * 128 * 64];
__device__ unsigned g_gp2[(size_t)NB * 32 * 256];
__device__ unsigned g_yp[(size_t)NB * 128 * 64];
__device__ unsigned g_Wbf[262144];   // Wg,Wp,Wt (65536 u32 each) + Wo (65536)

// ---------------- helpers ----------------
__device__ __forceinline__ uint32_t smem_u32(const void* p) {
    uint32_t a;
    asm("{ .reg .u64 t; cvta.to.shared.u64 t, %1; cvt.u32.u64 %0, t; }" : "=r"(a) : "l"(p));
    return a;
}
__device__ __forceinline__ void cp_async16(void* dst, const void* src) {
    asm volatile("cp.async.cg.shared.global [%0], [%1], 16;"
                 :: "r"(smem_u32(dst)), "l"(src));
}
#define CP_COMMIT() asm volatile("cp.async.commit_group;" ::: "memory")
#define CP_WAIT(n)  asm volatile("cp.async.wait_group %0;" :: "n"(n) : "memory")

__device__ __forceinline__ uint32_t f2tf32(float f) {
    uint32_t r;
    asm("cvt.rna.tf32.f32 %0, %1;" : "=r"(r) : "f"(f));
    return r;
}
// pack (lo, hi) -> bf16x2 u32 (lo in low half, matching memory order of pairs)
__device__ __forceinline__ uint32_t packbf(float lo, float hi) {
    uint32_t r;
    asm("cvt.rn.bf16x2.f32 %0, %1, %2;" : "=r"(r) : "f"(hi), "f"(lo));
    return r;
}
__device__ __forceinline__ void mma_tf32(float c[4], const uint32_t a[4], uint32_t b0, uint32_t b1) {
    asm volatile(
        "mma.sync.aligned.m16n8k8.row.col.f32.tf32.tf32.f32 "
        "{%0,%1,%2,%3}, {%4,%5,%6,%7}, {%8,%9}, {%0,%1,%2,%3};"
        : "+f"(c[0]), "+f"(c[1]), "+f"(c[2]), "+f"(c[3])
        : "r"(a[0]), "r"(a[1]), "r"(a[2]), "r"(a[3]), "r"(b0), "r"(b1));
}
__device__ __forceinline__ void mma_bf16(float c[4], const uint32_t a[4], uint32_t b0, uint32_t b1) {
    asm volatile(
        "mma.sync.aligned.m16n8k16.row.col.f32.bf16.bf16.f32 "
        "{%0,%1,%2,%3}, {%4,%5,%6,%7}, {%8,%9}, {%0,%1,%2,%3};"
        : "+f"(c[0]), "+f"(c[1]), "+f"(c[2]), "+f"(c[3])
        : "r"(a[0]), "r"(a[1]), "r"(a[2]), "r"(a[3]), "r"(b0), "r"(b1));
}

// ---------------- K0a: pack weights to bf16 pairs (k-contiguous) ----------------
__global__ __launch_bounds__(256)
void round_w(const float* __restrict__ Wg, const float* __restrict__ Wp,
             const float* __restrict__ Wt, const float* __restrict__ Wo,
             unsigned* __restrict__ dst)
{
    int i = blockIdx.x * 256 + threadIdx.x;   // 65536 pairs per matrix
    dst[i]              = packbf(Wg[2 * i], Wg[2 * i + 1]);
    dst[65536 + i]      = packbf(Wp[2 * i], Wp[2 * i + 1]);
    dst[131072 + i]     = packbf(Wt[2 * i], Wt[2 * i + 1]);
    dst[196608 + i]     = packbf(Wo[2 * i], Wo[2 * i + 1]);
}

// ---------------- K0b: pack query into [chp][tok] bf16x2 ----------------
__global__ __launch_bounds__(256)
void pack_q(const float4* __restrict__ q, uint4* __restrict__ qp)
{
    size_t gid = (size_t)blockIdx.x * 256 + threadIdx.x;  // 4.19M uint4
    size_t row = gid >> 4;            // global chp row (n*256 + kp)
    int tk = (int)(gid & 15);
    float4 lo = q[row * 32 + tk];          // ch = 2kp
    float4 hi = q[row * 32 + 16 + tk];     // ch = 2kp+1
    uint4 r;
    r.x = packbf(lo.x, hi.x);
    r.y = packbf(lo.y, hi.y);
    r.z = packbf(lo.z, hi.z);
    r.w = packbf(lo.w, hi.w);
    qp[gid] = r;
}

// ============================================================================
// K1: position mixing via tf32 mma -> ctxp (bf16 pair-interleaved)
// ============================================================================
#define MSTR 68
__global__ __launch_bounds__(256, 2)
void mix_mma(const float* __restrict__ ctx, const float* __restrict__ Wm,
             const float* __restrict__ bm, unsigned* __restrict__ ctxp)
{
    const int h = blockIdx.x;
    const int n0 = blockIdx.y * 4;

    extern __shared__ unsigned smem_u[];
    float* sm = (float*)smem_u;
    float* sA = sm;               // [128][MSTR]
    float* sB = sm + 128 * MSTR;  // [64][MSTR]

    const int t = threadIdx.x;
    const int w = t >> 5, lane = t & 31;
    const int g = lane >> 2, tq = lane & 3;
    const int wm = w & 3, wn = w >> 2;

    #pragma unroll
    for (int i = 0; i < 8; i++) {
        int idx = t + 256 * i;
        int r = idx >> 4, c = idx & 15;
        const float* src = ctx + (((size_t)(n0 + (r >> 5)) * C) + h * 32 + (r & 31)) * NP + c * 4;
        cp_async16(sA + r * MSTR + c * 4, src);
    }
    #pragma unroll
    for (int i = 0; i < 4; i++) {
        int idx = t + 256 * i;
        int r = idx >> 4, c = idx & 15;
        cp_async16(sB + r * MSTR + c * 4, Wm + (size_t)h * 4096 + r * 64 + c * 4);
    }
    CP_COMMIT();
    CP_WAIT(0);
    __syncthreads();

    float acc[2][4][4];
    #pragma unroll
    for (int mt = 0; mt < 2; mt++)
        #pragma unroll
        for (int nt = 0; nt < 4; nt++)
            #pragma unroll
            for (int i = 0; i < 4; i++) acc[mt][nt][i] = 0.f;

    #pragma unroll
    for (int s = 0; s < 8; s++) {
        const int kb = s * 8;
        uint32_t af[2][4];
        #pragma unroll
        for (int mt = 0; mt < 2; mt++) {
            const int rb = wm * 32 + mt * 16;
            af[mt][0] = f2tf32(sA[(rb + g)     * MSTR + kb + tq]);
            af[mt][1] = f2tf32(sA[(rb + g + 8) * MSTR + kb + tq]);
            af[mt][2] = f2tf32(sA[(rb + g)     * MSTR + kb + tq + 4]);
            af[mt][3] = f2tf32(sA[(rb + g + 8) * MSTR + kb + tq + 4]);
        }
        uint32_t bf[4][2];
        #pragma unroll
        for (int nt = 0; nt < 4; nt++) {
            const int nb = wn * 32 + nt * 8;
            bf[nt][0] = f2tf32(sB[(nb + g) * MSTR + kb + tq]);
            bf[nt][1] = f2tf32(sB[(nb + g) * MSTR + kb + tq + 4]);
        }
        #pragma unroll
        for (int mt = 0; mt < 2; mt++)
            #pragma unroll
            for (int nt = 0; nt < 4; nt++)
                mma_tf32(acc[mt][nt], af[mt], bf[nt][0], bf[nt][1]);
    }
    __syncthreads();   // sB reads done CTA-wide before reusing as staging

    // epilogue: +ctx +bm, pack channel-pairs via shfl, stage, coalesced store
    unsigned* sOut = (unsigned*)sB;   // [64][65] u32
    #pragma unroll
    for (int mt = 0; mt < 2; mt++) {
        const int rl0 = wm * 32 + mt * 16 + g;   // d = mt*16+g, nl = wm
        const int rl1 = rl0 + 8;
        #pragma unroll
        for (int nt = 0; nt < 4; nt++) {
            const int col = wn * 32 + nt * 8 + tq * 2;
            const float b0 = __ldg(bm + h * 64 + col);
            const float b1 = __ldg(bm + h * 64 + col + 1);
            float v00 = acc[mt][nt][0] + sA[rl0 * MSTR + col]     + b0;
            float v01 = acc[mt][nt][1] + sA[rl0 * MSTR + col + 1] + b1;
            float v10 = acc[mt][nt][2] + sA[rl1 * MSTR + col]     + b0;
            float v11 = acc[mt][nt][3] + sA[rl1 * MSTR + col + 1] + b1;
            float n00 = __shfl_down_sync(0xffffffffu, v00, 4);
            float n01 = __shfl_down_sync(0xffffffffu, v01, 4);
            float n10 = __shfl_down_sync(0xffffffffu, v10, 4);
            float n11 = __shfl_down_sync(0xffffffffu, v11, 4);
            if (!(g & 1)) {
                int srow0 = wm * 16 + mt * 8 + (g >> 1);
                int srow1 = srow0 + 4;
                sOut[srow0 * 65 + col]     = packbf(v00, n00);
                sOut[srow0 * 65 + col + 1] = packbf(v01, n01);
                sOut[srow1 * 65 + col]     = packbf(v10, n10);
                sOut[srow1 * 65 + col + 1] = packbf(v11, n11);
            }
        }
    }
    __syncthreads();
    #pragma unroll
    for (int i = 0; i < 16; i++) {
        int idx = t + 256 * i;              // < 4096
        int row = idx >> 6, tok = idx & 63;
        int nl = row >> 4, dp = row & 15;
        ctxp[((size_t)(n0 + nl) * 256 + h * 16 + dp) * 64 + tok] = sOut[row * 65 + tok];
    }
}

// ============================================================================
// bf16 GEMM core: 128 W-rows x 128 tokens (2 batches), m16n8k16.
// EPI: 0 = write [chp][tok] packed (theta/phi/...), 1 = write gp2 [tokp][ch],
//      2 = fp32 + bias + resid -> out
// ============================================================================
template<int K, int EPI>
__device__ __forceinline__ void gemm_bf16_core(
    const unsigned* __restrict__ W,                       // [128][K/2] u32
    const unsigned* __restrict__ X0, const unsigned* __restrict__ X1,  // [K/2][64]
    const float* __restrict__ bias, const float* __restrict__ resid,
    float* __restrict__ Yf, unsigned* __restrict__ Yu,
    int rowoff, int n0, unsigned* sA, unsigned* sB, int t)
{
    const int w = t >> 5, lane = t & 31;
    const int g = lane >> 2, tq = lane & 3;
    const int wm = w & 3, wn = w >> 2;

    float acc[2][8][4];
    #pragma unroll
    for (int mt = 0; mt < 2; mt++)
        #pragma unroll
        for (int nt = 0; nt < 8; nt++)
            #pragma unroll
            for (int i = 0; i < 4; i++) acc[mt][nt][i] = 0.f;

    constexpr int NIT = K / 32;

    auto copy_tiles = [&](int k0, int buf) {
        unsigned* dA = sA + buf * 128 * 20;
        unsigned* dB = sB + buf * 16 * 136;
        #pragma unroll
        for (int i = 0; i < 2; i++) {               // A: 128 rows x 16 u32
            int idx = t + 256 * i;
            int r = idx >> 2, c4 = idx & 3;
            cp_async16(dA + r * 20 + c4 * 4, W + (size_t)r * (K / 2) + (k0 >> 1) + c4 * 4);
        }
        #pragma unroll
        for (int i = 0; i < 2; i++) {               // B: 16 kp x 128 tok
            int idx = t + 256 * i;
            int r = idx >> 5, c = idx & 31;
            const unsigned* src = ((c < 16) ? X0 : X1) + (size_t)((k0 >> 1) + r) * 64 + (c & 15) * 4;
            cp_async16(dB + r * 136 + c * 4, src);
        }
    };

    copy_tiles(0, 0);
    CP_COMMIT();

    int buf = 0;
    for (int it = 0; it < NIT; ++it) {
        if (it + 1 < NIT) {
            copy_tiles((it + 1) * 32, buf ^ 1);
            CP_COMMIT();
            CP_WAIT(1);
        } else {
            CP_WAIT(0);
        }
        __syncthreads();

        const unsigned* cA = sA + buf * 128 * 20;
        const unsigned* cB = sB + buf * 16 * 136;
        #pragma unroll
        for (int j = 0; j < 2; j++) {               // two k16 steps per 32-k chunk
            uint32_t af[2][4];
            #pragma unroll
            for (int mt = 0; mt < 2; mt++) {
                const int rb = wm * 32 + mt * 16;
                af[mt][0] = cA[(rb + g)     * 20 + j * 8 + tq];
                af[mt][1] = cA[(rb + g + 8) * 20 + j * 8 + tq];
                af[mt][2] = cA[(rb + g)     * 20 + j * 8 + tq + 4];
                af[mt][3] = cA[(rb + g + 8) * 20 + j * 8 + tq + 4];
            }
            uint32_t bf[8][2];
            #pragma unroll
            for (int nt = 0; nt < 8; nt++) {
                const int nb = wn * 64 + nt * 8;
                bf[nt][0] = cB[(j * 8 + tq)     * 136 + nb + g];
                bf[nt][1] = cB[(j * 8 + tq + 4) * 136 + nb + g];
            }
            #pragma unroll
            for (int mt = 0; mt < 2; mt++)
                #pragma unroll
                for (int nt = 0; nt < 8; nt++)
                    mma_bf16(acc[mt][nt], af[mt], bf[nt][0], bf[nt][1]);
        }
        __syncthreads();
        buf ^= 1;
    }

    if (EPI == 2) {
        // fp32 epilogue + bias + residual
        #pragma unroll
        for (int mt = 0; mt < 2; mt++) {
            const int rl0 = wm * 32 + mt * 16 + g;
            const int rl1 = rl0 + 8;
            const float bv0 = bias[rl0];
            const float bv1 = bias[rl1];
            #pragma unroll
            for (int nt = 0; nt < 8; nt++) {
                const int gcol = wn * 64 + nt * 8 + tq * 2;
                const int n = n0 + (gcol >> 6);
                const int col = gcol & 63;
                size_t off0 = ((size_t)n * 512 + rowoff + rl0) * 64 + col;
                size_t off1 = ((size_t)n * 512 + rowoff + rl1) * 64 + col;
                float2 v0, v1;
                v0.x = acc[mt][nt][0] + bv0; v0.y = acc[mt][nt][1] + bv0;
                v1.x = acc[mt][nt][2] + bv1; v1.y = acc[mt][nt][3] + bv1;
                const float2 r0 = *(const float2*)(resid + off0);
                const float2 r1 = *(const float2*)(resid + off1);
                v0.x += r0.x; v0.y += r0.y;
                v1.x += r1.x; v1.y += r1.y;
                *(float2*)(Yf + off0) = v0;
                *(float2*)(Yf + off1) = v1;
            }
        }
    } else if (EPI == 1) {
        // gp2: in-thread token-pair pack, [tokp][256 ch]
        #pragma unroll
        for (int mt = 0; mt < 2; mt++) {
            const int rl0 = wm * 32 + mt * 16 + g;
            const int rl1 = rl0 + 8;
            const float bv0 = bias[rl0];
            const float bv1 = bias[rl1];
            #pragma unroll
            for (int nt = 0; nt < 8; nt++) {
                const int gcol = wn * 64 + nt * 8 + tq * 2;
                const int n = n0 + (gcol >> 6);
                const int colp = (gcol & 63) >> 1;
                size_t base = (size_t)n * 8192 + (size_t)colp * 256 + rowoff;
                Yu[base + rl0] = packbf(acc[mt][nt][0] + bv0, acc[mt][nt][1] + bv0);
                Yu[base + rl1] = packbf(acc[mt][nt][2] + bv1, acc[mt][nt][3] + bv1);
            }
        }
    } else {
        // [chp][tok]: channel-pair pack via shfl, stage, coalesced store
        unsigned* sOut = sA;   // [64][129] u32 (spans sA+sB, safe post-sync)
        #pragma unroll
        for (int mt = 0; mt < 2; mt++) {
            const int rl0 = wm * 32 + mt * 16 + g;
            const int rl1 = rl0 + 8;
            const float bv0 = bias[rl0];
            const float bv1 = bias[rl1];
            #pragma unroll
            for (int nt = 0; nt < 8; nt++) {
                const int gcol = wn * 64 + nt * 8 + tq * 2;
                float v00 = acc[mt][nt][0] + bv0;
                float v01 = acc[mt][nt][1] + bv0;
                float v10 = acc[mt][nt][2] + bv1;
                float v11 = acc[mt][nt][3] + bv1;
                float n00 = __shfl_down_sync(0xffffffffu, v00, 4);
                float n01 = __shfl_down_sync(0xffffffffu, v01, 4);
                float n10 = __shfl_down_sync(0xffffffffu, v10, 4);
                float n11 = __shfl_down_sync(0xffffffffu, v11, 4);
                if (!(g & 1)) {
                    const int r0 = rl0 >> 1, r1 = rl1 >> 1;
                    sOut[r0 * 129 + gcol]     = packbf(v00, n00);
                    sOut[r0 * 129 + gcol + 1] = packbf(v01, n01);
                    sOut[r1 * 129 + gcol]     = packbf(v10, n10);
                    sOut[r1 * 129 + gcol + 1] = packbf(v11, n11);
                }
            }
        }
        __syncthreads();
        #pragma unroll
        for (int i = 0; i < 32; i++) {
            int idx = t + 256 * i;              // < 8192
            int chp = idx >> 7, c = idx & 127;
            int n = n0 + (c >> 6), tok = c & 63;
            Yu[((size_t)n * 128 + (rowoff >> 1) + chp) * 64 + tok] = sOut[chp * 129 + c];
        }
    }
}

// ---- merged projections: tiles 0-1 g (EPI1), 2-3 phi (EPI0), 4-5 theta (EPI0) ----
__global__ __launch_bounds__(256, 2)
void proj_mma(const unsigned* __restrict__ Wgb, const unsigned* __restrict__ Wpb,
              const unsigned* __restrict__ Wtb,
              const float* __restrict__ bg, const float* __restrict__ bp,
              const float* __restrict__ bt,
              const unsigned* __restrict__ ctxp, const unsigned* __restrict__ qp,
              unsigned* __restrict__ gp2, unsigned* __restrict__ php,
              unsigned* __restrict__ thp)
{
    extern __shared__ unsigned smem_u[];
    unsigned* sA = smem_u;
    unsigned* sB = smem_u + 2 * 128 * 20;
    const int t = threadIdx.x;
    const int tile = blockIdx.x;
    const int n0 = blockIdx.y * 2;
    const int rowoff = (tile & 1) * 128;

    if (tile < 2) {
        const unsigned* X0 = ctxp + (size_t)n0 * 16384;
        gemm_bf16_core<512, 1>(Wgb + (size_t)rowoff * 256, X0, X0 + 16384,
                               bg + rowoff, nullptr, nullptr, gp2, rowoff, n0, sA, sB, t);
    } else if (tile < 4) {
        const unsigned* X0 = ctxp + (size_t)n0 * 16384;
        gemm_bf16_core<512, 0>(Wpb + (size_t)rowoff * 256, X0, X0 + 16384,
                               bp + rowoff, nullptr, nullptr, php, rowoff, n0, sA, sB, t);
    } else {
        const unsigned* X0 = qp + (size_t)n0 * 16384;
        gemm_bf16_core<512, 0>(Wtb + (size_t)rowoff * 256, X0, X0 + 16384,
                               bt + rowoff, nullptr, nullptr, thp, rowoff, n0, sA, sB, t);
    }
}

// ---- output projection ----
__global__ __launch_bounds__(256, 2)
void out_mma(const unsigned* __restrict__ Wob, const float* __restrict__ bo,
             const unsigned* __restrict__ yp, const float* __restrict__ query,
             float* __restrict__ out)
{
    extern __shared__ unsigned smem_u[];
    unsigned* sA = smem_u;
    unsigned* sB = smem_u + 2 * 128 * 20;
    const int t = threadIdx.x;
    const int rowoff = blockIdx.x * 128;
    const int n0 = blockIdx.y * 2;
    const unsigned* X0 = yp + (size_t)n0 * 8192;
    gemm_bf16_core<256, 2>(Wob + (size_t)rowoff * 128, X0, X0 + 8192,
                           bo + rowoff, query, out, nullptr, rowoff, n0, sA, sB, t);
}

// ============================================================================
// attention, bf16 mma end-to-end. CTA = (n, 2 heads), 8 warps.
// S: 1 mma per 8 tokens (K=16=d). AV: 4x2 mmas (K=64 tokens).
// ============================================================================
#define AT  0
#define AP  1152
#define AG  2304
#define APP 3840
#define ATOT 8448   // u32

__global__ __launch_bounds__(256, 3)
void attn_mma(const unsigned* __restrict__ thp, const unsigned* __restrict__ php,
              const unsigned* __restrict__ gp2, unsigned* __restrict__ yp)
{
    extern __shared__ unsigned smem_u[];
    const int hp = blockIdx.x;
    const int n  = blockIdx.y;
    const int t = threadIdx.x;
    const int w = t >> 5, lane = t & 31;
    const int g = lane >> 2, tq = lane & 3;
    const int hl = w >> 2;
    const int rb = (w & 3) * 16;

    {   // loads: theta/phi [8 dp][64 tok] stride 72; g [32 tokp][16 ch] stride 24
        int hd = t >> 7, dp = (t >> 4) & 7, c4 = t & 15;
        size_t srcTP = ((size_t)n * 128 + (2 * hp + hd) * 8 + dp) * 64 + c4 * 4;
        cp_async16(smem_u + AT + hd * 576 + dp * 72 + c4 * 4, thp + srcTP);
        cp_async16(smem_u + AP + hd * 576 + dp * 72 + c4 * 4, php + srcTP);
        int tokp = (t >> 2) & 31, c4g = t & 3;
        cp_async16(smem_u + AG + hd * 768 + tokp * 24 + c4g * 4,
                   gp2 + (size_t)n * 8192 + (size_t)tokp * 256 + (2 * hp + hd) * 16 + c4g * 4);
    }
    CP_COMMIT();
    CP_WAIT(0);
    __syncthreads();

    const unsigned* Tm = smem_u + AT + hl * 576;
    const unsigned* Pm = smem_u + AP + hl * 576;
    const unsigned* Gm = smem_u + AG + hl * 768;
    unsigned*       Pp = smem_u + APP + hl * 2304;   // [64 q][36] tokp-packed

    // ---- S = theta^T phi : M=16 q, N=64 tok, K=16 d (one mma per n-block) ----
    float sacc[8][4];
    #pragma unroll
    for (int nt = 0; nt < 8; nt++)
        #pragma unroll
        for (int i = 0; i < 4; i++) sacc[nt][i] = 0.f;
    {
        uint32_t af[4];
        af[0] = Tm[tq * 72 + rb + g];
        af[1] = Tm[tq * 72 + rb + g + 8];
        af[2] = Tm[(tq + 4) * 72 + rb + g];
        af[3] = Tm[(tq + 4) * 72 + rb + g + 8];
        #pragma unroll
        for (int nt = 0; nt < 8; nt++) {
            uint32_t b0 = Pm[tq * 72 + nt * 8 + g];
            uint32_t b1 = Pm[(tq + 4) * 72 + nt * 8 + g];
            mma_bf16(sacc[nt], af, b0, b1);
        }
    }

    // ---- softmax in registers ----
    {
        float m0 = -1e30f, m1 = -1e30f;
        #pragma unroll
        for (int nt = 0; nt < 8; nt++) {
            #pragma unroll
            for (int i = 0; i < 4; i++) sacc[nt][i] *= 0.25f;
            m0 = fmaxf(m0, fmaxf(sacc[nt][0], sacc[nt][1]));
            m1 = fmaxf(m1, fmaxf(sacc[nt][2], sacc[nt][3]));
        }
        m0 = fmaxf(m0, __shfl_xor_sync(0xffffffffu, m0, 1));
        m0 = fmaxf(m0, __shfl_xor_sync(0xffffffffu, m0, 2));
        m1 = fmaxf(m1, __shfl_xor_sync(0xffffffffu, m1, 1));
        m1 = fmaxf(m1, __shfl_xor_sync(0xffffffffu, m1, 2));
        float s0 = 0.f, s1 = 0.f;
        #pragma unroll
        for (int nt = 0; nt < 8; nt++) {
            sacc[nt][0] = __expf(sacc[nt][0] - m0);
            sacc[nt][1] = __expf(sacc[nt][1] - m0);
            sacc[nt][2] = __expf(sacc[nt][2] - m1);
            sacc[nt][3] = __expf(sacc[nt][3] - m1);
            s0 += sacc[nt][0] + sacc[nt][1];
            s1 += sacc[nt][2] + sacc[nt][3];
        }
        s0 += __shfl_xor_sync(0xffffffffu, s0, 1);
        s0 += __shfl_xor_sync(0xffffffffu, s0, 2);
        s1 += __shfl_xor_sync(0xffffffffu, s1, 1);
        s1 += __shfl_xor_sync(0xffffffffu, s1, 2);
        const float i0 = 1.0f / s0, i1 = 1.0f / s1;
        #pragma unroll
        for (int nt = 0; nt < 8; nt++) {   // in-thread token-pair pack
            Pp[(rb + g)     * 36 + nt * 4 + tq] = packbf(sacc[nt][0] * i0, sacc[nt][1] * i0);
            Pp[(rb + g + 8) * 36 + nt * 4 + tq] = packbf(sacc[nt][2] * i1, sacc[nt][3] * i1);
        }
    }
    __syncwarp();   // Pp is warp-private

    // ---- Y^T = P @ G^T : M=16 q, N=16 d, K=64 tok ----
    float acc2[2][4];
    #pragma unroll
    for (int nt = 0; nt < 2; nt++)
        #pragma unroll
        for (int i = 0; i < 4; i++) acc2[nt][i] = 0.f;

    #pragma unroll
    for (int j = 0; j < 4; j++) {
        uint32_t pa[4];
        pa[0] = Pp[(rb + g)     * 36 + j * 8 + tq];
        pa[1] = Pp[(rb + g + 8) * 36 + j * 8 + tq];
        pa[2] = Pp[(rb + g)     * 36 + j * 8 + tq + 4];
        pa[3] = Pp[(rb + g + 8) * 36 + j * 8 + tq + 4];
        #pragma unroll
        for (int nt = 0; nt < 2; nt++) {
            uint32_t b0 = Gm[(j * 8 + tq)     * 24 + nt * 8 + g];
            uint32_t b1 = Gm[(j * 8 + tq + 4) * 24 + nt * 8 + g];
            mma_bf16(acc2[nt], pa, b0, b1);
        }
    }

    // ---- store y in [chp][tok] packed (in-thread d-pair pack) ----
    const int hgl = 2 * hp + hl;
    #pragma unroll
    for (int nt = 0; nt < 2; nt++) {
        const int chp = hgl * 8 + nt * 4 + tq;
        yp[((size_t)n * 128 + chp) * 64 + rb + g]     = packbf(acc2[nt][0], acc2[nt][1]);
        yp[((size_t)n * 128 + chp) * 64 + rb + g + 8] = packbf(acc2[nt][2], acc2[nt][3]);
    }
}

// ---------------- launch ----------------
extern "C" void kernel_launch(void* const* d_in, const int* in_sizes, int n_in,
                              void* d_out, int out_size)
{
    const float* query   = (const float*)d_in[0];
    const float* context = (const float*)d_in[1];
    const float* Wm = (const float*)d_in[2];
    const float* bm = (const float*)d_in[3];
    const float* Wg = (const float*)d_in[4];
    const float* bg = (const float*)d_in[5];
    const float* Wt = (const float*)d_in[6];
    const float* bt = (const float*)d_in[7];
    const float* Wp = (const float*)d_in[8];
    const float* bp = (const float*)d_in[9];
    const float* Wo = (const float*)d_in[10];
    const float* bo = (const float*)d_in[11];
    float* out = (float*)d_out;

    unsigned *ctxp, *qp, *thp, *php, *gp2, *yp, *wr;
    cudaGetSymbolAddress((void**)&ctxp, g_ctxp);
    cudaGetSymbolAddress((void**)&qp,   g_qp);
    cudaGetSymbolAddress((void**)&thp,  g_thp);
    cudaGetSymbolAddress((void**)&php,  g_php);
    cudaGetSymbolAddress((void**)&gp2,  g_gp2);
    cudaGetSymbolAddress((void**)&yp,   g_yp);
    cudaGetSymbolAddress((void**)&wr,   g_Wbf);

    const unsigned* Wgb = wr;
    const unsigned* Wpb = wr + 65536;
    const unsigned* Wtb = wr + 131072;
    const unsigned* Wob = wr + 196608;

    const int GSMEM = (2 * 128 * 20 + 2 * 16 * 136) * 4;  // 37888 B
    const int XSMEM = (128 * MSTR + 64 * MSTR) * 4;       // 52224 B
    const int ASMEM = ATOT * 4;                           // 33792 B
    cudaFuncSetAttribute((const void*)proj_mma,
                         cudaFuncAttributeMaxDynamicSharedMemorySize, GSMEM);
    cudaFuncSetAttribute((const void*)out_mma,
                         cudaFuncAttributeMaxDynamicSharedMemorySize, GSMEM);
    cudaFuncSetAttribute((const void*)mix_mma,
                         cudaFuncAttributeMaxDynamicSharedMemorySize, XSMEM);
    cudaFuncSetAttribute((const void*)attn_mma,
                         cudaFuncAttributeMaxDynamicSharedMemorySize, ASMEM);

    // 0) pack weights + query to bf16
    round_w<<<256, 256>>>(Wg, Wp, Wt, Wo, wr);
    pack_q<<<16384, 256>>>((const float4*)query, (uint4*)qp);

    // 1) position mixing -> bf16 pair-interleaved ctxp
    mix_mma<<<dim3(HEADS, NB / 4), 256, XSMEM>>>(context, Wm, bm, ctxp);

    // 2) merged projections (bf16 mma)
    proj_mma<<<dim3(6, NB / 2), 256, GSMEM>>>(
        Wgb, Wpb, Wtb, bg, bp, bt, ctxp, qp, gp2, php, thp);

    // 3) attention (bf16 mma end-to-end)
    attn_mma<<<dim3(HEADS / 2, NB), 256, ASMEM>>>(thp, php, gp2, yp);

    // 4) output projection + bias + residual (fp32 epilogue)
    out_mma<<<dim3(4, NB / 2), 256, GSMEM>>>(Wob, bo, yp, query, out);
}

// round 11
// speedup vs baseline: 6.5123x; 1.0198x over previous
#include <cuda_runtime.h>
#include <cuda_bf16.h>
#include <cstdint>

#define NB    1024
#define C     512
#define NP    64
#define HEADS 16
#define INTER 256

// ---------------- scratch (__device__ globals, allocation-free) ----------------
//  ctxp    : per n [256 chp][64 tok] u32, bf16 pair along channel (lo = even ch)
//  thp/php : per n [128 chp][64 tok] u32, pair along channel
//  gp2     : per n [32 tokp][256 ch] u32, pair along token (lo = even tok)
//  yp      : per n [128 chp][64 tok] u32, pair along channel
__device__ unsigned g_ctxp[(size_t)NB * 256 * 64];
__device__ unsigned g_thp[(size_t)NB * 128 * 64];
__device__ unsigned g_php[(size_t)NB * 128 * 64];
__device__ unsigned g_gp2[(size_t)NB * 32 * 256];
__device__ unsigned g_yp[(size_t)NB * 128 * 64];
__device__ unsigned g_Wbf[262144];   // Wg,Wp,Wt,Wo (65536 u32 each)

// ---------------- helpers ----------------
__device__ __forceinline__ uint32_t smem_u32(const void* p) {
    uint32_t a;
    asm("{ .reg .u64 t; cvta.to.shared.u64 t, %1; cvt.u32.u64 %0, t; }" : "=r"(a) : "l"(p));
    return a;
}
__device__ __forceinline__ void cp_async16(void* dst, const void* src) {
    asm volatile("cp.async.cg.shared.global [%0], [%1], 16;"
                 :: "r"(smem_u32(dst)), "l"(src));
}
#define CP_COMMIT() asm volatile("cp.async.commit_group;" ::: "memory")
#define CP_WAIT(n)  asm volatile("cp.async.wait_group %0;" :: "n"(n) : "memory")

__device__ __forceinline__ uint32_t f2tf32(float f) {
    uint32_t r;
    asm("cvt.rna.tf32.f32 %0, %1;" : "=r"(r) : "f"(f));
    return r;
}
__device__ __forceinline__ uint32_t packbf(float lo, float hi) {
    uint32_t r;
    asm("cvt.rn.bf16x2.f32 %0, %1, %2;" : "=r"(r) : "f"(hi), "f"(lo));
    return r;
}
__device__ __forceinline__ void mma_tf32(float c[4], const uint32_t a[4], uint32_t b0, uint32_t b1) {
    asm volatile(
        "mma.sync.aligned.m16n8k8.row.col.f32.tf32.tf32.f32 "
        "{%0,%1,%2,%3}, {%4,%5,%6,%7}, {%8,%9}, {%0,%1,%2,%3};"
        : "+f"(c[0]), "+f"(c[1]), "+f"(c[2]), "+f"(c[3])
        : "r"(a[0]), "r"(a[1]), "r"(a[2]), "r"(a[3]), "r"(b0), "r"(b1));
}
__device__ __forceinline__ void mma_bf16(float c[4], const uint32_t a[4], uint32_t b0, uint32_t b1) {
    asm volatile(
        "mma.sync.aligned.m16n8k16.row.col.f32.bf16.bf16.f32 "
        "{%0,%1,%2,%3}, {%4,%5,%6,%7}, {%8,%9}, {%0,%1,%2,%3};"
        : "+f"(c[0]), "+f"(c[1]), "+f"(c[2]), "+f"(c[3])
        : "r"(a[0]), "r"(a[1]), "r"(a[2]), "r"(a[3]), "r"(b0), "r"(b1));
}

// ---------------- K0: pack weights to bf16 pairs (k-contiguous) ----------------
__global__ __launch_bounds__(256)
void round_w(const float* __restrict__ Wg, const float* __restrict__ Wp,
             const float* __restrict__ Wt, const float* __restrict__ Wo,
             unsigned* __restrict__ dst)
{
    int i = blockIdx.x * 256 + threadIdx.x;   // 65536 pairs per matrix
    dst[i]              = packbf(Wg[2 * i], Wg[2 * i + 1]);
    dst[65536 + i]      = packbf(Wp[2 * i], Wp[2 * i + 1]);
    dst[131072 + i]     = packbf(Wt[2 * i], Wt[2 * i + 1]);
    dst[196608 + i]     = packbf(Wo[2 * i], Wo[2 * i + 1]);
}

// ============================================================================
// K1: position mixing via tf32 mma -> ctxp (bf16 pair-interleaved)
// ============================================================================
#define MSTR 68
__global__ __launch_bounds__(256, 2)
void mix_mma(const float* __restrict__ ctx, const float* __restrict__ Wm,
             const float* __restrict__ bm, unsigned* __restrict__ ctxp)
{
    const int h = blockIdx.x;
    const int n0 = blockIdx.y * 4;

    extern __shared__ unsigned smem_u[];
    float* sm = (float*)smem_u;
    float* sA = sm;               // [128][MSTR]
    float* sB = sm + 128 * MSTR;  // [64][MSTR]

    const int t = threadIdx.x;
    const int w = t >> 5, lane = t & 31;
    const int g = lane >> 2, tq = lane & 3;
    const int wm = w & 3, wn = w >> 2;

    #pragma unroll
    for (int i = 0; i < 8; i++) {
        int idx = t + 256 * i;
        int r = idx >> 4, c = idx & 15;
        const float* src = ctx + (((size_t)(n0 + (r >> 5)) * C) + h * 32 + (r & 31)) * NP + c * 4;
        cp_async16(sA + r * MSTR + c * 4, src);
    }
    #pragma unroll
    for (int i = 0; i < 4; i++) {
        int idx = t + 256 * i;
        int r = idx >> 4, c = idx & 15;
        cp_async16(sB + r * MSTR + c * 4, Wm + (size_t)h * 4096 + r * 64 + c * 4);
    }
    CP_COMMIT();
    CP_WAIT(0);
    __syncthreads();

    float acc[2][4][4];
    #pragma unroll
    for (int mt = 0; mt < 2; mt++)
        #pragma unroll
        for (int nt = 0; nt < 4; nt++)
            #pragma unroll
            for (int i = 0; i < 4; i++) acc[mt][nt][i] = 0.f;

    #pragma unroll
    for (int s = 0; s < 8; s++) {
        const int kb = s * 8;
        uint32_t af[2][4];
        #pragma unroll
        for (int mt = 0; mt < 2; mt++) {
            const int rb = wm * 32 + mt * 16;
            af[mt][0] = f2tf32(sA[(rb + g)     * MSTR + kb + tq]);
            af[mt][1] = f2tf32(sA[(rb + g + 8) * MSTR + kb + tq]);
            af[mt][2] = f2tf32(sA[(rb + g)     * MSTR + kb + tq + 4]);
            af[mt][3] = f2tf32(sA[(rb + g + 8) * MSTR + kb + tq + 4]);
        }
        uint32_t bf[4][2];
        #pragma unroll
        for (int nt = 0; nt < 4; nt++) {
            const int nb = wn * 32 + nt * 8;
            bf[nt][0] = f2tf32(sB[(nb + g) * MSTR + kb + tq]);
            bf[nt][1] = f2tf32(sB[(nb + g) * MSTR + kb + tq + 4]);
        }
        #pragma unroll
        for (int mt = 0; mt < 2; mt++)
            #pragma unroll
            for (int nt = 0; nt < 4; nt++)
                mma_tf32(acc[mt][nt], af[mt], bf[nt][0], bf[nt][1]);
    }
    __syncthreads();

    unsigned* sOut = (unsigned*)sB;   // [64][65] u32
    #pragma unroll
    for (int mt = 0; mt < 2; mt++) {
        const int rl0 = wm * 32 + mt * 16 + g;
        const int rl1 = rl0 + 8;
        #pragma unroll
        for (int nt = 0; nt < 4; nt++) {
            const int col = wn * 32 + nt * 8 + tq * 2;
            const float b0 = __ldg(bm + h * 64 + col);
            const float b1 = __ldg(bm + h * 64 + col + 1);
            float v00 = acc[mt][nt][0] + sA[rl0 * MSTR + col]     + b0;
            float v01 = acc[mt][nt][1] + sA[rl0 * MSTR + col + 1] + b1;
            float v10 = acc[mt][nt][2] + sA[rl1 * MSTR + col]     + b0;
            float v11 = acc[mt][nt][3] + sA[rl1 * MSTR + col + 1] + b1;
            float n00 = __shfl_down_sync(0xffffffffu, v00, 4);
            float n01 = __shfl_down_sync(0xffffffffu, v01, 4);
            float n10 = __shfl_down_sync(0xffffffffu, v10, 4);
            float n11 = __shfl_down_sync(0xffffffffu, v11, 4);
            if (!(g & 1)) {
                int srow0 = wm * 16 + mt * 8 + (g >> 1);
                int srow1 = srow0 + 4;
                sOut[srow0 * 65 + col]     = packbf(v00, n00);
                sOut[srow0 * 65 + col + 1] = packbf(v01, n01);
                sOut[srow1 * 65 + col]     = packbf(v10, n10);
                sOut[srow1 * 65 + col + 1] = packbf(v11, n11);
            }
        }
    }
    __syncthreads();
    #pragma unroll
    for (int i = 0; i < 16; i++) {
        int idx = t + 256 * i;
        int row = idx >> 6, tok = idx & 63;
        int nl = row >> 4, dp = row & 15;
        ctxp[((size_t)(n0 + nl) * 256 + h * 16 + dp) * 64 + tok] = sOut[row * 65 + tok];
    }
}

// ============================================================================
// bf16 GEMM core, 3-stage cp.async pipeline. 128 W-rows x 128 tokens.
// BF32: B operand is raw fp32 (packed to bf16 at fragment read).
// EPI: 0 = [chp][tok] packed out, 1 = gp2 [tokp][ch], 2 = fp32+bias+resid
// ============================================================================
#define ASZ  2560            // 128 x 20 u32
#define BSZP 2176            // 16 x 136 u32 (packed)
#define BSZF 4224            // 32 x 132 u32 (fp32)
template<int K, int EPI, bool BF32>
__device__ __forceinline__ void gemm_bf16_core(
    const unsigned* __restrict__ W,
    const void* __restrict__ X0v, const void* __restrict__ X1v,
    const float* __restrict__ bias, const float* __restrict__ resid,
    float* __restrict__ Yf, unsigned* __restrict__ Yu,
    int rowoff, int n0, unsigned* smb, int t)
{
    constexpr int BSZ = BF32 ? BSZF : BSZP;
    constexpr int STG = ASZ + BSZ;
    constexpr int NIT = K / 32;

    const int w = t >> 5, lane = t & 31;
    const int g = lane >> 2, tq = lane & 3;
    const int wm = w & 3, wn = w >> 2;

    float acc[2][8][4];
    #pragma unroll
    for (int mt = 0; mt < 2; mt++)
        #pragma unroll
        for (int nt = 0; nt < 8; nt++)
            #pragma unroll
            for (int i = 0; i < 4; i++) acc[mt][nt][i] = 0.f;

    auto copy_tiles = [&](int k0, int slot) {
        unsigned* dA = smb + slot * STG;
        unsigned* dB = dA + ASZ;
        #pragma unroll
        for (int i = 0; i < 2; i++) {               // A: 128 rows x 16 u32
            int idx = t + 256 * i;
            int r = idx >> 2, c4 = idx & 3;
            cp_async16(dA + r * 20 + c4 * 4, W + (size_t)r * (K / 2) + (k0 >> 1) + c4 * 4);
        }
        if (BF32) {
            const float* X0 = (const float*)X0v;
            const float* X1 = (const float*)X1v;
            #pragma unroll
            for (int i = 0; i < 4; i++) {           // B: 32 k x 128 tok fp32
                int idx = t + 256 * i;
                int r = idx >> 5, c = idx & 31;
                const float* src = ((c < 16) ? X0 : X1) + (size_t)(k0 + r) * 64 + (c & 15) * 4;
                cp_async16((float*)dB + r * 132 + c * 4, src);
            }
        } else {
            const unsigned* X0 = (const unsigned*)X0v;
            const unsigned* X1 = (const unsigned*)X1v;
            #pragma unroll
            for (int i = 0; i < 2; i++) {           // B: 16 kp x 128 tok u32
                int idx = t + 256 * i;
                int r = idx >> 5, c = idx & 31;
                const unsigned* src = ((c < 16) ? X0 : X1) + (size_t)((k0 >> 1) + r) * 64 + (c & 15) * 4;
                cp_async16(dB + r * 136 + c * 4, src);
            }
        }
    };

    copy_tiles(0, 0);
    CP_COMMIT();
    copy_tiles(32, 1);
    CP_COMMIT();

    for (int it = 0; it < NIT; ++it) {
        if (it < NIT - 1) { CP_WAIT(1); } else { CP_WAIT(0); }
        __syncthreads();
        if (it + 2 < NIT) {
            copy_tiles((it + 2) * 32, (it + 2) % 3);
            CP_COMMIT();
        }

        const unsigned* cA = smb + (it % 3) * STG;
        const unsigned* cB = cA + ASZ;
        #pragma unroll
        for (int j = 0; j < 2; j++) {
            uint32_t af[2][4];
            #pragma unroll
            for (int mt = 0; mt < 2; mt++) {
                const int rb = wm * 32 + mt * 16;
                af[mt][0] = cA[(rb + g)     * 20 + j * 8 + tq];
                af[mt][1] = cA[(rb + g + 8) * 20 + j * 8 + tq];
                af[mt][2] = cA[(rb + g)     * 20 + j * 8 + tq + 4];
                af[mt][3] = cA[(rb + g + 8) * 20 + j * 8 + tq + 4];
            }
            uint32_t bf[8][2];
            if (BF32) {
                const float* fB = (const float*)cB;
                const float* r0 = fB + (j * 16 + 2 * tq) * 132;
                const float* r1 = r0 + 132;
                const float* r2 = fB + (j * 16 + 2 * tq + 8) * 132;
                const float* r3 = r2 + 132;
                #pragma unroll
                for (int nt = 0; nt < 8; nt++) {
                    const int col = wn * 64 + nt * 8 + g;
                    bf[nt][0] = packbf(r0[col], r1[col]);
                    bf[nt][1] = packbf(r2[col], r3[col]);
                }
            } else {
                #pragma unroll
                for (int nt = 0; nt < 8; nt++) {
                    const int nb = wn * 64 + nt * 8;
                    bf[nt][0] = cB[(j * 8 + tq)     * 136 + nb + g];
                    bf[nt][1] = cB[(j * 8 + tq + 4) * 136 + nb + g];
                }
            }
            #pragma unroll
            for (int mt = 0; mt < 2; mt++)
                #pragma unroll
                for (int nt = 0; nt < 8; nt++)
                    mma_bf16(acc[mt][nt], af[mt], bf[nt][0], bf[nt][1]);
        }
    }
    __syncthreads();

    if (EPI == 2) {
        #pragma unroll
        for (int mt = 0; mt < 2; mt++) {
            const int rl0 = wm * 32 + mt * 16 + g;
            const int rl1 = rl0 + 8;
            const float bv0 = bias[rl0];
            const float bv1 = bias[rl1];
            #pragma unroll
            for (int nt = 0; nt < 8; nt++) {
                const int gcol = wn * 64 + nt * 8 + tq * 2;
                const int n = n0 + (gcol >> 6);
                const int col = gcol & 63;
                size_t off0 = ((size_t)n * 512 + rowoff + rl0) * 64 + col;
                size_t off1 = ((size_t)n * 512 + rowoff + rl1) * 64 + col;
                float2 v0, v1;
                v0.x = acc[mt][nt][0] + bv0; v0.y = acc[mt][nt][1] + bv0;
                v1.x = acc[mt][nt][2] + bv1; v1.y = acc[mt][nt][3] + bv1;
                const float2 r0 = *(const float2*)(resid + off0);
                const float2 r1 = *(const float2*)(resid + off1);
                v0.x += r0.x; v0.y += r0.y;
                v1.x += r1.x; v1.y += r1.y;
                *(float2*)(Yf + off0) = v0;
                *(float2*)(Yf + off1) = v1;
            }
        }
    } else if (EPI == 1) {
        #pragma unroll
        for (int mt = 0; mt < 2; mt++) {
            const int rl0 = wm * 32 + mt * 16 + g;
            const int rl1 = rl0 + 8;
            const float bv0 = bias[rl0];
            const float bv1 = bias[rl1];
            #pragma unroll
            for (int nt = 0; nt < 8; nt++) {
                const int gcol = wn * 64 + nt * 8 + tq * 2;
                const int n = n0 + (gcol >> 6);
                const int colp = (gcol & 63) >> 1;
                size_t base = (size_t)n * 8192 + (size_t)colp * 256 + rowoff;
                Yu[base + rl0] = packbf(acc[mt][nt][0] + bv0, acc[mt][nt][1] + bv0);
                Yu[base + rl1] = packbf(acc[mt][nt][2] + bv1, acc[mt][nt][3] + bv1);
            }
        }
    } else {
        unsigned* sOut = smb;   // [64][129] u32
        #pragma unroll
        for (int mt = 0; mt < 2; mt++) {
            const int rl0 = wm * 32 + mt * 16 + g;
            const int rl1 = rl0 + 8;
            const float bv0 = bias[rl0];
            const float bv1 = bias[rl1];
            #pragma unroll
            for (int nt = 0; nt < 8; nt++) {
                const int gcol = wn * 64 + nt * 8 + tq * 2;
                float v00 = acc[mt][nt][0] + bv0;
                float v01 = acc[mt][nt][1] + bv0;
                float v10 = acc[mt][nt][2] + bv1;
                float v11 = acc[mt][nt][3] + bv1;
                float n00 = __shfl_down_sync(0xffffffffu, v00, 4);
                float n01 = __shfl_down_sync(0xffffffffu, v01, 4);
                float n10 = __shfl_down_sync(0xffffffffu, v10, 4);
                float n11 = __shfl_down_sync(0xffffffffu, v11, 4);
                if (!(g & 1)) {
                    const int r0 = rl0 >> 1, r1 = rl1 >> 1;
                    sOut[r0 * 129 + gcol]     = packbf(v00, n00);
                    sOut[r0 * 129 + gcol + 1] = packbf(v01, n01);
                    sOut[r1 * 129 + gcol]     = packbf(v10, n10);
                    sOut[r1 * 129 + gcol + 1] = packbf(v11, n11);
                }
            }
        }
        __syncthreads();
        #pragma unroll
        for (int i = 0; i < 32; i++) {
            int idx = t + 256 * i;
            int chp = idx >> 7, c = idx & 127;
            int n = n0 + (c >> 6), tok = c & 63;
            Yu[((size_t)n * 128 + (rowoff >> 1) + chp) * 64 + tok] = sOut[chp * 129 + c];
        }
    }
}

// ---- merged projections: tiles 0-1 g (EPI1), 2-3 phi (EPI0), 4-5 theta (EPI0+BF32) ----
__global__ __launch_bounds__(256, 2)
void proj_mma(const unsigned* __restrict__ Wgb, const unsigned* __restrict__ Wpb,
              const unsigned* __restrict__ Wtb,
              const float* __restrict__ bg, const float* __restrict__ bp,
              const float* __restrict__ bt,
              const unsigned* __restrict__ ctxp, const float* __restrict__ query,
              unsigned* __restrict__ gp2, unsigned* __restrict__ php,
              unsigned* __restrict__ thp)
{
    extern __shared__ unsigned smem_u[];
    const int t = threadIdx.x;
    const int tile = blockIdx.x;
    const int n0 = blockIdx.y * 2;
    const int rowoff = (tile & 1) * 128;

    if (tile < 2) {
        const unsigned* X0 = ctxp + (size_t)n0 * 16384;
        gemm_bf16_core<512, 1, false>(Wgb + (size_t)rowoff * 256, X0, X0 + 16384,
                                      bg + rowoff, nullptr, nullptr, gp2, rowoff, n0, smem_u, t);
    } else if (tile < 4) {
        const unsigned* X0 = ctxp + (size_t)n0 * 16384;
        gemm_bf16_core<512, 0, false>(Wpb + (size_t)rowoff * 256, X0, X0 + 16384,
                                      bp + rowoff, nullptr, nullptr, php, rowoff, n0, smem_u, t);
    } else {
        const float* X0 = query + (size_t)n0 * 512 * 64;
        gemm_bf16_core<512, 0, true>(Wtb + (size_t)rowoff * 256, X0, X0 + 512 * 64,
                                     bt + rowoff, nullptr, nullptr, thp, rowoff, n0, smem_u, t);
    }
}

// ---- output projection ----
__global__ __launch_bounds__(256, 2)
void out_mma(const unsigned* __restrict__ Wob, const float* __restrict__ bo,
             const unsigned* __restrict__ yp, const float* __restrict__ query,
             float* __restrict__ out)
{
    extern __shared__ unsigned smem_u[];
    const int t = threadIdx.x;
    const int rowoff = blockIdx.x * 128;
    const int n0 = blockIdx.y * 2;
    const unsigned* X0 = yp + (size_t)n0 * 8192;
    gemm_bf16_core<256, 2, false>(Wob + (size_t)rowoff * 128, X0, X0 + 8192,
                                  bo + rowoff, query, out, nullptr, rowoff, n0, smem_u, t);
}

// ============================================================================
// attention, bf16 mma end-to-end (unchanged from round 9)
// ============================================================================
#define AT  0
#define AP  1152
#define AG  2304
#define APP 3840
#define ATOT 8448   // u32

__global__ __launch_bounds__(256, 3)
void attn_mma(const unsigned* __restrict__ thp, const unsigned* __restrict__ php,
              const unsigned* __restrict__ gp2, unsigned* __restrict__ yp)
{
    extern __shared__ unsigned smem_u[];
    const int hp = blockIdx.x;
    const int n  = blockIdx.y;
    const int t = threadIdx.x;
    const int w = t >> 5, lane = t & 31;
    const int g = lane >> 2, tq = lane & 3;
    const int hl = w >> 2;
    const int rb = (w & 3) * 16;

    {
        int hd = t >> 7, dp = (t >> 4) & 7, c4 = t & 15;
        size_t srcTP = ((size_t)n * 128 + (2 * hp + hd) * 8 + dp) * 64 + c4 * 4;
        cp_async16(smem_u + AT + hd * 576 + dp * 72 + c4 * 4, thp + srcTP);
        cp_async16(smem_u + AP + hd * 576 + dp * 72 + c4 * 4, php + srcTP);
        int tokp = (t >> 2) & 31, c4g = t & 3;
        cp_async16(smem_u + AG + hd * 768 + tokp * 24 + c4g * 4,
                   gp2 + (size_t)n * 8192 + (size_t)tokp * 256 + (2 * hp + hd) * 16 + c4g * 4);
    }
    CP_COMMIT();
    CP_WAIT(0);
    __syncthreads();

    const unsigned* Tm = smem_u + AT + hl * 576;
    const unsigned* Pm = smem_u + AP + hl * 576;
    const unsigned* Gm = smem_u + AG + hl * 768;
    unsigned*       Pp = smem_u + APP + hl * 2304;

    float sacc[8][4];
    #pragma unroll
    for (int nt = 0; nt < 8; nt++)
        #pragma unroll
        for (int i = 0; i < 4; i++) sacc[nt][i] = 0.f;
    {
        uint32_t af[4];
        af[0] = Tm[tq * 72 + rb + g];
        af[1] = Tm[tq * 72 + rb + g + 8];
        af[2] = Tm[(tq + 4) * 72 + rb + g];
        af[3] = Tm[(tq + 4) * 72 + rb + g + 8];
        #pragma unroll
        for (int nt = 0; nt < 8; nt++) {
            uint32_t b0 = Pm[tq * 72 + nt * 8 + g];
            uint32_t b1 = Pm[(tq + 4) * 72 + nt * 8 + g];
            mma_bf16(sacc[nt], af, b0, b1);
        }
    }

    {
        float m0 = -1e30f, m1 = -1e30f;
        #pragma unroll
        for (int nt = 0; nt < 8; nt++) {
            #pragma unroll
            for (int i = 0; i < 4; i++) sacc[nt][i] *= 0.25f;
            m0 = fmaxf(m0, fmaxf(sacc[nt][0], sacc[nt][1]));
            m1 = fmaxf(m1, fmaxf(sacc[nt][2], sacc[nt][3]));
        }
        m0 = fmaxf(m0, __shfl_xor_sync(0xffffffffu, m0, 1));
        m0 = fmaxf(m0, __shfl_xor_sync(0xffffffffu, m0, 2));
        m1 = fmaxf(m1, __shfl_xor_sync(0xffffffffu, m1, 1));
        m1 = fmaxf(m1, __shfl_xor_sync(0xffffffffu, m1, 2));
        float s0 = 0.f, s1 = 0.f;
        #pragma unroll
        for (int nt = 0; nt < 8; nt++) {
            sacc[nt][0] = __expf(sacc[nt][0] - m0);
            sacc[nt][1] = __expf(sacc[nt][1] - m0);
            sacc[nt][2] = __expf(sacc[nt][2] - m1);
            sacc[nt][3] = __expf(sacc[nt][3] - m1);
            s0 += sacc[nt][0] + sacc[nt][1];
            s1 += sacc[nt][2] + sacc[nt][3];
        }
        s0 += __shfl_xor_sync(0xffffffffu, s0, 1);
        s0 += __shfl_xor_sync(0xffffffffu, s0, 2);
        s1 += __shfl_xor_sync(0xffffffffu, s1, 1);
        s1 += __shfl_xor_sync(0xffffffffu, s1, 2);
        const float i0 = 1.0f / s0, i1 = 1.0f / s1;
        #pragma unroll
        for (int nt = 0; nt < 8; nt++) {
            Pp[(rb + g)     * 36 + nt * 4 + tq] = packbf(sacc[nt][0] * i0, sacc[nt][1] * i0);
            Pp[(rb + g + 8) * 36 + nt * 4 + tq] = packbf(sacc[nt][2] * i1, sacc[nt][3] * i1);
        }
    }
    __syncwarp();

    float acc2[2][4];
    #pragma unroll
    for (int nt = 0; nt < 2; nt++)
        #pragma unroll
        for (int i = 0; i < 4; i++) acc2[nt][i] = 0.f;

    #pragma unroll
    for (int j = 0; j < 4; j++) {
        uint32_t pa[4];
        pa[0] = Pp[(rb + g)     * 36 + j * 8 + tq];
        pa[1] = Pp[(rb + g + 8) * 36 + j * 8 + tq];
        pa[2] = Pp[(rb + g)     * 36 + j * 8 + tq + 4];
        pa[3] = Pp[(rb + g + 8) * 36 + j * 8 + tq + 4];
        #pragma unroll
        for (int nt = 0; nt < 2; nt++) {
            uint32_t b0 = Gm[(j * 8 + tq)     * 24 + nt * 8 + g];
            uint32_t b1 = Gm[(j * 8 + tq + 4) * 24 + nt * 8 + g];
            mma_bf16(acc2[nt], pa, b0, b1);
        }
    }

    const int hgl = 2 * hp + hl;
    #pragma unroll
    for (int nt = 0; nt < 2; nt++) {
        const int chp = hgl * 8 + nt * 4 + tq;
        yp[((size_t)n * 128 + chp) * 64 + rb + g]     = packbf(acc2[nt][0], acc2[nt][1]);
        yp[((size_t)n * 128 + chp) * 64 + rb + g + 8] = packbf(acc2[nt][2], acc2[nt][3]);
    }
}

// ---------------- launch ----------------
extern "C" void kernel_launch(void* const* d_in, const int* in_sizes, int n_in,
                              void* d_out, int out_size)
{
    const float* query   = (const float*)d_in[0];
    const float* context = (const float*)d_in[1];
    const float* Wm = (const float*)d_in[2];
    const float* bm = (const float*)d_in[3];
    const float* Wg = (const float*)d_in[4];
    const float* bg = (const float*)d_in[5];
    const float* Wt = (const float*)d_in[6];
    const float* bt = (const float*)d_in[7];
    const float* Wp = (const float*)d_in[8];
    const float* bp = (const float*)d_in[9];
    const float* Wo = (const float*)d_in[10];
    const float* bo = (const float*)d_in[11];
    float* out = (float*)d_out;

    unsigned *ctxp, *thp, *php, *gp2, *yp, *wr;
    cudaGetSymbolAddress((void**)&ctxp, g_ctxp);
    cudaGetSymbolAddress((void**)&thp,  g_thp);
    cudaGetSymbolAddress((void**)&php,  g_php);
    cudaGetSymbolAddress((void**)&gp2,  g_gp2);
    cudaGetSymbolAddress((void**)&yp,   g_yp);
    cudaGetSymbolAddress((void**)&wr,   g_Wbf);

    const unsigned* Wgb = wr;
    const unsigned* Wpb = wr + 65536;
    const unsigned* Wtb = wr + 131072;
    const unsigned* Wob = wr + 196608;

    const int PSMEM = 3 * (ASZ + BSZF) * 4;               // 81408 B (theta path is max)
    const int OSMEM = 3 * (ASZ + BSZP) * 4;               // 56832 B
    const int XSMEM = (128 * MSTR + 64 * MSTR) * 4;       // 52224 B
    const int ASMEM = ATOT * 4;                           // 33792 B
    cudaFuncSetAttribute((const void*)proj_mma,
                         cudaFuncAttributeMaxDynamicSharedMemorySize, PSMEM);
    cudaFuncSetAttribute((const void*)out_mma,
                         cudaFuncAttributeMaxDynamicSharedMemorySize, OSMEM);
    cudaFuncSetAttribute((const void*)mix_mma,
                         cudaFuncAttributeMaxDynamicSharedMemorySize, XSMEM);
    cudaFuncSetAttribute((const void*)attn_mma,
                         cudaFuncAttributeMaxDynamicSharedMemorySize, ASMEM);

    // 0) pack weights to bf16
    round_w<<<256, 256>>>(Wg, Wp, Wt, Wo, wr);

    // 1) position mixing -> bf16 pair-interleaved ctxp
    mix_mma<<<dim3(HEADS, NB / 4), 256, XSMEM>>>(context, Wm, bm, ctxp);

    // 2) merged projections (3-stage pipeline; theta packs raw query in-loop)
    proj_mma<<<dim3(6, NB / 2), 256, PSMEM>>>(
        Wgb, Wpb, Wtb, bg, bp, bt, ctxp, query, gp2, php, thp);

    // 3) attention (bf16 mma end-to-end)
    attn_mma<<<dim3(HEADS / 2, NB), 256, ASMEM>>>(thp, php, gp2, yp);

    // 4) output projection + bias + residual (fp32 epilogue)
    out_mma<<<dim3(4, NB / 2), 256, OSMEM>>>(Wob, bo, yp, query, out);
}

// round 16
// speedup vs baseline: 6.8050x; 1.0449x over previous
#include <cuda_runtime.h>
#include <cuda_bf16.h>
#include <cstdint>

#define NB    1024
#define C     512
#define NP    64
#define HEADS 16
#define INTER 256

// ---------------- scratch (__device__ globals, allocation-free) ----------------
//  ctxp/qp : per n [256 chp][64 tok] u32, bf16 pair along channel (lo = even ch)
//  thp/php : per n [128 chp][64 tok] u32, pair along channel
//  gp2     : per n [32 tokp][256 ch] u32, pair along token (lo = even tok)
//  yp      : per n [128 chp][64 tok] u32, pair along channel
__device__ unsigned g_ctxp[(size_t)NB * 256 * 64];
__device__ unsigned g_qp[(size_t)NB * 256 * 64];
__device__ unsigned g_thp[(size_t)NB * 128 * 64];
__device__ unsigned g_php[(size_t)NB * 128 * 64];
__device__ unsigned g_gp2[(size_t)NB * 32 * 256];
__device__ unsigned g_yp[(size_t)NB * 128 * 64];
__device__ unsigned g_Wbf[262144];   // Wg,Wp,Wt,Wo (65536 u32 each)

// ---------------- helpers ----------------
__device__ __forceinline__ uint32_t smem_u32(const void* p) {
    uint32_t a;
    asm("{ .reg .u64 t; cvta.to.shared.u64 t, %1; cvt.u32.u64 %0, t; }" : "=r"(a) : "l"(p));
    return a;
}
__device__ __forceinline__ void cp_async16(void* dst, const void* src) {
    asm volatile("cp.async.cg.shared.global [%0], [%1], 16;"
                 :: "r"(smem_u32(dst)), "l"(src));
}
#define CP_COMMIT() asm volatile("cp.async.commit_group;" ::: "memory")
#define CP_WAIT(n)  asm volatile("cp.async.wait_group %0;" :: "n"(n) : "memory")

__device__ __forceinline__ uint32_t f2tf32(float f) {
    uint32_t r;
    asm("cvt.rna.tf32.f32 %0, %1;" : "=r"(r) : "f"(f));
    return r;
}
__device__ __forceinline__ uint32_t packbf(float lo, float hi) {
    uint32_t r;
    asm("cvt.rn.bf16x2.f32 %0, %1, %2;" : "=r"(r) : "f"(hi), "f"(lo));
    return r;
}
__device__ __forceinline__ void mma_tf32(float c[4], const uint32_t a[4], uint32_t b0, uint32_t b1) {
    asm volatile(
        "mma.sync.aligned.m16n8k8.row.col.f32.tf32.tf32.f32 "
        "{%0,%1,%2,%3}, {%4,%5,%6,%7}, {%8,%9}, {%0,%1,%2,%3};"
        : "+f"(c[0]), "+f"(c[1]), "+f"(c[2]), "+f"(c[3])
        : "r"(a[0]), "r"(a[1]), "r"(a[2]), "r"(a[3]), "r"(b0), "r"(b1));
}
__device__ __forceinline__ void mma_bf16(float c[4], const uint32_t a[4], uint32_t b0, uint32_t b1) {
    asm volatile(
        "mma.sync.aligned.m16n8k16.row.col.f32.bf16.bf16.f32 "
        "{%0,%1,%2,%3}, {%4,%5,%6,%7}, {%8,%9}, {%0,%1,%2,%3};"
        : "+f"(c[0]), "+f"(c[1]), "+f"(c[2]), "+f"(c[3])
        : "r"(a[0]), "r"(a[1]), "r"(a[2]), "r"(a[3]), "r"(b0), "r"(b1));
}
__device__ __forceinline__ void ldsm_x4(uint32_t& r0, uint32_t& r1, uint32_t& r2, uint32_t& r3,
                                        uint32_t addr) {
    asm volatile("ldmatrix.sync.aligned.m8n8.x4.shared.b16 {%0,%1,%2,%3}, [%4];"
                 : "=r"(r0), "=r"(r1), "=r"(r2), "=r"(r3) : "r"(addr));
}

// ---------------- K0: pack weights to bf16 pairs (k-contiguous) ----------------
__global__ __launch_bounds__(256)
void round_w(const float* __restrict__ Wg, const float* __restrict__ Wp,
             const float* __restrict__ Wt, const float* __restrict__ Wo,
             unsigned* __restrict__ dst)
{
    int i = blockIdx.x * 256 + threadIdx.x;   // 65536 pairs per matrix
    dst[i]              = packbf(Wg[2 * i], Wg[2 * i + 1]);
    dst[65536 + i]      = packbf(Wp[2 * i], Wp[2 * i + 1]);
    dst[131072 + i]     = packbf(Wt[2 * i], Wt[2 * i + 1]);
    dst[196608 + i]     = packbf(Wo[2 * i], Wo[2 * i + 1]);
}

// ============================================================================
// K1: position mixing via tf32 mma -> ctxp; ALSO packs query -> qp (fused)
// ============================================================================
#define MSTR 68
__global__ __launch_bounds__(256, 2)
void mix_mma(const float* __restrict__ ctx, const float* __restrict__ Wm,
             const float* __restrict__ bm, const float* __restrict__ query,
             unsigned* __restrict__ ctxp, unsigned* __restrict__ qp)
{
    const int h = blockIdx.x;
    const int n0 = blockIdx.y * 4;

    extern __shared__ unsigned smem_u[];
    float* sm = (float*)smem_u;
    float* sA = sm;               // [128][MSTR]
    float* sB = sm + 128 * MSTR;  // [64][MSTR]

    const int t = threadIdx.x;
    const int w = t >> 5, lane = t & 31;
    const int g = lane >> 2, tq = lane & 3;
    const int wm = w & 3, wn = w >> 2;

    #pragma unroll
    for (int i = 0; i < 8; i++) {
        int idx = t + 256 * i;
        int r = idx >> 4, c = idx & 15;
        const float* src = ctx + (((size_t)(n0 + (r >> 5)) * C) + h * 32 + (r & 31)) * NP + c * 4;
        cp_async16(sA + r * MSTR + c * 4, src);
    }
    #pragma unroll
    for (int i = 0; i < 4; i++) {
        int idx = t + 256 * i;
        int r = idx >> 4, c = idx & 15;
        cp_async16(sB + r * MSTR + c * 4, Wm + (size_t)h * 4096 + r * 64 + c * 4);
    }
    CP_COMMIT();

    // ---- fused query pack (hidden under the cp.async fill) ----
    // qp[(n*256 + h*16+cpl)*64 + tok] = pack(q[n][h*32+2cpl][tok], q[..+1][tok])
    #pragma unroll
    for (int i = 0; i < 16; i++) {
        int idx = t + 256 * i;              // < 4096
        int row = idx >> 6, tok = idx & 63;
        int nl = row >> 4, cpl = row & 15;
        const float* src = query + (((size_t)(n0 + nl) * C) + h * 32 + 2 * cpl) * NP + tok;
        qp[((size_t)(n0 + nl) * 256 + h * 16 + cpl) * 64 + tok] = packbf(src[0], src[64]);
    }

    CP_WAIT(0);
    __syncthreads();

    float acc[2][4][4];
    #pragma unroll
    for (int mt = 0; mt < 2; mt++)
        #pragma unroll
        for (int nt = 0; nt < 4; nt++)
            #pragma unroll
            for (int i = 0; i < 4; i++) acc[mt][nt][i] = 0.f;

    #pragma unroll
    for (int s = 0; s < 8; s++) {
        const int kb = s * 8;
        uint32_t af[2][4];
        #pragma unroll
        for (int mt = 0; mt < 2; mt++) {
            const int rb = wm * 32 + mt * 16;
            af[mt][0] = f2tf32(sA[(rb + g)     * MSTR + kb + tq]);
            af[mt][1] = f2tf32(sA[(rb + g + 8) * MSTR + kb + tq]);
            af[mt][2] = f2tf32(sA[(rb + g)     * MSTR + kb + tq + 4]);
            af[mt][3] = f2tf32(sA[(rb + g + 8) * MSTR + kb + tq + 4]);
        }
        uint32_t bf[4][2];
        #pragma unroll
        for (int nt = 0; nt < 4; nt++) {
            const int nb = wn * 32 + nt * 8;
            bf[nt][0] = f2tf32(sB[(nb + g) * MSTR + kb + tq]);
            bf[nt][1] = f2tf32(sB[(nb + g) * MSTR + kb + tq + 4]);
        }
        #pragma unroll
        for (int mt = 0; mt < 2; mt++)
            #pragma unroll
            for (int nt = 0; nt < 4; nt++)
                mma_tf32(acc[mt][nt], af[mt], bf[nt][0], bf[nt][1]);
    }
    __syncthreads();

    unsigned* sOut = (unsigned*)sB;   // [64][65] u32
    #pragma unroll
    for (int mt = 0; mt < 2; mt++) {
        const int rl0 = wm * 32 + mt * 16 + g;
        const int rl1 = rl0 + 8;
        #pragma unroll
        for (int nt = 0; nt < 4; nt++) {
            const int col = wn * 32 + nt * 8 + tq * 2;
            const float b0 = __ldg(bm + h * 64 + col);
            const float b1 = __ldg(bm + h * 64 + col + 1);
            float v00 = acc[mt][nt][0] + sA[rl0 * MSTR + col]     + b0;
            float v01 = acc[mt][nt][1] + sA[rl0 * MSTR + col + 1] + b1;
            float v10 = acc[mt][nt][2] + sA[rl1 * MSTR + col]     + b0;
            float v11 = acc[mt][nt][3] + sA[rl1 * MSTR + col + 1] + b1;
            float n00 = __shfl_down_sync(0xffffffffu, v00, 4);
            float n01 = __shfl_down_sync(0xffffffffu, v01, 4);
            float n10 = __shfl_down_sync(0xffffffffu, v10, 4);
            float n11 = __shfl_down_sync(0xffffffffu, v11, 4);
            if (!(g & 1)) {
                int srow0 = wm * 16 + mt * 8 + (g >> 1);
                int srow1 = srow0 + 4;
                sOut[srow0 * 65 + col]     = packbf(v00, n00);
                sOut[srow0 * 65 + col + 1] = packbf(v01, n01);
                sOut[srow1 * 65 + col]     = packbf(v10, n10);
                sOut[srow1 * 65 + col + 1] = packbf(v11, n11);
            }
        }
    }
    __syncthreads();
    #pragma unroll
    for (int i = 0; i < 16; i++) {
        int idx = t + 256 * i;
        int row = idx >> 6, tok = idx & 63;
        int nl = row >> 4, dp = row & 15;
        ctxp[((size_t)(n0 + nl) * 256 + h * 16 + dp) * 64 + tok] = sOut[row * 65 + tok];
    }
}

// ============================================================================
// bf16 GEMM core, 4-stage cp.async pipeline (distance 3), ldmatrix A-frags.
// 128 W-rows x 128 tokens (2 batches).
// EPI: 0 = [chp][tok] packed out, 1 = gp2 [tokp][ch], 2 = fp32+bias+resid
// ============================================================================
#define ASZ  2560            // 128 x 20 u32
#define BSZ  2176            // 16 x 136 u32
#define STG  (ASZ + BSZ)
template<int K, int EPI>
__device__ __forceinline__ void gemm_bf16_core(
    const unsigned* __restrict__ W,
    const unsigned* __restrict__ X0, const unsigned* __restrict__ X1,
    const float* __restrict__ bias, const float* __restrict__ resid,
    float* __restrict__ Yf, unsigned* __restrict__ Yu,
    int rowoff, int n0, unsigned* smb, int t)
{
    constexpr int NIT = K / 32;

    const int w = t >> 5, lane = t & 31;
    const int g = lane >> 2, tq = lane & 3;
    const int wm = w & 3, wn = w >> 2;

    // ldmatrix per-lane A address component (bytes): row = wm*32 + (lane&15), +16B col half
    const uint32_t smb_addr = smem_u32(smb);
    const uint32_t arow = (uint32_t)(wm * 32 + (lane & 15)) * 80 + (uint32_t)(lane >> 4) * 16;

    float acc[2][8][4];
    #pragma unroll
    for (int mt = 0; mt < 2; mt++)
        #pragma unroll
        for (int nt = 0; nt < 8; nt++)
            #pragma unroll
            for (int i = 0; i < 4; i++) acc[mt][nt][i] = 0.f;

    auto copy_tiles = [&](int k0, int slot) {
        unsigned* dA = smb + slot * STG;
        unsigned* dB = dA + ASZ;
        #pragma unroll
        for (int i = 0; i < 2; i++) {               // A: 128 rows x 16 u32
            int idx = t + 256 * i;
            int r = idx >> 2, c4 = idx & 3;
            cp_async16(dA + r * 20 + c4 * 4, W + (size_t)r * (K / 2) + (k0 >> 1) + c4 * 4);
        }
        #pragma unroll
        for (int i = 0; i < 2; i++) {               // B: 16 kp x 128 tok u32
            int idx = t + 256 * i;
            int r = idx >> 5, c = idx & 31;
            const unsigned* src = ((c < 16) ? X0 : X1) + (size_t)((k0 >> 1) + r) * 64 + (c & 15) * 4;
            cp_async16(dB + r * 136 + c * 4, src);
        }
    };

    copy_tiles(0, 0);  CP_COMMIT();
    copy_tiles(32, 1); CP_COMMIT();
    copy_tiles(64, 2); CP_COMMIT();

    for (int it = 0; it < NIT; ++it) {
        if (it < NIT - 1) { CP_WAIT(2); } else { CP_WAIT(0); }
        __syncthreads();
        if (it + 3 < NIT) {
            copy_tiles((it + 3) * 32, (it + 3) & 3);
            CP_COMMIT();
        }

        const uint32_t cAaddr = smb_addr + (uint32_t)(it & 3) * (STG * 4) + arow;
        const unsigned* cB = smb + (it & 3) * STG + ASZ;
        #pragma unroll
        for (int j = 0; j < 2; j++) {
            uint32_t af[2][4];
            ldsm_x4(af[0][0], af[0][1], af[0][2], af[0][3], cAaddr + j * 32);
            ldsm_x4(af[1][0], af[1][1], af[1][2], af[1][3], cAaddr + 1280 + j * 32);
            uint32_t bf[8][2];
            #pragma unroll
            for (int nt = 0; nt < 8; nt++) {
                const int nb = wn * 64 + nt * 8;
                bf[nt][0] = cB[(j * 8 + tq)     * 136 + nb + g];
                bf[nt][1] = cB[(j * 8 + tq + 4) * 136 + nb + g];
            }
            #pragma unroll
            for (int mt = 0; mt < 2; mt++)
                #pragma unroll
                for (int nt = 0; nt < 8; nt++)
                    mma_bf16(acc[mt][nt], af[mt], bf[nt][0], bf[nt][1]);
        }
    }
    __syncthreads();

    if (EPI == 2) {
        #pragma unroll
        for (int mt = 0; mt < 2; mt++) {
            const int rl0 = wm * 32 + mt * 16 + g;
            const int rl1 = rl0 + 8;
            const float bv0 = bias[rl0];
            const float bv1 = bias[rl1];
            #pragma unroll
            for (int nt = 0; nt < 8; nt++) {
                const int gcol = wn * 64 + nt * 8 + tq * 2;
                const int n = n0 + (gcol >> 6);
                const int col = gcol & 63;
                size_t off0 = ((size_t)n * 512 + rowoff + rl0) * 64 + col;
                size_t off1 = ((size_t)n * 512 + rowoff + rl1) * 64 + col;
                float2 v0, v1;
                v0.x = acc[mt][nt][0] + bv0; v0.y = acc[mt][nt][1] + bv0;
                v1.x = acc[mt][nt][2] + bv1; v1.y = acc[mt][nt][3] + bv1;
                const float2 r0 = *(const float2*)(resid + off0);
                const float2 r1 = *(const float2*)(resid + off1);
                v0.x += r0.x; v0.y += r0.y;
                v1.x += r1.x; v1.y += r1.y;
                *(float2*)(Yf + off0) = v0;
                *(float2*)(Yf + off1) = v1;
            }
        }
    } else if (EPI == 1) {
        #pragma unroll
        for (int mt = 0; mt < 2; mt++) {
            const int rl0 = wm * 32 + mt * 16 + g;
            const int rl1 = rl0 + 8;
            const float bv0 = bias[rl0];
            const float bv1 = bias[rl1];
            #pragma unroll
            for (int nt = 0; nt < 8; nt++) {
                const int gcol = wn * 64 + nt * 8 + tq * 2;
                const int n = n0 + (gcol >> 6);
                const int colp = (gcol & 63) >> 1;
                size_t base = (size_t)n * 8192 + (size_t)colp * 256 + rowoff;
                Yu[base + rl0] = packbf(acc[mt][nt][0] + bv0, acc[mt][nt][1] + bv0);
                Yu[base + rl1] = packbf(acc[mt][nt][2] + bv1, acc[mt][nt][3] + bv1);
            }
        }
    } else {
        unsigned* sOut = smb;   // [64][129] u32
        #pragma unroll
        for (int mt = 0; mt < 2; mt++) {
            const int rl0 = wm * 32 + mt * 16 + g;
            const int rl1 = rl0 + 8;
            const float bv0 = bias[rl0];
            const float bv1 = bias[rl1];
            #pragma unroll
            for (int nt = 0; nt < 8; nt++) {
                const int gcol = wn * 64 + nt * 8 + tq * 2;
                float v00 = acc[mt][nt][0] + bv0;
                float v01 = acc[mt][nt][1] + bv0;
                float v10 = acc[mt][nt][2] + bv1;
                float v11 = acc[mt][nt][3] + bv1;
                float n00 = __shfl_down_sync(0xffffffffu, v00, 4);
                float n01 = __shfl_down_sync(0xffffffffu, v01, 4);
                float n10 = __shfl_down_sync(0xffffffffu, v10, 4);
                float n11 = __shfl_down_sync(0xffffffffu, v11, 4);
                if (!(g & 1)) {
                    const int r0 = rl0 >> 1, r1 = rl1 >> 1;
                    sOut[r0 * 129 + gcol]     = packbf(v00, n00);
                    sOut[r0 * 129 + gcol + 1] = packbf(v01, n01);
                    sOut[r1 * 129 + gcol]     = packbf(v10, n10);
                    sOut[r1 * 129 + gcol + 1] = packbf(v11, n11);
                }
            }
        }
        __syncthreads();
        #pragma unroll
        for (int i = 0; i < 32; i++) {
            int idx = t + 256 * i;
            int chp = idx >> 7, c = idx & 127;
            int n = n0 + (c >> 6), tok = c & 63;
            Yu[((size_t)n * 128 + (rowoff >> 1) + chp) * 64 + tok] = sOut[chp * 129 + c];
        }
    }
}

// ---- merged projections: tiles 0-1 g (EPI1), 2-3 phi (EPI0), 4-5 theta (EPI0) ----
__global__ __launch_bounds__(256, 2)
void proj_mma(const unsigned* __restrict__ Wgb, const unsigned* __restrict__ Wpb,
              const unsigned* __restrict__ Wtb,
              const float* __restrict__ bg, const float* __restrict__ bp,
              const float* __restrict__ bt,
              const unsigned* __restrict__ ctxp, const unsigned* __restrict__ qp,
              unsigned* __restrict__ gp2, unsigned* __restrict__ php,
              unsigned* __restrict__ thp)
{
    extern __shared__ unsigned smem_u[];
    const int t = threadIdx.x;
    const int tile = blockIdx.x;
    const int n0 = blockIdx.y * 2;
    const int rowoff = (tile & 1) * 128;

    if (tile < 2) {
        const unsigned* X0 = ctxp + (size_t)n0 * 16384;
        gemm_bf16_core<512, 1>(Wgb + (size_t)rowoff * 256, X0, X0 + 16384,
                               bg + rowoff, nullptr, nullptr, gp2, rowoff, n0, smem_u, t);
    } else if (tile < 4) {
        const unsigned* X0 = ctxp + (size_t)n0 * 16384;
        gemm_bf16_core<512, 0>(Wpb + (size_t)rowoff * 256, X0, X0 + 16384,
                               bp + rowoff, nullptr, nullptr, php, rowoff, n0, smem_u, t);
    } else {
        const unsigned* X0 = qp + (size_t)n0 * 16384;
        gemm_bf16_core<512, 0>(Wtb + (size_t)rowoff * 256, X0, X0 + 16384,
                               bt + rowoff, nullptr, nullptr, thp, rowoff, n0, smem_u, t);
    }
}

// ---- output projection ----
__global__ __launch_bounds__(256, 2)
void out_mma(const unsigned* __restrict__ Wob, const float* __restrict__ bo,
             const unsigned* __restrict__ yp, const float* __restrict__ query,
             float* __restrict__ out)
{
    extern __shared__ unsigned smem_u[];
    const int t = threadIdx.x;
    const int rowoff = blockIdx.x * 128;
    const int n0 = blockIdx.y * 2;
    const unsigned* X0 = yp + (size_t)n0 * 8192;
    gemm_bf16_core<256, 2>(Wob + (size_t)rowoff * 128, X0, X0 + 8192,
                           bo + rowoff, query, out, nullptr, rowoff, n0, smem_u, t);
}

// ============================================================================
// attention, bf16 mma end-to-end (unchanged)
// ============================================================================
#define AT  0
#define AP  1152
#define AG  2304
#define APP 3840
#define ATOT 8448   // u32

__global__ __launch_bounds__(256, 3)
void attn_mma(const unsigned* __restrict__ thp, const unsigned* __restrict__ php,
              const unsigned* __restrict__ gp2, unsigned* __restrict__ yp)
{
    extern __shared__ unsigned smem_u[];
    const int hp = blockIdx.x;
    const int n  = blockIdx.y;
    const int t = threadIdx.x;
    const int w = t >> 5, lane = t & 31;
    const int g = lane >> 2, tq = lane & 3;
    const int hl = w >> 2;
    const int rb = (w & 3) * 16;

    {
        int hd = t >> 7, dp = (t >> 4) & 7, c4 = t & 15;
        size_t srcTP = ((size_t)n * 128 + (2 * hp + hd) * 8 + dp) * 64 + c4 * 4;
        cp_async16(smem_u + AT + hd * 576 + dp * 72 + c4 * 4, thp + srcTP);
        cp_async16(smem_u + AP + hd * 576 + dp * 72 + c4 * 4, php + srcTP);
        int tokp = (t >> 2) & 31, c4g = t & 3;
        cp_async16(smem_u + AG + hd * 768 + tokp * 24 + c4g * 4,
                   gp2 + (size_t)n * 8192 + (size_t)tokp * 256 + (2 * hp + hd) * 16 + c4g * 4);
    }
    CP_COMMIT();
    CP_WAIT(0);
    __syncthreads();

    const unsigned* Tm = smem_u + AT + hl * 576;
    const unsigned* Pm = smem_u + AP + hl * 576;
    const unsigned* Gm = smem_u + AG + hl * 768;
    unsigned*       Pp = smem_u + APP + hl * 2304;

    float sacc[8][4];
    #pragma unroll
    for (int nt = 0; nt < 8; nt++)
        #pragma unroll
        for (int i = 0; i < 4; i++) sacc[nt][i] = 0.f;
    {
        uint32_t af[4];
        af[0] = Tm[tq * 72 + rb + g];
        af[1] = Tm[tq * 72 + rb + g + 8];
        af[2] = Tm[(tq + 4) * 72 + rb + g];
        af[3] = Tm[(tq + 4) * 72 + rb + g + 8];
        #pragma unroll
        for (int nt = 0; nt < 8; nt++) {
            uint32_t b0 = Pm[tq * 72 + nt * 8 + g];
            uint32_t b1 = Pm[(tq + 4) * 72 + nt * 8 + g];
            mma_bf16(sacc[nt], af, b0, b1);
        }
    }

    {
        float m0 = -1e30f, m1 = -1e30f;
        #pragma unroll
        for (int nt = 0; nt < 8; nt++) {
            #pragma unroll
            for (int i = 0; i < 4; i++) sacc[nt][i] *= 0.25f;
            m0 = fmaxf(m0, fmaxf(sacc[nt][0], sacc[nt][1]));
            m1 = fmaxf(m1, fmaxf(sacc[nt][2], sacc[nt][3]));
        }
        m0 = fmaxf(m0, __shfl_xor_sync(0xffffffffu, m0, 1));
        m0 = fmaxf(m0, __shfl_xor_sync(0xffffffffu, m0, 2));
        m1 = fmaxf(m1, __shfl_xor_sync(0xffffffffu, m1, 1));
        m1 = fmaxf(m1, __shfl_xor_sync(0xffffffffu, m1, 2));
        float s0 = 0.f, s1 = 0.f;
        #pragma unroll
        for (int nt = 0; nt < 8; nt++) {
            sacc[nt][0] = __expf(sacc[nt][0] - m0);
            sacc[nt][1] = __expf(sacc[nt][1] - m0);
            sacc[nt][2] = __expf(sacc[nt][2] - m1);
            sacc[nt][3] = __expf(sacc[nt][3] - m1);
            s0 += sacc[nt][0] + sacc[nt][1];
            s1 += sacc[nt][2] + sacc[nt][3];
        }
        s0 += __shfl_xor_sync(0xffffffffu, s0, 1);
        s0 += __shfl_xor_sync(0xffffffffu, s0, 2);
        s1 += __shfl_xor_sync(0xffffffffu, s1, 1);
        s1 += __shfl_xor_sync(0xffffffffu, s1, 2);
        const float i0 = 1.0f / s0, i1 = 1.0f / s1;
        #pragma unroll
        for (int nt = 0; nt < 8; nt++) {
            Pp[(rb + g)     * 36 + nt * 4 + tq] = packbf(sacc[nt][0] * i0, sacc[nt][1] * i0);
            Pp[(rb + g + 8) * 36 + nt * 4 + tq] = packbf(sacc[nt][2] * i1, sacc[nt][3] * i1);
        }
    }
    __syncwarp();

    float acc2[2][4];
    #pragma unroll
    for (int nt = 0; nt < 2; nt++)
        #pragma unroll
        for (int i = 0; i < 4; i++) acc2[nt][i] = 0.f;

    #pragma unroll
    for (int j = 0; j < 4; j++) {
        uint32_t pa[4];
        pa[0] = Pp[(rb + g)     * 36 + j * 8 + tq];
        pa[1] = Pp[(rb + g + 8) * 36 + j * 8 + tq];
        pa[2] = Pp[(rb + g)     * 36 + j * 8 + tq + 4];
        pa[3] = Pp[(rb + g + 8) * 36 + j * 8 + tq + 4];
        #pragma unroll
        for (int nt = 0; nt < 2; nt++) {
            uint32_t b0 = Gm[(j * 8 + tq)     * 24 + nt * 8 + g];
            uint32_t b1 = Gm[(j * 8 + tq + 4) * 24 + nt * 8 + g];
            mma_bf16(acc2[nt], pa, b0, b1);
        }
    }

    const int hgl = 2 * hp + hl;
    #pragma unroll
    for (int nt = 0; nt < 2; nt++) {
        const int chp = hgl * 8 + nt * 4 + tq;
        yp[((size_t)n * 128 + chp) * 64 + rb + g]     = packbf(acc2[nt][0], acc2[nt][1]);
        yp[((size_t)n * 128 + chp) * 64 + rb + g + 8] = packbf(acc2[nt][2], acc2[nt][3]);
    }
}

// ---------------- launch ----------------
extern "C" void kernel_launch(void* const* d_in, const int* in_sizes, int n_in,
                              void* d_out, int out_size)
{
    const float* query   = (const float*)d_in[0];
    const float* context = (const float*)d_in[1];
    const float* Wm = (const float*)d_in[2];
    const float* bm = (const float*)d_in[3];
    const float* Wg = (const float*)d_in[4];
    const float* bg = (const float*)d_in[5];
    const float* Wt = (const float*)d_in[6];
    const float* bt = (const float*)d_in[7];
    const float* Wp = (const float*)d_in[8];
    const float* bp = (const float*)d_in[9];
    const float* Wo = (const float*)d_in[10];
    const float* bo = (const float*)d_in[11];
    float* out = (float*)d_out;

    unsigned *ctxp, *qp, *thp, *php, *gp2, *yp, *wr;
    cudaGetSymbolAddress((void**)&ctxp, g_ctxp);
    cudaGetSymbolAddress((void**)&qp,   g_qp);
    cudaGetSymbolAddress((void**)&thp,  g_thp);
    cudaGetSymbolAddress((void**)&php,  g_php);
    cudaGetSymbolAddress((void**)&gp2,  g_gp2);
    cudaGetSymbolAddress((void**)&yp,   g_yp);
    cudaGetSymbolAddress((void**)&wr,   g_Wbf);

    const unsigned* Wgb = wr;
    const unsigned* Wpb = wr + 65536;
    const unsigned* Wtb = wr + 131072;
    const unsigned* Wob = wr + 196608;

    const int GSMEM = 4 * STG * 4;                        // 75776 B
    const int XSMEM = (128 * MSTR + 64 * MSTR) * 4;       // 52224 B
    const int ASMEM = ATOT * 4;                           // 33792 B
    cudaFuncSetAttribute((const void*)proj_mma,
                         cudaFuncAttributeMaxDynamicSharedMemorySize, GSMEM);
    cudaFuncSetAttribute((const void*)out_mma,
                         cudaFuncAttributeMaxDynamicSharedMemorySize, GSMEM);
    cudaFuncSetAttribute((const void*)mix_mma,
                         cudaFuncAttributeMaxDynamicSharedMemorySize, XSMEM);
    cudaFuncSetAttribute((const void*)attn_mma,
                         cudaFuncAttributeMaxDynamicSharedMemorySize, ASMEM);

    // 0) pack weights to bf16
    round_w<<<256, 256>>>(Wg, Wp, Wt, Wo, wr);

    // 1) position mixing -> ctxp; fused query pack -> qp
    mix_mma<<<dim3(HEADS, NB / 4), 256, XSMEM>>>(context, Wm, bm, query, ctxp, qp);

    // 2) merged projections (4-stage pipeline, ldmatrix A)
    proj_mma<<<dim3(6, NB / 2), 256, GSMEM>>>(
        Wgb, Wpb, Wtb, bg, bp, bt, ctxp, qp, gp2, php, thp);

    // 3) attention (bf16 mma end-to-end)
    attn_mma<<<dim3(HEADS / 2, NB), 256, ASMEM>>>(thp, php, gp2, yp);

    // 4) output projection + bias + residual (fp32 epilogue)
    out_mma<<<dim3(4, NB / 2), 256, GSMEM>>>(Wob, bo, yp, query, out);
}